// round 2
// baseline (speedup 1.0000x reference)
#include <cuda_runtime.h>
#include <math.h>

// Problem constants
#define BB   16
#define SSEQ 1024
#define DD   768
#define HH   12
#define DHH  64
#define DFF_ 3072
#define MTOK (BB*SSEQ)   // 16384 tokens

// ---------------- scratch (static __device__, allocation-free) ----------------
__device__ float g_h  [(size_t)MTOK * DD];        // ln1 out / ln2 out (reused)
__device__ float g_q  [(size_t)MTOK * DD];        // [B,S,H,DH]
__device__ float g_k  [(size_t)MTOK * DD];
__device__ float g_v  [(size_t)MTOK * DD];
__device__ float g_ctx[(size_t)MTOK * DD];        // [B,S,H,DH]
__device__ float g_x2 [(size_t)MTOK * DD];        // x + attn_out
__device__ float g_ff [(size_t)MTOK * DFF_];      // gelu(h2@W1+b1)
__device__ float g_sc [(size_t)BB * HH * SSEQ * SSEQ]; // scores/probs, 805MB
__device__ float g_wt [3 * DD * DD];              // Wq/Wk/Wv remapped to [D, H*DH]

// ---------------- QKV weight remap: [H,D,DH] -> [D, H*DH] ----------------
__global__ void __launch_bounds__(256) transpose_qkvw(
    const float* __restrict__ Wq, const float* __restrict__ Wk,
    const float* __restrict__ Wv, float* __restrict__ wt)
{
    int idx = blockIdx.x * 256 + threadIdx.x;
    if (idx >= DD * DD) return;
    int d = idx / DD;
    int n = idx % DD;
    int h = n >> 6;      // n / 64
    int c = n & 63;      // n % 64
    size_t src = (size_t)h * DD * DHH + (size_t)d * DHH + c;
    wt[idx]                = Wq[src];
    wt[idx + DD * DD]      = Wk[src];
    wt[idx + 2 * DD * DD]  = Wv[src];
}

// ---------------- LayerNorm over D=768, one block per row ----------------
__global__ void __launch_bounds__(256) lnorm_kernel(
    const float* __restrict__ x, const float* __restrict__ g,
    const float* __restrict__ b, float* __restrict__ out)
{
    size_t row = blockIdx.x;
    const float* xr = x + row * DD;
    int t = threadIdx.x;
    float v0 = xr[t], v1 = xr[t + 256], v2 = xr[t + 512];
    float s  = v0 + v1 + v2;
    float s2 = v0*v0 + v1*v1 + v2*v2;
    #pragma unroll
    for (int o = 16; o; o >>= 1) {
        s  += __shfl_xor_sync(0xFFFFFFFFu, s,  o);
        s2 += __shfl_xor_sync(0xFFFFFFFFu, s2, o);
    }
    __shared__ float sh[2][8];
    int w = t >> 5, l = t & 31;
    if (l == 0) { sh[0][w] = s; sh[1][w] = s2; }
    __syncthreads();
    s = 0.f; s2 = 0.f;
    #pragma unroll
    for (int i = 0; i < 8; i++) { s += sh[0][i]; s2 += sh[1][i]; }
    float mean = s * (1.f / 768.f);
    float var  = s2 * (1.f / 768.f) - mean * mean;
    float inv  = rsqrtf(var + 1e-5f);
    float* orow = out + row * DD;
    orow[t      ] = (v0 - mean) * inv * g[t      ] + b[t      ];
    orow[t + 256] = (v1 - mean) * inv * g[t + 256] + b[t + 256];
    orow[t + 512] = (v2 - mean) * inv * g[t + 512] + b[t + 512];
}

// ---------------- Softmax over rows of 1024 ----------------
__global__ void __launch_bounds__(256) softmax1024(float* __restrict__ sc)
{
    size_t row = blockIdx.x;
    float* r = sc + row * 1024;
    int t = threadIdx.x;
    float v[4];
    float mx = -1e30f;
    #pragma unroll
    for (int i = 0; i < 4; i++) { v[i] = r[t + i * 256]; mx = fmaxf(mx, v[i]); }
    #pragma unroll
    for (int o = 16; o; o >>= 1) mx = fmaxf(mx, __shfl_xor_sync(0xFFFFFFFFu, mx, o));
    __shared__ float sh[8];
    int w = t >> 5, l = t & 31;
    if (l == 0) sh[w] = mx;
    __syncthreads();
    mx = sh[0];
    #pragma unroll
    for (int i = 1; i < 8; i++) mx = fmaxf(mx, sh[i]);
    float s = 0.f;
    #pragma unroll
    for (int i = 0; i < 4; i++) { v[i] = expf(v[i] - mx); s += v[i]; }
    #pragma unroll
    for (int o = 16; o; o >>= 1) s += __shfl_xor_sync(0xFFFFFFFFu, s, o);
    __syncthreads();              // sh reuse
    if (l == 0) sh[w] = s;
    __syncthreads();
    s = 0.f;
    #pragma unroll
    for (int i = 0; i < 8; i++) s += sh[i];
    float invs = 1.f / s;
    #pragma unroll
    for (int i = 0; i < 4; i++) r[t + i * 256] = v[i] * invs;
}

// ---------------- Generic batched SGEMM, 128x128x16, 8x8/thread ----------------
// A[m,k]  at A + z_off(a) + m*as_m + k            (k contiguous)
// B[k,n]  at B + z_off(b) + k*bs_k + n*bs_n
// C[m,n]  at C + z_off(c) + m*cs_m + n            (n contiguous)
// z_off(o) = (z / zdiv)*out + (z % zdiv)*in
struct GemmP {
    const float* A; int  as_m; long a_out, a_in; int a_zdiv;
    const float* B; int  bs_k, bs_n; long b_out, b_in; int b_zdiv;
    const float* bias;
    const float* R;           // residual, same layout/offsets as C
    float*       C; int  cs_m; long c_out, c_in; int c_zdiv;
    int M, N, K;
    float alpha;
    int act;                  // 0 none, 1 exact gelu
};

__global__ void __launch_bounds__(256, 2) sgemm_kernel(GemmP p)
{
    __shared__ float As[16][128];
    __shared__ float Bs[16][128];

    const int tid = threadIdx.x;
    const int tx = tid & 15, ty = tid >> 4;
    const int m0 = blockIdx.y * 128, n0 = blockIdx.x * 128;
    const int z  = blockIdx.z;

    const float* A = p.A + (long)(z / p.a_zdiv) * p.a_out + (long)(z % p.a_zdiv) * p.a_in;
    const float* B = p.B + (long)(z / p.b_zdiv) * p.b_out + (long)(z % p.b_zdiv) * p.b_in;
    const long coff = (long)(z / p.c_zdiv) * p.c_out + (long)(z % p.c_zdiv) * p.c_in;
    float* C = p.C + coff;
    const float* R = p.R ? (p.R + coff) : nullptr;

    float acc[8][8];
    #pragma unroll
    for (int i = 0; i < 8; i++)
        #pragma unroll
        for (int j = 0; j < 8; j++) acc[i][j] = 0.f;

    const bool bn1 = (p.bs_n == 1);

    for (int k0 = 0; k0 < p.K; k0 += 16) {
        // A tile (MTxKT = 128x16), k contiguous in gmem
        #pragma unroll
        for (int r = 0; r < 8; r++) {
            int idx = tid + r * 256;
            int m = idx >> 4, k = idx & 15;
            As[k][m] = A[(long)(m0 + m) * p.as_m + (k0 + k)];
        }
        // B tile (KTxNT = 16x128)
        if (bn1) {
            #pragma unroll
            for (int r = 0; r < 8; r++) {
                int idx = tid + r * 256;
                int k = idx >> 7, n = idx & 127;
                float v = 0.f;
                if (n0 + n < p.N)
                    v = B[(long)(k0 + k) * p.bs_k + (long)(n0 + n)];
                Bs[k][n] = v;
            }
        } else { // bs_k == 1 (scores GEMM, K contiguous)
            #pragma unroll
            for (int r = 0; r < 8; r++) {
                int idx = tid + r * 256;
                int n = idx >> 4, k = idx & 15;
                float v = 0.f;
                if (n0 + n < p.N)
                    v = B[(long)(k0 + k) * p.bs_k + (long)(n0 + n) * p.bs_n];
                Bs[k][n] = v;
            }
        }
        __syncthreads();
        #pragma unroll
        for (int kk = 0; kk < 16; kk++) {
            float4 a0 = *(const float4*)&As[kk][ty * 8];
            float4 a1 = *(const float4*)&As[kk][ty * 8 + 4];
            float4 b0 = *(const float4*)&Bs[kk][tx * 8];
            float4 b1 = *(const float4*)&Bs[kk][tx * 8 + 4];
            float a[8] = {a0.x, a0.y, a0.z, a0.w, a1.x, a1.y, a1.z, a1.w};
            float b[8] = {b0.x, b0.y, b0.z, b0.w, b1.x, b1.y, b1.z, b1.w};
            #pragma unroll
            for (int i = 0; i < 8; i++)
                #pragma unroll
                for (int j = 0; j < 8; j++)
                    acc[i][j] = fmaf(a[i], b[j], acc[i][j]);
        }
        __syncthreads();
    }

    // epilogue: alpha*acc + bias -> (gelu) -> + residual -> store
    #pragma unroll
    for (int i = 0; i < 8; i++) {
        int m = m0 + ty * 8 + i;
        #pragma unroll
        for (int j = 0; j < 8; j++) {
            int n = n0 + tx * 8 + j;
            if (n < p.N) {
                float v = p.alpha * acc[i][j];
                if (p.bias) v += p.bias[n];
                if (p.act)  v = 0.5f * v * (1.f + erff(v * 0.70710678118654752f));
                long ci = (long)m * p.cs_m + n;
                if (R) v += R[ci];
                C[ci] = v;
            }
        }
    }
}

// ---------------- host driver ----------------
extern "C" void kernel_launch(void* const* d_in, const int* in_sizes, int n_in,
                              void* d_out, int out_size)
{
    (void)in_sizes; (void)n_in; (void)out_size;
    const float* x    = (const float*)d_in[0];
    const float* ln1g = (const float*)d_in[1];
    const float* ln1b = (const float*)d_in[2];
    const float* Wq   = (const float*)d_in[3];
    const float* bq   = (const float*)d_in[4];
    const float* Wk   = (const float*)d_in[5];
    const float* bk   = (const float*)d_in[6];
    const float* Wv   = (const float*)d_in[7];
    const float* bv   = (const float*)d_in[8];
    const float* Wo   = (const float*)d_in[9];
    const float* bo   = (const float*)d_in[10];
    const float* ln2g = (const float*)d_in[11];
    const float* ln2b = (const float*)d_in[12];
    const float* W1   = (const float*)d_in[13];
    const float* b1   = (const float*)d_in[14];
    const float* W2   = (const float*)d_in[15];
    const float* b2   = (const float*)d_in[16];
    float* out = (float*)d_out;

    float *h, *q, *k, *v, *ctx, *x2, *ff, *sc, *wt;
    cudaGetSymbolAddress((void**)&h,   g_h);
    cudaGetSymbolAddress((void**)&q,   g_q);
    cudaGetSymbolAddress((void**)&k,   g_k);
    cudaGetSymbolAddress((void**)&v,   g_v);
    cudaGetSymbolAddress((void**)&ctx, g_ctx);
    cudaGetSymbolAddress((void**)&x2,  g_x2);
    cudaGetSymbolAddress((void**)&ff,  g_ff);
    cudaGetSymbolAddress((void**)&sc,  g_sc);
    cudaGetSymbolAddress((void**)&wt,  g_wt);

    // 1) QKV weight remap
    transpose_qkvw<<<(DD * DD + 255) / 256, 256>>>(Wq, Wk, Wv, wt);

    // 2) ln1
    lnorm_kernel<<<MTOK, 256>>>(x, ln1g, ln1b, h);

    // 3) Q/K/V projections: [16384,768] = h @ wt_x + bias, out layout [B,S,H,DH]
    GemmP p{};
    p.A = h; p.as_m = DD; p.a_out = 0; p.a_in = 0; p.a_zdiv = 1;
    p.bs_k = DD; p.bs_n = 1; p.b_out = 0; p.b_in = 0; p.b_zdiv = 1;
    p.R = nullptr;
    p.cs_m = DD; p.c_out = 0; p.c_in = 0; p.c_zdiv = 1;
    p.M = MTOK; p.N = DD; p.K = DD; p.alpha = 1.f; p.act = 0;
    dim3 gproj(DD / 128, MTOK / 128, 1);
    p.B = wt;              p.bias = bq; p.C = q; sgemm_kernel<<<gproj, 256>>>(p);
    p.B = wt + DD * DD;    p.bias = bk; p.C = k; sgemm_kernel<<<gproj, 256>>>(p);
    p.B = wt + 2 * DD * DD;p.bias = bv; p.C = v; sgemm_kernel<<<gproj, 256>>>(p);

    // 4) scores[b,h,s,t] = 0.125 * q . k   (batched over B*H = 192)
    {
        GemmP s{};
        s.A = q;  s.as_m = DD;
        s.a_out = (long)SSEQ * DD; s.a_in = DHH; s.a_zdiv = HH;
        s.B = k;  s.bs_k = 1; s.bs_n = DD;
        s.b_out = (long)SSEQ * DD; s.b_in = DHH; s.b_zdiv = HH;
        s.bias = nullptr; s.R = nullptr;
        s.C = sc; s.cs_m = SSEQ;
        s.c_out = (long)SSEQ * SSEQ; s.c_in = 0; s.c_zdiv = 1;
        s.M = SSEQ; s.N = SSEQ; s.K = DHH;
        s.alpha = 0.125f; s.act = 0;
        sgemm_kernel<<<dim3(SSEQ / 128, SSEQ / 128, BB * HH), 256>>>(s);
    }

    // 5) softmax over 192*1024 rows of 1024
    softmax1024<<<BB * HH * SSEQ, 256>>>(sc);

    // 6) ctx[b,s,h,:] = probs @ v   (batched over B*H, N=64)
    {
        GemmP s{};
        s.A = sc; s.as_m = SSEQ;
        s.a_out = (long)SSEQ * SSEQ; s.a_in = 0; s.a_zdiv = 1;
        s.B = v;  s.bs_k = DD; s.bs_n = 1;
        s.b_out = (long)SSEQ * DD; s.b_in = DHH; s.b_zdiv = HH;
        s.bias = nullptr; s.R = nullptr;
        s.C = ctx; s.cs_m = DD;
        s.c_out = (long)SSEQ * DD; s.c_in = DHH; s.c_zdiv = HH;
        s.M = SSEQ; s.N = DHH; s.K = SSEQ;
        s.alpha = 1.f; s.act = 0;
        sgemm_kernel<<<dim3(1, SSEQ / 128, BB * HH), 256>>>(s);
    }

    // 7) x2 = x + ctx @ Wo + bo
    {
        GemmP s{};
        s.A = ctx; s.as_m = DD; s.a_out = 0; s.a_in = 0; s.a_zdiv = 1;
        s.B = Wo;  s.bs_k = DD; s.bs_n = 1; s.b_out = 0; s.b_in = 0; s.b_zdiv = 1;
        s.bias = bo; s.R = x;
        s.C = x2; s.cs_m = DD; s.c_out = 0; s.c_in = 0; s.c_zdiv = 1;
        s.M = MTOK; s.N = DD; s.K = DD; s.alpha = 1.f; s.act = 0;
        sgemm_kernel<<<dim3(DD / 128, MTOK / 128, 1), 256>>>(s);
    }

    // 8) ln2
    lnorm_kernel<<<MTOK, 256>>>(x2, ln2g, ln2b, h);

    // 9) ff = gelu(h @ W1 + b1)
    {
        GemmP s{};
        s.A = h;  s.as_m = DD; s.a_out = 0; s.a_in = 0; s.a_zdiv = 1;
        s.B = W1; s.bs_k = DFF_; s.bs_n = 1; s.b_out = 0; s.b_in = 0; s.b_zdiv = 1;
        s.bias = b1; s.R = nullptr;
        s.C = ff; s.cs_m = DFF_; s.c_out = 0; s.c_in = 0; s.c_zdiv = 1;
        s.M = MTOK; s.N = DFF_; s.K = DD; s.alpha = 1.f; s.act = 1;
        sgemm_kernel<<<dim3(DFF_ / 128, MTOK / 128, 1), 256>>>(s);
    }

    // 10) out = x2 + ff @ W2 + b2
    {
        GemmP s{};
        s.A = ff; s.as_m = DFF_; s.a_out = 0; s.a_in = 0; s.a_zdiv = 1;
        s.B = W2; s.bs_k = DD; s.bs_n = 1; s.b_out = 0; s.b_in = 0; s.b_zdiv = 1;
        s.bias = b2; s.R = x2;
        s.C = out; s.cs_m = DD; s.c_out = 0; s.c_in = 0; s.c_zdiv = 1;
        s.M = MTOK; s.N = DD; s.K = DFF_; s.alpha = 1.f; s.act = 0;
        sgemm_kernel<<<dim3(DD / 128, MTOK / 128, 1), 256>>>(s);
    }
}

// round 4
// speedup vs baseline: 2.7014x; 2.7014x over previous
#include <cuda_runtime.h>
#include <cuda_bf16.h>
#include <math.h>
#include <stdint.h>

#define BB   16
#define SSEQ 1024
#define DD   768
#define HH   12
#define DHH  64
#define DFF_ 3072
#define MTOK (BB*SSEQ)

// ---------------- scratch ----------------
__device__ float          g_v  [(size_t)MTOK * DD];
__device__ float          g_sc [(size_t)BB * HH * SSEQ * SSEQ];
__device__ float          g_x2 [(size_t)MTOK * DD];
__device__ __nv_bfloat16  g_hh [(size_t)MTOK * DD],  g_hl [(size_t)MTOK * DD];
__device__ __nv_bfloat16  g_qh [(size_t)MTOK * DD],  g_ql [(size_t)MTOK * DD];
__device__ __nv_bfloat16  g_kh [(size_t)MTOK * DD],  g_kl [(size_t)MTOK * DD];
__device__ __nv_bfloat16  g_vth[(size_t)MTOK * DD],  g_vtl[(size_t)MTOK * DD];
__device__ __nv_bfloat16  g_ch [(size_t)MTOK * DD],  g_cl [(size_t)MTOK * DD];
__device__ __nv_bfloat16  g_ph [(size_t)BB * HH * SSEQ * SSEQ];
__device__ __nv_bfloat16  g_pl [(size_t)BB * HH * SSEQ * SSEQ];
__device__ __nv_bfloat16  g_ffh[(size_t)MTOK * DFF_], g_ffl[(size_t)MTOK * DFF_];
__device__ __nv_bfloat16  g_wqh[3 * DD * DD], g_wql[3 * DD * DD];
__device__ __nv_bfloat16  g_woh[DD * DD],     g_wol[DD * DD];
__device__ __nv_bfloat16  g_w1h[DD * DFF_],   g_w1l[DD * DFF_];
__device__ __nv_bfloat16  g_w2h[DD * DFF_],   g_w2l[DD * DFF_];

// ---------------- helpers ----------------
__device__ __forceinline__ uint32_t smem_u32(const void* p) {
    uint32_t a;
    asm("{ .reg .u64 t; cvta.to.shared.u64 t, %1; cvt.u32.u64 %0, t; }" : "=r"(a) : "l"(p));
    return a;
}
__device__ __forceinline__ void splitbf(float x, __nv_bfloat16& h, __nv_bfloat16& l) {
    h = __float2bfloat16(x);
    l = __float2bfloat16(x - __bfloat162float(h));
}
__device__ __forceinline__ float gelu_f(float v) {
    return 0.5f * v * (1.f + erff(v * 0.70710678118654752f));
}

#define CP_ASYNC16(dst, src) \
    asm volatile("cp.async.cg.shared.global [%0], [%1], 16;" :: "r"(dst), "l"(src))
#define CP_COMMIT()  asm volatile("cp.async.commit_group;" ::: "memory")
#define CP_WAIT1()   asm volatile("cp.async.wait_group 1;" ::: "memory")
#define CP_WAIT0()   asm volatile("cp.async.wait_group 0;" ::: "memory")

#define LDSM_X4(r0, r1, r2, r3, a) \
    asm volatile("ldmatrix.sync.aligned.m8n8.x4.shared.b16 {%0,%1,%2,%3}, [%4];" \
        : "=r"(r0), "=r"(r1), "=r"(r2), "=r"(r3) : "r"(a))
#define LDSM_X2(r0, r1, a) \
    asm volatile("ldmatrix.sync.aligned.m8n8.x2.shared.b16 {%0,%1}, [%2];" \
        : "=r"(r0), "=r"(r1) : "r"(a))

#define MMA16816(c0, c1, c2, c3, a0, a1, a2, a3, b0, b1) \
    asm volatile("mma.sync.aligned.m16n8k16.row.col.f32.bf16.bf16.f32 " \
        "{%0,%1,%2,%3}, {%4,%5,%6,%7}, {%8,%9}, {%0,%1,%2,%3};" \
        : "+f"(c0), "+f"(c1), "+f"(c2), "+f"(c3) \
        : "r"(a0), "r"(a1), "r"(a2), "r"(a3), "r"(b0), "r"(b1))

// ---------------- HMMA GEMM ----------------
// C[128 x 128] tile = 3 passes of A(hi/lo)[M,K] @ B(hi/lo)[N,K]^T  (both K-contig)
struct TcP {
    const __nv_bfloat16 *Ah, *Al, *Bh, *Bl;
    const float *bias, *R;
    float* Cf; __nv_bfloat16 *Ch, *Cl;
    long a_out, a_in, b_out, b_in, c_out, c_in;
    int a_zdiv, b_zdiv, c_zdiv;
    int as_m, bs_n, cs_m;
    int K, N; float alpha; int act;
};

// smem: 2 stages x (A: 128 rows x 80B, B: 128 rows x 80B). Row stride 80B =>
// 8 consecutive ldmatrix rows hit 8 distinct 4-bank groups (20*r mod 32): no conflicts.
#define RS   80
#define STGB (128 * RS)          // 10240 per operand
#define STG2 (2 * STGB)          // 20480 per stage

__global__ void __launch_bounds__(256, 2) tcmm(TcP p)
{
    __shared__ __align__(128) char smem[2 * STG2];

    const int tid = threadIdx.x, wid = tid >> 5, lane = tid & 31;
    const int n0 = blockIdx.x * 128, m0 = blockIdx.y * 128, z = blockIdx.z;
    const int wm = (wid >> 2) * 64;      // warp m offset (2 warp-rows)
    const int wn = (wid & 3) * 32;       // warp n offset (4 warp-cols)

    const __nv_bfloat16* Ah = p.Ah + (long)(z / p.a_zdiv) * p.a_out + (long)(z % p.a_zdiv) * p.a_in;
    const __nv_bfloat16* Al = p.Al + (long)(z / p.a_zdiv) * p.a_out + (long)(z % p.a_zdiv) * p.a_in;
    const __nv_bfloat16* Bh = p.Bh + (long)(z / p.b_zdiv) * p.b_out + (long)(z % p.b_zdiv) * p.b_in;
    const __nv_bfloat16* Bl = p.Bl + (long)(z / p.b_zdiv) * p.b_out + (long)(z % p.b_zdiv) * p.b_in;
    const long coff = (long)(z / p.c_zdiv) * p.c_out + (long)(z % p.c_zdiv) * p.c_in;

    const uint32_t sbase = smem_u32(smem);
    const int KC = p.K >> 5;             // 32-wide k chunks per pass
    const int NC = 3 * KC;

    // per-thread load slots: 2 A chunks + 2 B chunks (16B each)
    const int rowA0 = tid >> 2,        unitA0 = tid & 3;         // chunks 0..255
    const int rowA1 = (tid + 256) >> 2, unitA1 = tid & 3;        // chunks 256..511
    const bool bok0 = (n0 + rowA0 < p.N);
    const bool bok1 = (n0 + rowA1 < p.N);

    float acc[4][4][4];
    #pragma unroll
    for (int i = 0; i < 4; i++)
        #pragma unroll
        for (int j = 0; j < 4; j++)
            #pragma unroll
            for (int r = 0; r < 4; r++) acc[i][j][r] = 0.f;

    auto load_stage = [&](int s, int c) {
        const int pass = c / KC;
        const int kc   = c - pass * KC;
        const long kof = (long)kc << 5;
        const __nv_bfloat16* A = (pass == 2) ? Al : Ah;
        const __nv_bfloat16* B = (pass == 1) ? Bl : Bh;
        uint32_t dA = sbase + s * STG2;
        uint32_t dB = dA + STGB;
        CP_ASYNC16(dA + rowA0 * RS + unitA0 * 16,
                   A + (long)(m0 + rowA0) * p.as_m + kof + unitA0 * 8);
        CP_ASYNC16(dA + rowA1 * RS + unitA1 * 16,
                   A + (long)(m0 + rowA1) * p.as_m + kof + unitA1 * 8);
        if (bok0)
            CP_ASYNC16(dB + rowA0 * RS + unitA0 * 16,
                       B + (long)(n0 + rowA0) * p.bs_n + kof + unitA0 * 8);
        if (bok1)
            CP_ASYNC16(dB + rowA1 * RS + unitA1 * 16,
                       B + (long)(n0 + rowA1) * p.bs_n + kof + unitA1 * 8);
    };

    load_stage(0, 0);
    CP_COMMIT();

    for (int c = 0; c < NC; c++) {
        const int s = c & 1;
        if (c + 1 < NC) { load_stage(s ^ 1, c + 1); CP_COMMIT(); CP_WAIT1(); }
        else            { CP_WAIT0(); }
        __syncthreads();

        const uint32_t sA = sbase + s * STG2;
        const uint32_t sB = sA + STGB;

        #pragma unroll
        for (int ks = 0; ks < 2; ks++) {
            uint32_t a[4][4], b[4][2];
            #pragma unroll
            for (int i = 0; i < 4; i++) {
                uint32_t ad = sA + (uint32_t)(wm + i * 16 + (lane & 15)) * RS
                            + ks * 32 + (lane >> 4) * 16;
                LDSM_X4(a[i][0], a[i][1], a[i][2], a[i][3], ad);
            }
            #pragma unroll
            for (int j = 0; j < 4; j++) {
                uint32_t bd = sB + (uint32_t)(wn + j * 8 + (lane & 7)) * RS
                            + ks * 32 + ((lane >> 3) & 1) * 16;
                LDSM_X2(b[j][0], b[j][1], bd);
            }
            #pragma unroll
            for (int i = 0; i < 4; i++)
                #pragma unroll
                for (int j = 0; j < 4; j++)
                    MMA16816(acc[i][j][0], acc[i][j][1], acc[i][j][2], acc[i][j][3],
                             a[i][0], a[i][1], a[i][2], a[i][3], b[j][0], b[j][1]);
        }
        __syncthreads();
    }

    // epilogue
    #pragma unroll
    for (int i = 0; i < 4; i++) {
        #pragma unroll
        for (int j = 0; j < 4; j++) {
            int n = n0 + wn + j * 8 + (lane & 3) * 2;
            if (n >= p.N) continue;
            #pragma unroll
            for (int half = 0; half < 2; half++) {
                int m = m0 + wm + i * 16 + (lane >> 2) + half * 8;
                float vx = acc[i][j][half * 2 + 0] * p.alpha;
                float vy = acc[i][j][half * 2 + 1] * p.alpha;
                if (p.bias) { vx += p.bias[n]; vy += p.bias[n + 1]; }
                if (p.act)  { vx = gelu_f(vx); vy = gelu_f(vy); }
                const long base = coff + (long)m * p.cs_m + n;
                if (p.R) {
                    float2 rr = *(const float2*)(p.R + base);
                    vx += rr.x; vy += rr.y;
                }
                if (p.Cf) *(float2*)(p.Cf + base) = make_float2(vx, vy);
                if (p.Ch) {
                    __nv_bfloat16 h0, h1, l0, l1;
                    splitbf(vx, h0, l0); splitbf(vy, h1, l1);
                    *(__nv_bfloat162*)(p.Ch + base) = __halves2bfloat162(h0, h1);
                    *(__nv_bfloat162*)(p.Cl + base) = __halves2bfloat162(l0, l1);
                }
            }
        }
    }
}

// ---------------- prep kernels ----------------
__global__ void __launch_bounds__(256) prep_qkvw(
    const float* __restrict__ Wq, const float* __restrict__ Wk, const float* __restrict__ Wv,
    __nv_bfloat16* __restrict__ th, __nv_bfloat16* __restrict__ tl)
{
    int idx = blockIdx.x * 256 + threadIdx.x;
    if (idx >= DD * DD) return;
    int n = idx / DD, d = idx % DD;
    int h = n >> 6, c = n & 63;
    size_t src = (size_t)h * DD * DHH + (size_t)d * DHH + c;
    __nv_bfloat16 hh, ll;
    splitbf(Wq[src], hh, ll); th[idx] = hh;            tl[idx] = ll;
    splitbf(Wk[src], hh, ll); th[idx + DD*DD] = hh;    tl[idx + DD*DD] = ll;
    splitbf(Wv[src], hh, ll); th[idx + 2*DD*DD] = hh;  tl[idx + 2*DD*DD] = ll;
}

__global__ void __launch_bounds__(256) prep_transpose(
    const float* __restrict__ W, int K, int N,
    __nv_bfloat16* __restrict__ th, __nv_bfloat16* __restrict__ tl)
{
    long idx = (long)blockIdx.x * 256 + threadIdx.x;
    if (idx >= (long)K * N) return;
    int n = (int)(idx / K), k = (int)(idx % K);
    __nv_bfloat16 hh, ll;
    splitbf(W[(long)k * N + n], hh, ll);
    th[idx] = hh; tl[idx] = ll;
}

// v [b,t,h*64+c] fp32 -> vT [(b*12+h)*64+c, t] hi/lo bf16
__global__ void __launch_bounds__(256) vtrans(
    const float* __restrict__ v, __nv_bfloat16* __restrict__ th, __nv_bfloat16* __restrict__ tl)
{
    __shared__ float tile[32][33];
    int z = blockIdx.z, b = z / HH, h = z % HH;
    int t0 = blockIdx.x * 32, c0 = blockIdx.y * 32;
    int tx = threadIdx.x, ty = threadIdx.y;
    for (int i = ty; i < 32; i += 8)
        tile[i][tx] = v[(size_t)(b * SSEQ + t0 + i) * DD + h * DHH + c0 + tx];
    __syncthreads();
    for (int i = ty; i < 32; i += 8) {
        __nv_bfloat16 hh, ll;
        splitbf(tile[tx][i], hh, ll);
        size_t o = ((size_t)z * DHH + c0 + i) * SSEQ + t0 + tx;
        th[o] = hh; tl[o] = ll;
    }
}

// ---------------- LayerNorm -> split bf16 ----------------
__global__ void __launch_bounds__(256) lnorm_kernel(
    const float* __restrict__ x, const float* __restrict__ g, const float* __restrict__ b,
    __nv_bfloat16* __restrict__ oh, __nv_bfloat16* __restrict__ ol)
{
    size_t row = blockIdx.x;
    const float* xr = x + row * DD;
    int t = threadIdx.x;
    float v0 = xr[t], v1 = xr[t + 256], v2 = xr[t + 512];
    float s  = v0 + v1 + v2;
    float s2 = v0*v0 + v1*v1 + v2*v2;
    #pragma unroll
    for (int o = 16; o; o >>= 1) {
        s  += __shfl_xor_sync(0xFFFFFFFFu, s,  o);
        s2 += __shfl_xor_sync(0xFFFFFFFFu, s2, o);
    }
    __shared__ float sh[2][8];
    int w = t >> 5, l = t & 31;
    if (l == 0) { sh[0][w] = s; sh[1][w] = s2; }
    __syncthreads();
    s = 0.f; s2 = 0.f;
    #pragma unroll
    for (int i = 0; i < 8; i++) { s += sh[0][i]; s2 += sh[1][i]; }
    float mean = s * (1.f / 768.f);
    float var  = s2 * (1.f / 768.f) - mean * mean;
    float inv  = rsqrtf(var + 1e-5f);
    __nv_bfloat16 hh, ll;
    float y0 = (v0 - mean) * inv * g[t]       + b[t];
    float y1 = (v1 - mean) * inv * g[t + 256] + b[t + 256];
    float y2 = (v2 - mean) * inv * g[t + 512] + b[t + 512];
    splitbf(y0, hh, ll); oh[row*DD + t]       = hh; ol[row*DD + t]       = ll;
    splitbf(y1, hh, ll); oh[row*DD + t + 256] = hh; ol[row*DD + t + 256] = ll;
    splitbf(y2, hh, ll); oh[row*DD + t + 512] = hh; ol[row*DD + t + 512] = ll;
}

// ---------------- Softmax -> split bf16 ----------------
__global__ void __launch_bounds__(256) softmax1024(
    const float* __restrict__ sc, __nv_bfloat16* __restrict__ ph, __nv_bfloat16* __restrict__ pl)
{
    size_t row = blockIdx.x;
    const float* r = sc + row * 1024;
    int t = threadIdx.x;
    float v[4];
    float mx = -1e30f;
    #pragma unroll
    for (int i = 0; i < 4; i++) { v[i] = r[t + i * 256]; mx = fmaxf(mx, v[i]); }
    #pragma unroll
    for (int o = 16; o; o >>= 1) mx = fmaxf(mx, __shfl_xor_sync(0xFFFFFFFFu, mx, o));
    __shared__ float sh[8];
    int w = t >> 5, l = t & 31;
    if (l == 0) sh[w] = mx;
    __syncthreads();
    mx = sh[0];
    #pragma unroll
    for (int i = 1; i < 8; i++) mx = fmaxf(mx, sh[i]);
    float s = 0.f;
    #pragma unroll
    for (int i = 0; i < 4; i++) { v[i] = expf(v[i] - mx); s += v[i]; }
    #pragma unroll
    for (int o = 16; o; o >>= 1) s += __shfl_xor_sync(0xFFFFFFFFu, s, o);
    __syncthreads();
    if (l == 0) sh[w] = s;
    __syncthreads();
    s = 0.f;
    #pragma unroll
    for (int i = 0; i < 8; i++) s += sh[i];
    float invs = 1.f / s;
    #pragma unroll
    for (int i = 0; i < 4; i++) {
        __nv_bfloat16 hh, ll;
        splitbf(v[i] * invs, hh, ll);
        ph[row * 1024 + t + i * 256] = hh;
        pl[row * 1024 + t + i * 256] = ll;
    }
}

// ---------------- host ----------------
extern "C" void kernel_launch(void* const* d_in, const int* in_sizes, int n_in,
                              void* d_out, int out_size)
{
    (void)in_sizes; (void)n_in; (void)out_size;
    const float* x    = (const float*)d_in[0];
    const float* ln1g = (const float*)d_in[1];
    const float* ln1b = (const float*)d_in[2];
    const float* Wq   = (const float*)d_in[3];
    const float* bq   = (const float*)d_in[4];
    const float* Wk   = (const float*)d_in[5];
    const float* bk   = (const float*)d_in[6];
    const float* Wv   = (const float*)d_in[7];
    const float* bv   = (const float*)d_in[8];
    const float* Wo   = (const float*)d_in[9];
    const float* bo   = (const float*)d_in[10];
    const float* ln2g = (const float*)d_in[11];
    const float* ln2b = (const float*)d_in[12];
    const float* W1   = (const float*)d_in[13];
    const float* b1   = (const float*)d_in[14];
    const float* W2   = (const float*)d_in[15];
    const float* b2   = (const float*)d_in[16];
    float* out = (float*)d_out;

    float *v, *sc, *x2;
    __nv_bfloat16 *hh, *hl, *qh, *ql, *kh, *kl, *vth, *vtl, *ch, *cl, *ph, *pl,
                  *ffh, *ffl, *wqh, *wql, *woh, *wol, *w1h, *w1l, *w2h, *w2l;
    cudaGetSymbolAddress((void**)&v,   g_v);
    cudaGetSymbolAddress((void**)&sc,  g_sc);
    cudaGetSymbolAddress((void**)&x2,  g_x2);
    cudaGetSymbolAddress((void**)&hh,  g_hh);  cudaGetSymbolAddress((void**)&hl,  g_hl);
    cudaGetSymbolAddress((void**)&qh,  g_qh);  cudaGetSymbolAddress((void**)&ql,  g_ql);
    cudaGetSymbolAddress((void**)&kh,  g_kh);  cudaGetSymbolAddress((void**)&kl,  g_kl);
    cudaGetSymbolAddress((void**)&vth, g_vth); cudaGetSymbolAddress((void**)&vtl, g_vtl);
    cudaGetSymbolAddress((void**)&ch,  g_ch);  cudaGetSymbolAddress((void**)&cl,  g_cl);
    cudaGetSymbolAddress((void**)&ph,  g_ph);  cudaGetSymbolAddress((void**)&pl,  g_pl);
    cudaGetSymbolAddress((void**)&ffh, g_ffh); cudaGetSymbolAddress((void**)&ffl, g_ffl);
    cudaGetSymbolAddress((void**)&wqh, g_wqh); cudaGetSymbolAddress((void**)&wql, g_wql);
    cudaGetSymbolAddress((void**)&woh, g_woh); cudaGetSymbolAddress((void**)&wol, g_wol);
    cudaGetSymbolAddress((void**)&w1h, g_w1h); cudaGetSymbolAddress((void**)&w1l, g_w1l);
    cudaGetSymbolAddress((void**)&w2h, g_w2h); cudaGetSymbolAddress((void**)&w2l, g_w2l);

    // weight prep
    prep_qkvw<<<(DD * DD + 255) / 256, 256>>>(Wq, Wk, Wv, wqh, wql);
    prep_transpose<<<(DD * DD + 255) / 256, 256>>>(Wo, DD, DD, woh, wol);
    prep_transpose<<<(DD * DFF_ + 255) / 256, 256>>>(W1, DD, DFF_, w1h, w1l);
    prep_transpose<<<(DD * DFF_ + 255) / 256, 256>>>(W2, DFF_, DD, w2h, w2l);

    // ln1
    lnorm_kernel<<<MTOK, 256>>>(x, ln1g, ln1b, hh, hl);

    // Q/K/V projections
    TcP p{};
    p.Ah = hh; p.Al = hl; p.as_m = DD; p.a_out = 0; p.a_in = 0; p.a_zdiv = 1;
    p.bs_n = DD; p.b_out = 0; p.b_in = 0; p.b_zdiv = 1;
    p.cs_m = DD; p.c_out = 0; p.c_in = 0; p.c_zdiv = 1;
    p.K = DD; p.N = DD; p.alpha = 1.f; p.act = 0; p.R = nullptr;
    dim3 gproj(DD / 128, MTOK / 128, 1);
    p.Bh = wqh;             p.Bl = wql;             p.bias = bq;
    p.Cf = nullptr; p.Ch = qh; p.Cl = ql;
    tcmm<<<gproj, 256>>>(p);
    p.Bh = wqh + DD*DD;     p.Bl = wql + DD*DD;     p.bias = bk;
    p.Cf = nullptr; p.Ch = kh; p.Cl = kl;
    tcmm<<<gproj, 256>>>(p);
    p.Bh = wqh + 2*DD*DD;   p.Bl = wql + 2*DD*DD;   p.bias = bv;
    p.Cf = v; p.Ch = nullptr; p.Cl = nullptr;
    tcmm<<<gproj, 256>>>(p);

    // v transpose+split
    vtrans<<<dim3(SSEQ / 32, DHH / 32, BB * HH), dim3(32, 8)>>>(v, vth, vtl);

    // scores = 0.125 * q k^T
    {
        TcP s{};
        s.Ah = qh; s.Al = ql; s.as_m = DD;
        s.a_out = (long)SSEQ * DD; s.a_in = DHH; s.a_zdiv = HH;
        s.Bh = kh; s.Bl = kl; s.bs_n = DD;
        s.b_out = (long)SSEQ * DD; s.b_in = DHH; s.b_zdiv = HH;
        s.bias = nullptr; s.R = nullptr;
        s.Cf = sc; s.Ch = nullptr; s.Cl = nullptr;
        s.cs_m = SSEQ; s.c_out = (long)SSEQ * SSEQ; s.c_in = 0; s.c_zdiv = 1;
        s.K = DHH; s.N = SSEQ; s.alpha = 0.125f; s.act = 0;
        tcmm<<<dim3(SSEQ / 128, SSEQ / 128, BB * HH), 256>>>(s);
    }

    // softmax -> probs hi/lo
    softmax1024<<<BB * HH * SSEQ, 256>>>(sc, ph, pl);

    // ctx = probs @ v   (N=64, half the block tile masked)
    {
        TcP s{};
        s.Ah = ph; s.Al = pl; s.as_m = SSEQ;
        s.a_out = (long)SSEQ * SSEQ; s.a_in = 0; s.a_zdiv = 1;
        s.Bh = vth; s.Bl = vtl; s.bs_n = SSEQ;
        s.b_out = (long)DHH * SSEQ; s.b_in = 0; s.b_zdiv = 1;
        s.bias = nullptr; s.R = nullptr;
        s.Cf = nullptr; s.Ch = ch; s.Cl = cl;
        s.cs_m = DD; s.c_out = (long)SSEQ * DD; s.c_in = DHH; s.c_zdiv = HH;
        s.K = SSEQ; s.N = DHH; s.alpha = 1.f; s.act = 0;
        tcmm<<<dim3(1, SSEQ / 128, BB * HH), 256>>>(s);
    }

    // x2 = x + ctx @ Wo + bo
    {
        TcP s{};
        s.Ah = ch; s.Al = cl; s.as_m = DD; s.a_out = 0; s.a_in = 0; s.a_zdiv = 1;
        s.Bh = woh; s.Bl = wol; s.bs_n = DD; s.b_out = 0; s.b_in = 0; s.b_zdiv = 1;
        s.bias = bo; s.R = x;
        s.Cf = x2; s.Ch = nullptr; s.Cl = nullptr;
        s.cs_m = DD; s.c_out = 0; s.c_in = 0; s.c_zdiv = 1;
        s.K = DD; s.N = DD; s.alpha = 1.f; s.act = 0;
        tcmm<<<dim3(DD / 128, MTOK / 128, 1), 256>>>(s);
    }

    // ln2
    lnorm_kernel<<<MTOK, 256>>>(x2, ln2g, ln2b, hh, hl);

    // ff = gelu(h @ W1 + b1)
    {
        TcP s{};
        s.Ah = hh; s.Al = hl; s.as_m = DD; s.a_out = 0; s.a_in = 0; s.a_zdiv = 1;
        s.Bh = w1h; s.Bl = w1l; s.bs_n = DD; s.b_out = 0; s.b_in = 0; s.b_zdiv = 1;
        s.bias = b1; s.R = nullptr;
        s.Cf = nullptr; s.Ch = ffh; s.Cl = ffl;
        s.cs_m = DFF_; s.c_out = 0; s.c_in = 0; s.c_zdiv = 1;
        s.K = DD; s.N = DFF_; s.alpha = 1.f; s.act = 1;
        tcmm<<<dim3(DFF_ / 128, MTOK / 128, 1), 256>>>(s);
    }

    // out = x2 + ff @ W2 + b2
    {
        TcP s{};
        s.Ah = ffh; s.Al = ffl; s.as_m = DFF_; s.a_out = 0; s.a_in = 0; s.a_zdiv = 1;
        s.Bh = w2h; s.Bl = w2l; s.bs_n = DFF_; s.b_out = 0; s.b_in = 0; s.b_zdiv = 1;
        s.bias = b2; s.R = x2;
        s.Cf = out; s.Ch = nullptr; s.Cl = nullptr;
        s.cs_m = DD; s.c_out = 0; s.c_in = 0; s.c_zdiv = 1;
        s.K = DFF_; s.N = DD; s.alpha = 1.f; s.act = 0;
        tcmm<<<dim3(DD / 128, MTOK / 128, 1), 256>>>(s);
    }
}

// round 5
// speedup vs baseline: 3.2955x; 1.2199x over previous
#include <cuda_runtime.h>
#include <cuda_bf16.h>
#include <math.h>
#include <stdint.h>

#define BB   16
#define SSEQ 1024
#define DD   768
#define HH   12
#define DHH  64
#define DFF_ 3072
#define MTOK (BB*SSEQ)

// ---------------- scratch ----------------
__device__ float          g_x2 [(size_t)MTOK * DD];
__device__ __nv_bfloat16  g_hh [(size_t)MTOK * DD],  g_hl [(size_t)MTOK * DD];
__device__ __nv_bfloat16  g_qh [(size_t)MTOK * DD],  g_ql [(size_t)MTOK * DD];
__device__ __nv_bfloat16  g_kh [(size_t)MTOK * DD],  g_kl [(size_t)MTOK * DD];
__device__ __nv_bfloat16  g_vh [(size_t)MTOK * DD],  g_vl [(size_t)MTOK * DD];
__device__ __nv_bfloat16  g_ch [(size_t)MTOK * DD],  g_cl [(size_t)MTOK * DD];
__device__ __nv_bfloat16  g_ffh[(size_t)MTOK * DFF_], g_ffl[(size_t)MTOK * DFF_];
__device__ __nv_bfloat16  g_wqh[3 * DD * DD], g_wql[3 * DD * DD];
__device__ __nv_bfloat16  g_woh[DD * DD],     g_wol[DD * DD];
__device__ __nv_bfloat16  g_w1h[DD * DFF_],   g_w1l[DD * DFF_];
__device__ __nv_bfloat16  g_w2h[DD * DFF_],   g_w2l[DD * DFF_];

// ---------------- helpers ----------------
__device__ __forceinline__ uint32_t smem_u32(const void* p) {
    uint32_t a;
    asm("{ .reg .u64 t; cvta.to.shared.u64 t, %1; cvt.u32.u64 %0, t; }" : "=r"(a) : "l"(p));
    return a;
}
__device__ __forceinline__ void splitbf(float x, __nv_bfloat16& h, __nv_bfloat16& l) {
    h = __float2bfloat16(x);
    l = __float2bfloat16(x - __bfloat162float(h));
}
__device__ __forceinline__ float gelu_f(float v) {
    return 0.5f * v * (1.f + erff(v * 0.70710678118654752f));
}
__device__ __forceinline__ void split_pack(float x, float y, uint32_t& hi, uint32_t& lo) {
    __nv_bfloat16 hx = __float2bfloat16(x), hy = __float2bfloat16(y);
    __nv_bfloat16 lx = __float2bfloat16(x - __bfloat162float(hx));
    __nv_bfloat16 ly = __float2bfloat16(y - __bfloat162float(hy));
    __nv_bfloat162 H = __halves2bfloat162(hx, hy);
    __nv_bfloat162 L = __halves2bfloat162(lx, ly);
    hi = *reinterpret_cast<uint32_t*>(&H);
    lo = *reinterpret_cast<uint32_t*>(&L);
}

#define CP_ASYNC16(dst, src) \
    asm volatile("cp.async.cg.shared.global [%0], [%1], 16;" :: "r"(dst), "l"(src))
#define CP_COMMIT()  asm volatile("cp.async.commit_group;" ::: "memory")
#define CP_WAIT2()   asm volatile("cp.async.wait_group 2;" ::: "memory")
#define CP_WAIT1()   asm volatile("cp.async.wait_group 1;" ::: "memory")
#define CP_WAIT0()   asm volatile("cp.async.wait_group 0;" ::: "memory")

#define LDSM_X4(r0, r1, r2, r3, a) \
    asm volatile("ldmatrix.sync.aligned.m8n8.x4.shared.b16 {%0,%1,%2,%3}, [%4];" \
        : "=r"(r0), "=r"(r1), "=r"(r2), "=r"(r3) : "r"(a))
#define LDSM_X4T(r0, r1, r2, r3, a) \
    asm volatile("ldmatrix.sync.aligned.m8n8.x4.trans.shared.b16 {%0,%1,%2,%3}, [%4];" \
        : "=r"(r0), "=r"(r1), "=r"(r2), "=r"(r3) : "r"(a))
#define LDSM_X2(r0, r1, a) \
    asm volatile("ldmatrix.sync.aligned.m8n8.x2.shared.b16 {%0,%1}, [%2];" \
        : "=r"(r0), "=r"(r1) : "r"(a))

#define MMA16816(c0, c1, c2, c3, a0, a1, a2, a3, b0, b1) \
    asm volatile("mma.sync.aligned.m16n8k16.row.col.f32.bf16.bf16.f32 " \
        "{%0,%1,%2,%3}, {%4,%5,%6,%7}, {%8,%9}, {%0,%1,%2,%3};" \
        : "+f"(c0), "+f"(c1), "+f"(c2), "+f"(c3) \
        : "r"(a0), "r"(a1), "r"(a2), "r"(a3), "r"(b0), "r"(b1))

__device__ __forceinline__ void mma_acc(float* c, const uint32_t* a, uint32_t b0, uint32_t b1) {
    MMA16816(c[0], c[1], c[2], c[3], a[0], a[1], a[2], a[3], b0, b1);
}

// ---------------- HMMA GEMM (3-stage pipeline) ----------------
struct TcP {
    const __nv_bfloat16 *Ah, *Al, *Bh, *Bl;
    const float *bias, *R;
    float* Cf; __nv_bfloat16 *Ch, *Cl;
    long a_out, a_in, b_out, b_in, c_out, c_in;
    int a_zdiv, b_zdiv, c_zdiv;
    int as_m, bs_n, cs_m;
    int K, N; float alpha; int act;
};

#define RS   80
#define STGB (128 * RS)
#define STG2 (2 * STGB)          // 20480 per stage
#define GSMEM (3 * STG2)         // 61440

__global__ void __launch_bounds__(256, 2) tcmm(TcP p)
{
    extern __shared__ __align__(128) char gsm[];

    const int tid = threadIdx.x, wid = tid >> 5, lane = tid & 31;
    const int n0 = blockIdx.x * 128, m0 = blockIdx.y * 128, z = blockIdx.z;
    const int wm = (wid >> 2) * 64;
    const int wn = (wid & 3) * 32;

    const __nv_bfloat16* Ah = p.Ah + (long)(z / p.a_zdiv) * p.a_out + (long)(z % p.a_zdiv) * p.a_in;
    const __nv_bfloat16* Al = p.Al + (long)(z / p.a_zdiv) * p.a_out + (long)(z % p.a_zdiv) * p.a_in;
    const __nv_bfloat16* Bh = p.Bh + (long)(z / p.b_zdiv) * p.b_out + (long)(z % p.b_zdiv) * p.b_in;
    const __nv_bfloat16* Bl = p.Bl + (long)(z / p.b_zdiv) * p.b_out + (long)(z % p.b_zdiv) * p.b_in;
    const long coff = (long)(z / p.c_zdiv) * p.c_out + (long)(z % p.c_zdiv) * p.c_in;

    const uint32_t sbase = smem_u32(gsm);
    const int KC = p.K >> 5;
    const int NC = 3 * KC;

    const int rowA0 = tid >> 2,         unitA0 = tid & 3;
    const int rowA1 = (tid + 256) >> 2, unitA1 = tid & 3;
    const bool bok0 = (n0 + rowA0 < p.N);
    const bool bok1 = (n0 + rowA1 < p.N);

    float acc[4][4][4];
    #pragma unroll
    for (int i = 0; i < 4; i++)
        #pragma unroll
        for (int j = 0; j < 4; j++)
            #pragma unroll
            for (int r = 0; r < 4; r++) acc[i][j][r] = 0.f;

    auto load_stage = [&](int s, int c) {
        const int pass = c / KC;
        const int kc   = c - pass * KC;
        const long kof = (long)kc << 5;
        const __nv_bfloat16* A = (pass == 2) ? Al : Ah;
        const __nv_bfloat16* B = (pass == 1) ? Bl : Bh;
        uint32_t dA = sbase + s * STG2;
        uint32_t dB = dA + STGB;
        CP_ASYNC16(dA + rowA0 * RS + unitA0 * 16,
                   A + (long)(m0 + rowA0) * p.as_m + kof + unitA0 * 8);
        CP_ASYNC16(dA + rowA1 * RS + unitA1 * 16,
                   A + (long)(m0 + rowA1) * p.as_m + kof + unitA1 * 8);
        if (bok0)
            CP_ASYNC16(dB + rowA0 * RS + unitA0 * 16,
                       B + (long)(n0 + rowA0) * p.bs_n + kof + unitA0 * 8);
        if (bok1)
            CP_ASYNC16(dB + rowA1 * RS + unitA1 * 16,
                       B + (long)(n0 + rowA1) * p.bs_n + kof + unitA1 * 8);
    };

    load_stage(0, 0); CP_COMMIT();
    load_stage(1, 1); CP_COMMIT();

    for (int c = 0; c < NC; c++) {
        const int s = c - (c / 3) * 3;
        if (c + 2 < NC) { load_stage((c + 2) % 3, c + 2); CP_COMMIT(); CP_WAIT2(); }
        else if (c + 1 < NC) { CP_WAIT1(); }
        else { CP_WAIT0(); }
        __syncthreads();

        const uint32_t sA = sbase + s * STG2;
        const uint32_t sB = sA + STGB;

        #pragma unroll
        for (int ks = 0; ks < 2; ks++) {
            uint32_t a[4][4], b[4][2];
            #pragma unroll
            for (int i = 0; i < 4; i++) {
                uint32_t ad = sA + (uint32_t)(wm + i * 16 + (lane & 15)) * RS
                            + ks * 32 + (lane >> 4) * 16;
                LDSM_X4(a[i][0], a[i][1], a[i][2], a[i][3], ad);
            }
            #pragma unroll
            for (int j = 0; j < 4; j++) {
                uint32_t bd = sB + (uint32_t)(wn + j * 8 + (lane & 7)) * RS
                            + ks * 32 + ((lane >> 3) & 1) * 16;
                LDSM_X2(b[j][0], b[j][1], bd);
            }
            #pragma unroll
            for (int i = 0; i < 4; i++)
                #pragma unroll
                for (int j = 0; j < 4; j++)
                    MMA16816(acc[i][j][0], acc[i][j][1], acc[i][j][2], acc[i][j][3],
                             a[i][0], a[i][1], a[i][2], a[i][3], b[j][0], b[j][1]);
        }
        __syncthreads();
    }

    // epilogue
    #pragma unroll
    for (int i = 0; i < 4; i++) {
        #pragma unroll
        for (int j = 0; j < 4; j++) {
            int n = n0 + wn + j * 8 + (lane & 3) * 2;
            if (n >= p.N) continue;
            #pragma unroll
            for (int half = 0; half < 2; half++) {
                int m = m0 + wm + i * 16 + (lane >> 2) + half * 8;
                float vx = acc[i][j][half * 2 + 0] * p.alpha;
                float vy = acc[i][j][half * 2 + 1] * p.alpha;
                if (p.bias) { vx += p.bias[n]; vy += p.bias[n + 1]; }
                if (p.act)  { vx = gelu_f(vx); vy = gelu_f(vy); }
                const long base = coff + (long)m * p.cs_m + n;
                if (p.R) {
                    float2 rr = *(const float2*)(p.R + base);
                    vx += rr.x; vy += rr.y;
                }
                if (p.Cf) *(float2*)(p.Cf + base) = make_float2(vx, vy);
                if (p.Ch) {
                    __nv_bfloat16 h0, h1, l0, l1;
                    splitbf(vx, h0, l0); splitbf(vy, h1, l1);
                    *(__nv_bfloat162*)(p.Ch + base) = __halves2bfloat162(h0, h1);
                    *(__nv_bfloat162*)(p.Cl + base) = __halves2bfloat162(l0, l1);
                }
            }
        }
    }
}

// ---------------- Flash attention ----------------
// grid (8, 1, 192): mtile, -, b*12+h. 256 threads = 8 warps; warp owns 16 q-rows.
#define FRS  144
#define FPL  (128 * FRS)      // 18432 per plane
#define FSTG (4 * FPL)        // Kh,Kl,Vh,Vl per stage = 73728
#define FSMEM (2 * FPL + 2 * FSTG)   // Qh,Ql + 2 stages = 184320

__global__ void __launch_bounds__(256, 1) flash_attn(
    const __nv_bfloat16* __restrict__ qh, const __nv_bfloat16* __restrict__ ql,
    const __nv_bfloat16* __restrict__ kh, const __nv_bfloat16* __restrict__ kl,
    const __nv_bfloat16* __restrict__ vh, const __nv_bfloat16* __restrict__ vl,
    __nv_bfloat16* __restrict__ ch, __nv_bfloat16* __restrict__ cl)
{
    extern __shared__ __align__(128) char fsm[];
    const int tid = threadIdx.x, wid = tid >> 5, lane = tid & 31;
    const int b = blockIdx.z / HH, h = blockIdx.z % HH;
    const size_t qrow0 = (size_t)b * SSEQ + blockIdx.x * 128;
    const size_t krow0 = (size_t)b * SSEQ;
    const int hc = h * DHH;

    const uint32_t sb  = smem_u32(fsm);
    const uint32_t sKV = sb + 2 * FPL;

    // Q load (2 planes x 1024 16B-chunks)
    {
        #pragma unroll
        for (int i = 0; i < 8; i++) {
            int id = tid + i * 256;
            int pl = id >> 10, rc = id & 1023;
            int row = rc >> 3, cu = rc & 7;
            const __nv_bfloat16* src = (pl ? ql : qh) + (qrow0 + row) * DD + hc + cu * 8;
            CP_ASYNC16(sb + pl * FPL + (uint32_t)(row * FRS + cu * 16), src);
        }
    }
    auto loadKV = [&](int kt, int s) {
        uint32_t base = sKV + (uint32_t)s * FSTG;
        size_t r0 = krow0 + (size_t)kt * 128;
        #pragma unroll
        for (int i = 0; i < 16; i++) {
            int id = tid + i * 256;
            int pl = id >> 10, rc = id & 1023;
            int row = rc >> 3, cu = rc & 7;
            const __nv_bfloat16* g = (pl == 0) ? kh : (pl == 1) ? kl : (pl == 2) ? vh : vl;
            CP_ASYNC16(base + (uint32_t)(pl * FPL + row * FRS + cu * 16),
                       g + (r0 + row) * DD + hc + cu * 8);
        }
    };
    loadKV(0, 0); CP_COMMIT();
    loadKV(1, 1); CP_COMMIT();
    CP_WAIT1(); __syncthreads();

    // Q fragments (persistent)
    uint32_t qfh[4][4], qfl[4][4];
    const int mw = wid * 16;
    #pragma unroll
    for (int kf = 0; kf < 4; kf++) {
        uint32_t ad = sb + (uint32_t)((mw + (lane & 15)) * FRS + kf * 32 + (lane >> 4) * 16);
        LDSM_X4(qfh[kf][0], qfh[kf][1], qfh[kf][2], qfh[kf][3], ad);
        LDSM_X4(qfl[kf][0], qfl[kf][1], qfl[kf][2], qfl[kf][3], ad + FPL);
    }

    float accO[8][4];
    #pragma unroll
    for (int i = 0; i < 8; i++) { accO[i][0] = accO[i][1] = accO[i][2] = accO[i][3] = 0.f; }
    float mrun0 = -1e30f, mrun1 = -1e30f, lrun0 = 0.f, lrun1 = 0.f;

    for (int kt = 0; kt < 8; kt++) {
        const uint32_t bK = sKV + (uint32_t)(kt & 1) * FSTG;
        const uint32_t bV = bK + 2 * FPL;

        // ---- S = 0.125 * Q K^T (3-pass split) ----
        float S[16][4];
        #pragma unroll
        for (int j = 0; j < 16; j++) { S[j][0] = S[j][1] = S[j][2] = S[j][3] = 0.f; }

        #pragma unroll
        for (int pass = 0; pass < 3; pass++) {
            const uint32_t kb = bK + ((pass == 1) ? FPL : 0);
            #pragma unroll
            for (int kf = 0; kf < 4; kf++) {
                const uint32_t* qa = (pass == 2) ? qfl[kf] : qfh[kf];
                #pragma unroll
                for (int jp = 0; jp < 8; jp++) {
                    uint32_t b0, b1, b2, b3;
                    uint32_t ad = kb + (uint32_t)((jp * 16 + ((lane >> 4) & 1) * 8 + (lane & 7)) * FRS
                                + kf * 32 + ((lane >> 3) & 1) * 16);
                    LDSM_X4(b0, b1, b2, b3, ad);
                    mma_acc(S[2 * jp],     qa, b0, b1);
                    mma_acc(S[2 * jp + 1], qa, b2, b3);
                }
            }
        }

        // ---- online softmax ----
        float rm0 = -1e30f, rm1 = -1e30f;
        #pragma unroll
        for (int j = 0; j < 16; j++) {
            S[j][0] *= 0.125f; S[j][1] *= 0.125f; S[j][2] *= 0.125f; S[j][3] *= 0.125f;
            rm0 = fmaxf(rm0, fmaxf(S[j][0], S[j][1]));
            rm1 = fmaxf(rm1, fmaxf(S[j][2], S[j][3]));
        }
        rm0 = fmaxf(rm0, __shfl_xor_sync(0xFFFFFFFFu, rm0, 1));
        rm0 = fmaxf(rm0, __shfl_xor_sync(0xFFFFFFFFu, rm0, 2));
        rm1 = fmaxf(rm1, __shfl_xor_sync(0xFFFFFFFFu, rm1, 1));
        rm1 = fmaxf(rm1, __shfl_xor_sync(0xFFFFFFFFu, rm1, 2));
        float mn0 = fmaxf(mrun0, rm0), mn1 = fmaxf(mrun1, rm1);
        float sc0 = __expf(mrun0 - mn0), sc1 = __expf(mrun1 - mn1);
        mrun0 = mn0; mrun1 = mn1;
        float rs0 = 0.f, rs1 = 0.f;
        #pragma unroll
        for (int j = 0; j < 16; j++) {
            S[j][0] = __expf(S[j][0] - mn0); S[j][1] = __expf(S[j][1] - mn0);
            S[j][2] = __expf(S[j][2] - mn1); S[j][3] = __expf(S[j][3] - mn1);
            rs0 += S[j][0] + S[j][1];
            rs1 += S[j][2] + S[j][3];
        }
        rs0 += __shfl_xor_sync(0xFFFFFFFFu, rs0, 1);
        rs0 += __shfl_xor_sync(0xFFFFFFFFu, rs0, 2);
        rs1 += __shfl_xor_sync(0xFFFFFFFFu, rs1, 1);
        rs1 += __shfl_xor_sync(0xFFFFFFFFu, rs1, 2);
        lrun0 = lrun0 * sc0 + rs0;
        lrun1 = lrun1 * sc1 + rs1;
        #pragma unroll
        for (int i = 0; i < 8; i++) {
            accO[i][0] *= sc0; accO[i][1] *= sc0;
            accO[i][2] *= sc1; accO[i][3] *= sc1;
        }

        // ---- O += P V (3-pass split; P frags direct from S regs) ----
        #pragma unroll
        for (int kf = 0; kf < 8; kf++) {
            uint32_t pah[4], pal[4];
            split_pack(S[2 * kf][0],     S[2 * kf][1],     pah[0], pal[0]);
            split_pack(S[2 * kf][2],     S[2 * kf][3],     pah[1], pal[1]);
            split_pack(S[2 * kf + 1][0], S[2 * kf + 1][1], pah[2], pal[2]);
            split_pack(S[2 * kf + 1][2], S[2 * kf + 1][3], pah[3], pal[3]);
            uint32_t vhf[4][4], vlf[4][4];
            #pragma unroll
            for (int np = 0; np < 4; np++) {
                uint32_t ad = bV + (uint32_t)((kf * 16 + ((lane >> 3) & 1) * 8 + (lane & 7)) * FRS
                            + np * 32 + (lane >> 4) * 16);
                LDSM_X4T(vhf[np][0], vhf[np][1], vhf[np][2], vhf[np][3], ad);
                LDSM_X4T(vlf[np][0], vlf[np][1], vlf[np][2], vlf[np][3], ad + FPL);
            }
            #pragma unroll
            for (int np = 0; np < 4; np++) {
                mma_acc(accO[2 * np],     pah, vhf[np][0], vhf[np][1]);
                mma_acc(accO[2 * np + 1], pah, vhf[np][2], vhf[np][3]);
                mma_acc(accO[2 * np],     pah, vlf[np][0], vlf[np][1]);
                mma_acc(accO[2 * np + 1], pah, vlf[np][2], vlf[np][3]);
                mma_acc(accO[2 * np],     pal, vhf[np][0], vhf[np][1]);
                mma_acc(accO[2 * np + 1], pal, vhf[np][2], vhf[np][3]);
            }
        }

        __syncthreads();
        if (kt + 2 < 8) { loadKV(kt + 2, kt & 1); CP_COMMIT(); }
        if (kt + 1 < 8) {
            if (kt + 2 < 8) { CP_WAIT1(); } else { CP_WAIT0(); }
            __syncthreads();
        }
    }

    // ---- epilogue: O/l -> split bf16 ctx ----
    float inv0 = 1.f / lrun0, inv1 = 1.f / lrun1;
    size_t r0 = qrow0 + mw + (lane >> 2);
    #pragma unroll
    for (int nt = 0; nt < 8; nt++) {
        int col = hc + nt * 8 + 2 * (lane & 3);
        {
            float vx = accO[nt][0] * inv0, vy = accO[nt][1] * inv0;
            __nv_bfloat16 h0, h1, l0, l1;
            splitbf(vx, h0, l0); splitbf(vy, h1, l1);
            size_t base = r0 * DD + col;
            *(__nv_bfloat162*)(ch + base) = __halves2bfloat162(h0, h1);
            *(__nv_bfloat162*)(cl + base) = __halves2bfloat162(l0, l1);
        }
        {
            float vx = accO[nt][2] * inv1, vy = accO[nt][3] * inv1;
            __nv_bfloat16 h0, h1, l0, l1;
            splitbf(vx, h0, l0); splitbf(vy, h1, l1);
            size_t base = (r0 + 8) * DD + col;
            *(__nv_bfloat162*)(ch + base) = __halves2bfloat162(h0, h1);
            *(__nv_bfloat162*)(cl + base) = __halves2bfloat162(l0, l1);
        }
    }
}

// ---------------- prep kernels ----------------
__global__ void __launch_bounds__(256) prep_qkvw(
    const float* __restrict__ Wq, const float* __restrict__ Wk, const float* __restrict__ Wv,
    __nv_bfloat16* __restrict__ th, __nv_bfloat16* __restrict__ tl)
{
    int idx = blockIdx.x * 256 + threadIdx.x;
    if (idx >= DD * DD) return;
    int n = idx / DD, d = idx % DD;
    int h = n >> 6, c = n & 63;
    size_t src = (size_t)h * DD * DHH + (size_t)d * DHH + c;
    __nv_bfloat16 hh, ll;
    splitbf(Wq[src], hh, ll); th[idx] = hh;            tl[idx] = ll;
    splitbf(Wk[src], hh, ll); th[idx + DD*DD] = hh;    tl[idx + DD*DD] = ll;
    splitbf(Wv[src], hh, ll); th[idx + 2*DD*DD] = hh;  tl[idx + 2*DD*DD] = ll;
}

__global__ void __launch_bounds__(256) prep_transpose(
    const float* __restrict__ W, int K, int N,
    __nv_bfloat16* __restrict__ th, __nv_bfloat16* __restrict__ tl)
{
    long idx = (long)blockIdx.x * 256 + threadIdx.x;
    if (idx >= (long)K * N) return;
    int n = (int)(idx / K), k = (int)(idx % K);
    __nv_bfloat16 hh, ll;
    splitbf(W[(long)k * N + n], hh, ll);
    th[idx] = hh; tl[idx] = ll;
}

// ---------------- LayerNorm -> split bf16 ----------------
__global__ void __launch_bounds__(256) lnorm_kernel(
    const float* __restrict__ x, const float* __restrict__ g, const float* __restrict__ b,
    __nv_bfloat16* __restrict__ oh, __nv_bfloat16* __restrict__ ol)
{
    size_t row = blockIdx.x;
    const float* xr = x + row * DD;
    int t = threadIdx.x;
    float v0 = xr[t], v1 = xr[t + 256], v2 = xr[t + 512];
    float s  = v0 + v1 + v2;
    float s2 = v0*v0 + v1*v1 + v2*v2;
    #pragma unroll
    for (int o = 16; o; o >>= 1) {
        s  += __shfl_xor_sync(0xFFFFFFFFu, s,  o);
        s2 += __shfl_xor_sync(0xFFFFFFFFu, s2, o);
    }
    __shared__ float sh[2][8];
    int w = t >> 5, l = t & 31;
    if (l == 0) { sh[0][w] = s; sh[1][w] = s2; }
    __syncthreads();
    s = 0.f; s2 = 0.f;
    #pragma unroll
    for (int i = 0; i < 8; i++) { s += sh[0][i]; s2 += sh[1][i]; }
    float mean = s * (1.f / 768.f);
    float var  = s2 * (1.f / 768.f) - mean * mean;
    float inv  = rsqrtf(var + 1e-5f);
    __nv_bfloat16 hh, ll;
    float y0 = (v0 - mean) * inv * g[t]       + b[t];
    float y1 = (v1 - mean) * inv * g[t + 256] + b[t + 256];
    float y2 = (v2 - mean) * inv * g[t + 512] + b[t + 512];
    splitbf(y0, hh, ll); oh[row*DD + t]       = hh; ol[row*DD + t]       = ll;
    splitbf(y1, hh, ll); oh[row*DD + t + 256] = hh; ol[row*DD + t + 256] = ll;
    splitbf(y2, hh, ll); oh[row*DD + t + 512] = hh; ol[row*DD + t + 512] = ll;
}

// ---------------- host ----------------
extern "C" void kernel_launch(void* const* d_in, const int* in_sizes, int n_in,
                              void* d_out, int out_size)
{
    (void)in_sizes; (void)n_in; (void)out_size;
    const float* x    = (const float*)d_in[0];
    const float* ln1g = (const float*)d_in[1];
    const float* ln1b = (const float*)d_in[2];
    const float* Wq   = (const float*)d_in[3];
    const float* bq   = (const float*)d_in[4];
    const float* Wk   = (const float*)d_in[5];
    const float* bk   = (const float*)d_in[6];
    const float* Wv   = (const float*)d_in[7];
    const float* bv   = (const float*)d_in[8];
    const float* Wo   = (const float*)d_in[9];
    const float* bo   = (const float*)d_in[10];
    const float* ln2g = (const float*)d_in[11];
    const float* ln2b = (const float*)d_in[12];
    const float* W1   = (const float*)d_in[13];
    const float* b1   = (const float*)d_in[14];
    const float* W2   = (const float*)d_in[15];
    const float* b2   = (const float*)d_in[16];
    float* out = (float*)d_out;

    float *x2;
    __nv_bfloat16 *hh, *hl, *qh, *ql, *kh, *kl, *vh, *vl, *ch, *cl,
                  *ffh, *ffl, *wqh, *wql, *woh, *wol, *w1h, *w1l, *w2h, *w2l;
    cudaGetSymbolAddress((void**)&x2,  g_x2);
    cudaGetSymbolAddress((void**)&hh,  g_hh);  cudaGetSymbolAddress((void**)&hl,  g_hl);
    cudaGetSymbolAddress((void**)&qh,  g_qh);  cudaGetSymbolAddress((void**)&ql,  g_ql);
    cudaGetSymbolAddress((void**)&kh,  g_kh);  cudaGetSymbolAddress((void**)&kl,  g_kl);
    cudaGetSymbolAddress((void**)&vh,  g_vh);  cudaGetSymbolAddress((void**)&vl,  g_vl);
    cudaGetSymbolAddress((void**)&ch,  g_ch);  cudaGetSymbolAddress((void**)&cl,  g_cl);
    cudaGetSymbolAddress((void**)&ffh, g_ffh); cudaGetSymbolAddress((void**)&ffl, g_ffl);
    cudaGetSymbolAddress((void**)&wqh, g_wqh); cudaGetSymbolAddress((void**)&wql, g_wql);
    cudaGetSymbolAddress((void**)&woh, g_woh); cudaGetSymbolAddress((void**)&wol, g_wol);
    cudaGetSymbolAddress((void**)&w1h, g_w1h); cudaGetSymbolAddress((void**)&w1l, g_w1l);
    cudaGetSymbolAddress((void**)&w2h, g_w2h); cudaGetSymbolAddress((void**)&w2l, g_w2l);

    cudaFuncSetAttribute(tcmm, cudaFuncAttributeMaxDynamicSharedMemorySize, GSMEM);
    cudaFuncSetAttribute(flash_attn, cudaFuncAttributeMaxDynamicSharedMemorySize, FSMEM);

    // weight prep
    prep_qkvw<<<(DD * DD + 255) / 256, 256>>>(Wq, Wk, Wv, wqh, wql);
    prep_transpose<<<(DD * DD + 255) / 256, 256>>>(Wo, DD, DD, woh, wol);
    prep_transpose<<<(DD * DFF_ + 255) / 256, 256>>>(W1, DD, DFF_, w1h, w1l);
    prep_transpose<<<(DD * DFF_ + 255) / 256, 256>>>(W2, DFF_, DD, w2h, w2l);

    // ln1
    lnorm_kernel<<<MTOK, 256>>>(x, ln1g, ln1b, hh, hl);

    // Q/K/V projections (all outputs split bf16)
    TcP p{};
    p.Ah = hh; p.Al = hl; p.as_m = DD; p.a_out = 0; p.a_in = 0; p.a_zdiv = 1;
    p.bs_n = DD; p.b_out = 0; p.b_in = 0; p.b_zdiv = 1;
    p.cs_m = DD; p.c_out = 0; p.c_in = 0; p.c_zdiv = 1;
    p.K = DD; p.N = DD; p.alpha = 1.f; p.act = 0; p.R = nullptr; p.Cf = nullptr;
    dim3 gproj(DD / 128, MTOK / 128, 1);
    p.Bh = wqh;              p.Bl = wql;              p.bias = bq;
    p.Ch = qh; p.Cl = ql;    tcmm<<<gproj, 256, GSMEM>>>(p);
    p.Bh = wqh + DD*DD;      p.Bl = wql + DD*DD;      p.bias = bk;
    p.Ch = kh; p.Cl = kl;    tcmm<<<gproj, 256, GSMEM>>>(p);
    p.Bh = wqh + 2*DD*DD;    p.Bl = wql + 2*DD*DD;    p.bias = bv;
    p.Ch = vh; p.Cl = vl;    tcmm<<<gproj, 256, GSMEM>>>(p);

    // fused attention: scores + softmax + ctx
    flash_attn<<<dim3(SSEQ / 128, 1, BB * HH), 256, FSMEM>>>(
        qh, ql, kh, kl, vh, vl, ch, cl);

    // x2 = x + ctx @ Wo + bo
    {
        TcP s{};
        s.Ah = ch; s.Al = cl; s.as_m = DD; s.a_out = 0; s.a_in = 0; s.a_zdiv = 1;
        s.Bh = woh; s.Bl = wol; s.bs_n = DD; s.b_out = 0; s.b_in = 0; s.b_zdiv = 1;
        s.bias = bo; s.R = x;
        s.Cf = x2; s.Ch = nullptr; s.Cl = nullptr;
        s.cs_m = DD; s.c_out = 0; s.c_in = 0; s.c_zdiv = 1;
        s.K = DD; s.N = DD; s.alpha = 1.f; s.act = 0;
        tcmm<<<dim3(DD / 128, MTOK / 128, 1), 256, GSMEM>>>(s);
    }

    // ln2
    lnorm_kernel<<<MTOK, 256>>>(x2, ln2g, ln2b, hh, hl);

    // ff = gelu(h @ W1 + b1)
    {
        TcP s{};
        s.Ah = hh; s.Al = hl; s.as_m = DD; s.a_out = 0; s.a_in = 0; s.a_zdiv = 1;
        s.Bh = w1h; s.Bl = w1l; s.bs_n = DD; s.b_out = 0; s.b_in = 0; s.b_zdiv = 1;
        s.bias = b1; s.R = nullptr;
        s.Cf = nullptr; s.Ch = ffh; s.Cl = ffl;
        s.cs_m = DFF_; s.c_out = 0; s.c_in = 0; s.c_zdiv = 1;
        s.K = DD; s.N = DFF_; s.alpha = 1.f; s.act = 1;
        tcmm<<<dim3(DFF_ / 128, MTOK / 128, 1), 256, GSMEM>>>(s);
    }

    // out = x2 + ff @ W2 + b2
    {
        TcP s{};
        s.Ah = ffh; s.Al = ffl; s.as_m = DFF_; s.a_out = 0; s.a_in = 0; s.a_zdiv = 1;
        s.Bh = w2h; s.Bl = w2l; s.bs_n = DFF_; s.b_out = 0; s.b_in = 0; s.b_zdiv = 1;
        s.bias = b2; s.R = x2;
        s.Cf = out; s.Ch = nullptr; s.Cl = nullptr;
        s.cs_m = DD; s.c_out = 0; s.c_in = 0; s.c_zdiv = 1;
        s.K = DFF_; s.N = DD; s.alpha = 1.f; s.act = 0;
        tcmm<<<dim3(DD / 128, MTOK / 128, 1), 256, GSMEM>>>(s);
    }
}

// round 6
// speedup vs baseline: 3.6873x; 1.1189x over previous
#include <cuda_runtime.h>
#include <cuda_bf16.h>
#include <cuda_fp16.h>
#include <math.h>
#include <stdint.h>

#define BB   16
#define SSEQ 1024
#define DD   768
#define HH   12
#define DHH  64
#define DFF_ 3072
#define MTOK (BB*SSEQ)
#define QSCL 0.18033688011112042f   /* 0.125 * log2(e) */

// ---------------- scratch ----------------
__device__ float          g_x2 [(size_t)MTOK * DD];
__device__ __nv_bfloat16  g_hh [(size_t)MTOK * DD],  g_hl [(size_t)MTOK * DD];
__device__ __nv_bfloat16  g_qh [(size_t)MTOK * DD],  g_ql [(size_t)MTOK * DD];
__device__ __nv_bfloat16  g_kh [(size_t)MTOK * DD],  g_kl [(size_t)MTOK * DD];
__device__ __half         g_vh [(size_t)MTOK * DD],  g_vl [(size_t)MTOK * DD];
__device__ __nv_bfloat16  g_ch [(size_t)MTOK * DD],  g_cl [(size_t)MTOK * DD];
__device__ __nv_bfloat16  g_ffh[(size_t)MTOK * DFF_], g_ffl[(size_t)MTOK * DFF_];
__device__ __nv_bfloat16  g_wqh[3 * DD * DD], g_wql[3 * DD * DD];
__device__ __nv_bfloat16  g_woh[DD * DD],     g_wol[DD * DD];
__device__ __nv_bfloat16  g_w1h[DD * DFF_],   g_w1l[DD * DFF_];
__device__ __nv_bfloat16  g_w2h[DD * DFF_],   g_w2l[DD * DFF_];

// ---------------- helpers ----------------
__device__ __forceinline__ uint32_t smem_u32(const void* p) {
    uint32_t a;
    asm("{ .reg .u64 t; cvta.to.shared.u64 t, %1; cvt.u32.u64 %0, t; }" : "=r"(a) : "l"(p));
    return a;
}
__device__ __forceinline__ void splitbf(float x, __nv_bfloat16& h, __nv_bfloat16& l) {
    h = __float2bfloat16(x);
    l = __float2bfloat16(x - __bfloat162float(h));
}
__device__ __forceinline__ float gelu_f(float v) {
    return 0.5f * v * (1.f + erff(v * 0.70710678118654752f));
}

#define CP_ASYNC16(dst, src) \
    asm volatile("cp.async.cg.shared.global [%0], [%1], 16;" :: "r"(dst), "l"(src))
#define CP_COMMIT()  asm volatile("cp.async.commit_group;" ::: "memory")
#define CP_WAIT2()   asm volatile("cp.async.wait_group 2;" ::: "memory")
#define CP_WAIT1()   asm volatile("cp.async.wait_group 1;" ::: "memory")
#define CP_WAIT0()   asm volatile("cp.async.wait_group 0;" ::: "memory")

#define LDSM_X4(r0, r1, r2, r3, a) \
    asm volatile("ldmatrix.sync.aligned.m8n8.x4.shared.b16 {%0,%1,%2,%3}, [%4];" \
        : "=r"(r0), "=r"(r1), "=r"(r2), "=r"(r3) : "r"(a))
#define LDSM_X4T(r0, r1, r2, r3, a) \
    asm volatile("ldmatrix.sync.aligned.m8n8.x4.trans.shared.b16 {%0,%1,%2,%3}, [%4];" \
        : "=r"(r0), "=r"(r1), "=r"(r2), "=r"(r3) : "r"(a))

#define MMA16816(c0, c1, c2, c3, a0, a1, a2, a3, b0, b1) \
    asm volatile("mma.sync.aligned.m16n8k16.row.col.f32.bf16.bf16.f32 " \
        "{%0,%1,%2,%3}, {%4,%5,%6,%7}, {%8,%9}, {%0,%1,%2,%3};" \
        : "+f"(c0), "+f"(c1), "+f"(c2), "+f"(c3) \
        : "r"(a0), "r"(a1), "r"(a2), "r"(a3), "r"(b0), "r"(b1))

#define MMAF16(c0, c1, c2, c3, a0, a1, a2, a3, b0, b1) \
    asm volatile("mma.sync.aligned.m16n8k16.row.col.f32.f16.f16.f32 " \
        "{%0,%1,%2,%3}, {%4,%5,%6,%7}, {%8,%9}, {%0,%1,%2,%3};" \
        : "+f"(c0), "+f"(c1), "+f"(c2), "+f"(c3) \
        : "r"(a0), "r"(a1), "r"(a2), "r"(a3), "r"(b0), "r"(b1))

__device__ __forceinline__ void mma_acc(float* c, const uint32_t* a, uint32_t b0, uint32_t b1) {
    MMA16816(c[0], c[1], c[2], c[3], a[0], a[1], a[2], a[3], b0, b1);
}
__device__ __forceinline__ void mma_f16(float* c, const uint32_t* a, uint32_t b0, uint32_t b1) {
    MMAF16(c[0], c[1], c[2], c[3], a[0], a[1], a[2], a[3], b0, b1);
}

// ---------------- HMMA GEMM (4-stage, single sync per chunk) ----------------
struct TcP {
    const __nv_bfloat16 *Ah, *Al, *Bh, *Bl;
    const float *bias, *bias1, *bias2, *R;
    float* Cf; __nv_bfloat16 *Ch, *Cl, *Ch1, *Cl1;
    __half *Vh, *Vl;
    long a_out, a_in, b_out, b_in, c_out, c_in;
    int a_zdiv, b_zdiv, c_zdiv;
    int as_m, bs_n, cs_m;
    int K, N; float alpha; int act; int qkv;
};

#define RS   80
#define STGB (128 * RS)
#define STG2 (2 * STGB)          // 20480 per stage
#define GSMEM (4 * STG2)         // 81920

__global__ void __launch_bounds__(256, 2) tcmm(TcP p)
{
    extern __shared__ __align__(128) char gsm[];

    const int tid = threadIdx.x, wid = tid >> 5, lane = tid & 31;
    const int n0 = blockIdx.x * 128, m0 = blockIdx.y * 128, z = blockIdx.z;
    const int wm = (wid >> 2) * 64;
    const int wn = (wid & 3) * 32;

    const __nv_bfloat16* Ah = p.Ah + (long)(z / p.a_zdiv) * p.a_out + (long)(z % p.a_zdiv) * p.a_in;
    const __nv_bfloat16* Al = p.Al + (long)(z / p.a_zdiv) * p.a_out + (long)(z % p.a_zdiv) * p.a_in;
    const __nv_bfloat16* Bh = p.Bh + (long)(z / p.b_zdiv) * p.b_out + (long)(z % p.b_zdiv) * p.b_in;
    const __nv_bfloat16* Bl = p.Bl + (long)(z / p.b_zdiv) * p.b_out + (long)(z % p.b_zdiv) * p.b_in;
    const long coff = (long)(z / p.c_zdiv) * p.c_out + (long)(z % p.c_zdiv) * p.c_in;

    const uint32_t sbase = smem_u32(gsm);
    const int KC = p.K >> 5;
    const int NC = 3 * KC;

    const int rowA0 = tid >> 2,         unitA0 = tid & 3;
    const int rowA1 = (tid + 256) >> 2, unitA1 = tid & 3;
    const bool bok0 = (n0 + rowA0 < p.N);
    const bool bok1 = (n0 + rowA1 < p.N);

    float acc[4][4][4];
    #pragma unroll
    for (int i = 0; i < 4; i++)
        #pragma unroll
        for (int j = 0; j < 4; j++)
            #pragma unroll
            for (int r = 0; r < 4; r++) acc[i][j][r] = 0.f;

    auto load_stage = [&](int s, int c) {
        const int pass = c / KC;
        const int kc   = c - pass * KC;
        const long kof = (long)kc << 5;
        const __nv_bfloat16* A = (pass == 2) ? Al : Ah;
        const __nv_bfloat16* B = (pass == 1) ? Bl : Bh;
        uint32_t dA = sbase + s * STG2;
        uint32_t dB = dA + STGB;
        CP_ASYNC16(dA + rowA0 * RS + unitA0 * 16,
                   A + (long)(m0 + rowA0) * p.as_m + kof + unitA0 * 8);
        CP_ASYNC16(dA + rowA1 * RS + unitA1 * 16,
                   A + (long)(m0 + rowA1) * p.as_m + kof + unitA1 * 8);
        if (bok0)
            CP_ASYNC16(dB + rowA0 * RS + unitA0 * 16,
                       B + (long)(n0 + rowA0) * p.bs_n + kof + unitA0 * 8);
        if (bok1)
            CP_ASYNC16(dB + rowA1 * RS + unitA1 * 16,
                       B + (long)(n0 + rowA1) * p.bs_n + kof + unitA1 * 8);
    };

    load_stage(0, 0); CP_COMMIT();
    load_stage(1, 1); CP_COMMIT();
    load_stage(2, 2); CP_COMMIT();

    for (int c = 0; c < NC; c++) {
        const int rem = NC - 1 - c;
        if (rem >= 2)      { CP_WAIT2(); }
        else if (rem == 1) { CP_WAIT1(); }
        else               { CP_WAIT0(); }
        __syncthreads();
        if (c + 3 < NC) { load_stage((c + 3) & 3, c + 3); CP_COMMIT(); }

        const uint32_t sA = sbase + (c & 3) * STG2;
        const uint32_t sB = sA + STGB;

        #pragma unroll
        for (int ks = 0; ks < 2; ks++) {
            uint32_t a[4][4], b[4][2];
            #pragma unroll
            for (int i = 0; i < 4; i++) {
                uint32_t ad = sA + (uint32_t)(wm + i * 16 + (lane & 15)) * RS
                            + ks * 32 + (lane >> 4) * 16;
                LDSM_X4(a[i][0], a[i][1], a[i][2], a[i][3], ad);
            }
            #pragma unroll
            for (int j = 0; j < 2; j++) {
                uint32_t bd = sB + (uint32_t)(wn + j * 16 + ((lane >> 4) & 1) * 8 + (lane & 7)) * RS
                            + ks * 32 + ((lane >> 3) & 1) * 16;
                LDSM_X4(b[2*j][0], b[2*j][1], b[2*j+1][0], b[2*j+1][1], bd);
            }
            #pragma unroll
            for (int i = 0; i < 4; i++)
                #pragma unroll
                for (int j = 0; j < 4; j++)
                    MMA16816(acc[i][j][0], acc[i][j][1], acc[i][j][2], acc[i][j][3],
                             a[i][0], a[i][1], a[i][2], a[i][3], b[j][0], b[j][1]);
        }
    }

    // epilogue (select outputs; for qkv mode z picks the target)
    const float* bias = p.bias;
    float alpha = p.alpha;
    __nv_bfloat16 *Ch = p.Ch, *Cl = p.Cl;
    __half *Vh = nullptr, *Vl = nullptr;
    if (p.qkv) {
        if (z == 0)      { bias = p.bias;  alpha = QSCL; Ch = p.Ch;  Cl = p.Cl; }
        else if (z == 1) { bias = p.bias1; alpha = 1.f;  Ch = p.Ch1; Cl = p.Cl1; }
        else             { bias = p.bias2; alpha = 1.f;  Ch = nullptr; Cl = nullptr;
                           Vh = p.Vh; Vl = p.Vl; }
    }

    #pragma unroll
    for (int i = 0; i < 4; i++) {
        #pragma unroll
        for (int j = 0; j < 4; j++) {
            int n = n0 + wn + j * 8 + (lane & 3) * 2;
            if (n >= p.N) continue;
            #pragma unroll
            for (int half_ = 0; half_ < 2; half_++) {
                int m = m0 + wm + i * 16 + (lane >> 2) + half_ * 8;
                float vx = acc[i][j][half_ * 2 + 0];
                float vy = acc[i][j][half_ * 2 + 1];
                if (bias) { vx += bias[n]; vy += bias[n + 1]; }
                vx *= alpha; vy *= alpha;
                if (p.act)  { vx = gelu_f(vx); vy = gelu_f(vy); }
                const long base = coff + (long)m * p.cs_m + n;
                if (p.R) {
                    float2 rr = *(const float2*)(p.R + base);
                    vx += rr.x; vy += rr.y;
                }
                if (p.Cf) *(float2*)(p.Cf + base) = make_float2(vx, vy);
                if (Ch) {
                    __nv_bfloat16 h0, h1, l0, l1;
                    splitbf(vx, h0, l0); splitbf(vy, h1, l1);
                    *(__nv_bfloat162*)(Ch + base) = __halves2bfloat162(h0, h1);
                    *(__nv_bfloat162*)(Cl + base) = __halves2bfloat162(l0, l1);
                }
                if (Vh) {
                    __half h0 = __float2half_rn(vx), h1 = __float2half_rn(vy);
                    __half l0 = __float2half_rn(vx - __half2float(h0));
                    __half l1 = __float2half_rn(vy - __half2float(h1));
                    *(__half2*)(Vh + base) = __halves2half2(h0, h1);
                    *(__half2*)(Vl + base) = __halves2half2(l0, l1);
                }
            }
        }
    }
}

// ---------------- Flash attention (exp2/f16 path) ----------------
#define FRS  144
#define FPL  (128 * FRS)
#define FSTG (4 * FPL)
#define FSMEM (2 * FPL + 2 * FSTG)   // 184320

__global__ void __launch_bounds__(256, 1) flash_attn(
    const __nv_bfloat16* __restrict__ qh, const __nv_bfloat16* __restrict__ ql,
    const __nv_bfloat16* __restrict__ kh, const __nv_bfloat16* __restrict__ kl,
    const __half* __restrict__ vh, const __half* __restrict__ vl,
    __nv_bfloat16* __restrict__ ch, __nv_bfloat16* __restrict__ cl)
{
    extern __shared__ __align__(128) char fsm[];
    const int tid = threadIdx.x, wid = tid >> 5, lane = tid & 31;
    const int b = blockIdx.z / HH, h = blockIdx.z % HH;
    const size_t qrow0 = (size_t)b * SSEQ + blockIdx.x * 128;
    const size_t krow0 = (size_t)b * SSEQ;
    const int hc = h * DHH;

    const uint32_t sb  = smem_u32(fsm);
    const uint32_t sKV = sb + 2 * FPL;

    {
        #pragma unroll
        for (int i = 0; i < 8; i++) {
            int id = tid + i * 256;
            int pl = id >> 10, rc = id & 1023;
            int row = rc >> 3, cu = rc & 7;
            const __nv_bfloat16* src = (pl ? ql : qh) + (qrow0 + row) * DD + hc + cu * 8;
            CP_ASYNC16(sb + pl * FPL + (uint32_t)(row * FRS + cu * 16), src);
        }
    }
    auto loadKV = [&](int kt, int s) {
        uint32_t base = sKV + (uint32_t)s * FSTG;
        size_t r0 = krow0 + (size_t)kt * 128;
        #pragma unroll
        for (int i = 0; i < 16; i++) {
            int id = tid + i * 256;
            int pl = id >> 10, rc = id & 1023;
            int row = rc >> 3, cu = rc & 7;
            const char* g = (pl == 0) ? (const char*)kh : (pl == 1) ? (const char*)kl
                          : (pl == 2) ? (const char*)vh : (const char*)vl;
            CP_ASYNC16(base + (uint32_t)(pl * FPL + row * FRS + cu * 16),
                       g + ((r0 + row) * DD + hc + cu * 8) * 2);
        }
    };
    loadKV(0, 0); CP_COMMIT();
    loadKV(1, 1); CP_COMMIT();
    CP_WAIT1(); __syncthreads();

    uint32_t qfh[4][4], qfl[4][4];
    const int mw = wid * 16;
    #pragma unroll
    for (int kf = 0; kf < 4; kf++) {
        uint32_t ad = sb + (uint32_t)((mw + (lane & 15)) * FRS + kf * 32 + (lane >> 4) * 16);
        LDSM_X4(qfh[kf][0], qfh[kf][1], qfh[kf][2], qfh[kf][3], ad);
        LDSM_X4(qfl[kf][0], qfl[kf][1], qfl[kf][2], qfl[kf][3], ad + FPL);
    }

    float accO[8][4];
    #pragma unroll
    for (int i = 0; i < 8; i++) { accO[i][0] = accO[i][1] = accO[i][2] = accO[i][3] = 0.f; }
    float mrun0 = -1e30f, mrun1 = -1e30f, lrun0 = 0.f, lrun1 = 0.f;

    for (int kt = 0; kt < 8; kt++) {
        const uint32_t bK = sKV + (uint32_t)(kt & 1) * FSTG;
        const uint32_t bV = bK + 2 * FPL;

        // ---- S = Q' K^T (log2-domain scores; Q pre-scaled by 0.125*log2e) ----
        float S[16][4];
        #pragma unroll
        for (int j = 0; j < 16; j++) { S[j][0] = S[j][1] = S[j][2] = S[j][3] = 0.f; }

        #pragma unroll
        for (int pass = 0; pass < 3; pass++) {
            const uint32_t kb = bK + ((pass == 1) ? FPL : 0);
            #pragma unroll
            for (int kf = 0; kf < 4; kf++) {
                const uint32_t* qa = (pass == 2) ? qfl[kf] : qfh[kf];
                #pragma unroll
                for (int jp = 0; jp < 8; jp++) {
                    uint32_t b0, b1, b2, b3;
                    uint32_t ad = kb + (uint32_t)((jp * 16 + ((lane >> 4) & 1) * 8 + (lane & 7)) * FRS
                                + kf * 32 + ((lane >> 3) & 1) * 16);
                    LDSM_X4(b0, b1, b2, b3, ad);
                    mma_acc(S[2 * jp],     qa, b0, b1);
                    mma_acc(S[2 * jp + 1], qa, b2, b3);
                }
            }
        }

        // ---- online max (log2 domain) ----
        float rm0 = -1e30f, rm1 = -1e30f;
        #pragma unroll
        for (int j = 0; j < 16; j++) {
            rm0 = fmaxf(rm0, fmaxf(S[j][0], S[j][1]));
            rm1 = fmaxf(rm1, fmaxf(S[j][2], S[j][3]));
        }
        rm0 = fmaxf(rm0, __shfl_xor_sync(0xFFFFFFFFu, rm0, 1));
        rm0 = fmaxf(rm0, __shfl_xor_sync(0xFFFFFFFFu, rm0, 2));
        rm1 = fmaxf(rm1, __shfl_xor_sync(0xFFFFFFFFu, rm1, 1));
        rm1 = fmaxf(rm1, __shfl_xor_sync(0xFFFFFFFFu, rm1, 2));
        float mn0 = fmaxf(mrun0, rm0), mn1 = fmaxf(mrun1, rm1);
        float sc0 = exp2f(mrun0 - mn0), sc1 = exp2f(mrun1 - mn1);
        mrun0 = mn0; mrun1 = mn1;
        #pragma unroll
        for (int i = 0; i < 8; i++) {
            accO[i][0] *= sc0; accO[i][1] *= sc0;
            accO[i][2] *= sc1; accO[i][3] *= sc1;
        }

        // ---- P = exp2(S - m) in f16; O += P V (2-pass f16 split V) ----
        float rs0 = 0.f, rs1 = 0.f;
        #pragma unroll
        for (int kf = 0; kf < 8; kf++) {
            __half2 e0 = h2exp2(__floats2half2_rn(S[2*kf][0]   - mn0, S[2*kf][1]   - mn0));
            __half2 e1 = h2exp2(__floats2half2_rn(S[2*kf][2]   - mn1, S[2*kf][3]   - mn1));
            __half2 e2 = h2exp2(__floats2half2_rn(S[2*kf+1][0] - mn0, S[2*kf+1][1] - mn0));
            __half2 e3 = h2exp2(__floats2half2_rn(S[2*kf+1][2] - mn1, S[2*kf+1][3] - mn1));
            uint32_t pa[4];
            pa[0] = *reinterpret_cast<uint32_t*>(&e0);
            pa[1] = *reinterpret_cast<uint32_t*>(&e1);
            pa[2] = *reinterpret_cast<uint32_t*>(&e2);
            pa[3] = *reinterpret_cast<uint32_t*>(&e3);
            float2 f0 = __half22float2(e0), f1 = __half22float2(e1);
            float2 f2 = __half22float2(e2), f3 = __half22float2(e3);
            rs0 += f0.x + f0.y + f2.x + f2.y;
            rs1 += f1.x + f1.y + f3.x + f3.y;

            #pragma unroll
            for (int np = 0; np < 4; np++) {
                uint32_t ad = bV + (uint32_t)((kf * 16 + ((lane >> 3) & 1) * 8 + (lane & 7)) * FRS
                            + np * 32 + (lane >> 4) * 16);
                uint32_t v0, v1, v2, v3;
                LDSM_X4T(v0, v1, v2, v3, ad);
                mma_f16(accO[2 * np],     pa, v0, v1);
                mma_f16(accO[2 * np + 1], pa, v2, v3);
                LDSM_X4T(v0, v1, v2, v3, ad + FPL);
                mma_f16(accO[2 * np],     pa, v0, v1);
                mma_f16(accO[2 * np + 1], pa, v2, v3);
            }
        }
        rs0 += __shfl_xor_sync(0xFFFFFFFFu, rs0, 1);
        rs0 += __shfl_xor_sync(0xFFFFFFFFu, rs0, 2);
        rs1 += __shfl_xor_sync(0xFFFFFFFFu, rs1, 1);
        rs1 += __shfl_xor_sync(0xFFFFFFFFu, rs1, 2);
        lrun0 = lrun0 * sc0 + rs0;
        lrun1 = lrun1 * sc1 + rs1;

        __syncthreads();
        if (kt + 2 < 8) { loadKV(kt + 2, kt & 1); CP_COMMIT(); }
        if (kt + 1 < 8) {
            if (kt + 2 < 8) { CP_WAIT1(); } else { CP_WAIT0(); }
            __syncthreads();
        }
    }

    float inv0 = 1.f / lrun0, inv1 = 1.f / lrun1;
    size_t r0 = qrow0 + mw + (lane >> 2);
    #pragma unroll
    for (int nt = 0; nt < 8; nt++) {
        int col = hc + nt * 8 + 2 * (lane & 3);
        {
            float vx = accO[nt][0] * inv0, vy = accO[nt][1] * inv0;
            __nv_bfloat16 h0, h1, l0, l1;
            splitbf(vx, h0, l0); splitbf(vy, h1, l1);
            size_t base = r0 * DD + col;
            *(__nv_bfloat162*)(ch + base) = __halves2bfloat162(h0, h1);
            *(__nv_bfloat162*)(cl + base) = __halves2bfloat162(l0, l1);
        }
        {
            float vx = accO[nt][2] * inv1, vy = accO[nt][3] * inv1;
            __nv_bfloat16 h0, h1, l0, l1;
            splitbf(vx, h0, l0); splitbf(vy, h1, l1);
            size_t base = (r0 + 8) * DD + col;
            *(__nv_bfloat162*)(ch + base) = __halves2bfloat162(h0, h1);
            *(__nv_bfloat162*)(cl + base) = __halves2bfloat162(l0, l1);
        }
    }
}

// ---------------- merged weight prep ----------------
#define QKVN (DD * DD)            // per-matrix element count for qkv remap
#define WON  (DD * DD)
#define W12N (DD * DFF_)
__global__ void __launch_bounds__(256) prep_all(
    const float* __restrict__ Wq, const float* __restrict__ Wk, const float* __restrict__ Wv,
    const float* __restrict__ Wo, const float* __restrict__ W1, const float* __restrict__ W2,
    __nv_bfloat16* __restrict__ wqh, __nv_bfloat16* __restrict__ wql,
    __nv_bfloat16* __restrict__ woh, __nv_bfloat16* __restrict__ wol,
    __nv_bfloat16* __restrict__ w1h, __nv_bfloat16* __restrict__ w1l,
    __nv_bfloat16* __restrict__ w2h, __nv_bfloat16* __restrict__ w2l)
{
    long idx = (long)blockIdx.x * 256 + threadIdx.x;
    __nv_bfloat16 hh, ll;
    if (idx < QKVN) {
        int n = (int)(idx / DD), d = (int)(idx % DD);
        int h = n >> 6, c = n & 63;
        size_t src = (size_t)h * DD * DHH + (size_t)d * DHH + c;
        splitbf(Wq[src], hh, ll); wqh[idx] = hh;              wql[idx] = ll;
        splitbf(Wk[src], hh, ll); wqh[idx + QKVN] = hh;       wql[idx + QKVN] = ll;
        splitbf(Wv[src], hh, ll); wqh[idx + 2*QKVN] = hh;     wql[idx + 2*QKVN] = ll;
        return;
    }
    idx -= QKVN;
    if (idx < WON) {
        int n = (int)(idx / DD), k = (int)(idx % DD);
        splitbf(Wo[(long)k * DD + n], hh, ll);
        woh[idx] = hh; wol[idx] = ll;
        return;
    }
    idx -= WON;
    if (idx < W12N) {
        int n = (int)(idx / DD), k = (int)(idx % DD);      // [DFF rows, D cols] transposed
        splitbf(W1[(long)k * DFF_ + n], hh, ll);
        w1h[idx] = hh; w1l[idx] = ll;
        return;
    }
    idx -= W12N;
    if (idx < W12N) {
        int n = (int)(idx / DFF_), k = (int)(idx % DFF_);
        splitbf(W2[(long)k * DD + n], hh, ll);
        w2h[idx] = hh; w2l[idx] = ll;
    }
}

// ---------------- LayerNorm -> split bf16 ----------------
__global__ void __launch_bounds__(256) lnorm_kernel(
    const float* __restrict__ x, const float* __restrict__ g, const float* __restrict__ b,
    __nv_bfloat16* __restrict__ oh, __nv_bfloat16* __restrict__ ol)
{
    size_t row = blockIdx.x;
    const float* xr = x + row * DD;
    int t = threadIdx.x;
    float v0 = xr[t], v1 = xr[t + 256], v2 = xr[t + 512];
    float s  = v0 + v1 + v2;
    float s2 = v0*v0 + v1*v1 + v2*v2;
    #pragma unroll
    for (int o = 16; o; o >>= 1) {
        s  += __shfl_xor_sync(0xFFFFFFFFu, s,  o);
        s2 += __shfl_xor_sync(0xFFFFFFFFu, s2, o);
    }
    __shared__ float sh[2][8];
    int w = t >> 5, l = t & 31;
    if (l == 0) { sh[0][w] = s; sh[1][w] = s2; }
    __syncthreads();
    s = 0.f; s2 = 0.f;
    #pragma unroll
    for (int i = 0; i < 8; i++) { s += sh[0][i]; s2 += sh[1][i]; }
    float mean = s * (1.f / 768.f);
    float var  = s2 * (1.f / 768.f) - mean * mean;
    float inv  = rsqrtf(var + 1e-5f);
    __nv_bfloat16 hh, ll;
    float y0 = (v0 - mean) * inv * g[t]       + b[t];
    float y1 = (v1 - mean) * inv * g[t + 256] + b[t + 256];
    float y2 = (v2 - mean) * inv * g[t + 512] + b[t + 512];
    splitbf(y0, hh, ll); oh[row*DD + t]       = hh; ol[row*DD + t]       = ll;
    splitbf(y1, hh, ll); oh[row*DD + t + 256] = hh; ol[row*DD + t + 256] = ll;
    splitbf(y2, hh, ll); oh[row*DD + t + 512] = hh; ol[row*DD + t + 512] = ll;
}

// ---------------- host ----------------
extern "C" void kernel_launch(void* const* d_in, const int* in_sizes, int n_in,
                              void* d_out, int out_size)
{
    (void)in_sizes; (void)n_in; (void)out_size;
    const float* x    = (const float*)d_in[0];
    const float* ln1g = (const float*)d_in[1];
    const float* ln1b = (const float*)d_in[2];
    const float* Wq   = (const float*)d_in[3];
    const float* bq   = (const float*)d_in[4];
    const float* Wk   = (const float*)d_in[5];
    const float* bk   = (const float*)d_in[6];
    const float* Wv   = (const float*)d_in[7];
    const float* bv   = (const float*)d_in[8];
    const float* Wo   = (const float*)d_in[9];
    const float* bo   = (const float*)d_in[10];
    const float* ln2g = (const float*)d_in[11];
    const float* ln2b = (const float*)d_in[12];
    const float* W1   = (const float*)d_in[13];
    const float* b1   = (const float*)d_in[14];
    const float* W2   = (const float*)d_in[15];
    const float* b2   = (const float*)d_in[16];
    float* out = (float*)d_out;

    float *x2;
    __nv_bfloat16 *hh, *hl, *qh, *ql, *kh, *kl, *ch, *cl,
                  *ffh, *ffl, *wqh, *wql, *woh, *wol, *w1h, *w1l, *w2h, *w2l;
    __half *vh, *vl;
    cudaGetSymbolAddress((void**)&x2,  g_x2);
    cudaGetSymbolAddress((void**)&hh,  g_hh);  cudaGetSymbolAddress((void**)&hl,  g_hl);
    cudaGetSymbolAddress((void**)&qh,  g_qh);  cudaGetSymbolAddress((void**)&ql,  g_ql);
    cudaGetSymbolAddress((void**)&kh,  g_kh);  cudaGetSymbolAddress((void**)&kl,  g_kl);
    cudaGetSymbolAddress((void**)&vh,  g_vh);  cudaGetSymbolAddress((void**)&vl,  g_vl);
    cudaGetSymbolAddress((void**)&ch,  g_ch);  cudaGetSymbolAddress((void**)&cl,  g_cl);
    cudaGetSymbolAddress((void**)&ffh, g_ffh); cudaGetSymbolAddress((void**)&ffl, g_ffl);
    cudaGetSymbolAddress((void**)&wqh, g_wqh); cudaGetSymbolAddress((void**)&wql, g_wql);
    cudaGetSymbolAddress((void**)&woh, g_woh); cudaGetSymbolAddress((void**)&wol, g_wol);
    cudaGetSymbolAddress((void**)&w1h, g_w1h); cudaGetSymbolAddress((void**)&w1l, g_w1l);
    cudaGetSymbolAddress((void**)&w2h, g_w2h); cudaGetSymbolAddress((void**)&w2l, g_w2l);

    cudaFuncSetAttribute(tcmm, cudaFuncAttributeMaxDynamicSharedMemorySize, GSMEM);
    cudaFuncSetAttribute(flash_attn, cudaFuncAttributeMaxDynamicSharedMemorySize, FSMEM);

    // merged weight prep
    {
        long total = (long)QKVN + WON + 2L * W12N;
        prep_all<<<(unsigned)((total + 255) / 256), 256>>>(
            Wq, Wk, Wv, Wo, W1, W2, wqh, wql, woh, wol, w1h, w1l, w2h, w2l);
    }

    // ln1
    lnorm_kernel<<<MTOK, 256>>>(x, ln1g, ln1b, hh, hl);

    // fused QKV projection (z = 0:q, 1:k, 2:v)
    {
        TcP p{};
        p.Ah = hh; p.Al = hl; p.as_m = DD; p.a_out = 0; p.a_in = 0; p.a_zdiv = 1;
        p.Bh = wqh; p.Bl = wql; p.bs_n = DD;
        p.b_out = (long)DD * DD; p.b_in = 0; p.b_zdiv = 1;
        p.cs_m = DD; p.c_out = 0; p.c_in = 0; p.c_zdiv = 1;
        p.K = DD; p.N = DD; p.alpha = 1.f; p.act = 0; p.R = nullptr; p.Cf = nullptr;
        p.qkv = 1;
        p.bias = bq; p.bias1 = bk; p.bias2 = bv;
        p.Ch = qh; p.Cl = ql; p.Ch1 = kh; p.Cl1 = kl; p.Vh = vh; p.Vl = vl;
        tcmm<<<dim3(DD / 128, MTOK / 128, 3), 256, GSMEM>>>(p);
    }

    // fused attention
    flash_attn<<<dim3(SSEQ / 128, 1, BB * HH), 256, FSMEM>>>(
        qh, ql, kh, kl, vh, vl, ch, cl);

    // x2 = x + ctx @ Wo + bo
    {
        TcP s{};
        s.Ah = ch; s.Al = cl; s.as_m = DD; s.a_out = 0; s.a_in = 0; s.a_zdiv = 1;
        s.Bh = woh; s.Bl = wol; s.bs_n = DD; s.b_out = 0; s.b_in = 0; s.b_zdiv = 1;
        s.bias = bo; s.R = x;
        s.Cf = x2; s.Ch = nullptr; s.Cl = nullptr;
        s.cs_m = DD; s.c_out = 0; s.c_in = 0; s.c_zdiv = 1;
        s.K = DD; s.N = DD; s.alpha = 1.f; s.act = 0; s.qkv = 0;
        tcmm<<<dim3(DD / 128, MTOK / 128, 1), 256, GSMEM>>>(s);
    }

    // ln2
    lnorm_kernel<<<MTOK, 256>>>(x2, ln2g, ln2b, hh, hl);

    // ff = gelu(h @ W1 + b1)
    {
        TcP s{};
        s.Ah = hh; s.Al = hl; s.as_m = DD; s.a_out = 0; s.a_in = 0; s.a_zdiv = 1;
        s.Bh = w1h; s.Bl = w1l; s.bs_n = DD; s.b_out = 0; s.b_in = 0; s.b_zdiv = 1;
        s.bias = b1; s.R = nullptr;
        s.Cf = nullptr; s.Ch = ffh; s.Cl = ffl;
        s.cs_m = DFF_; s.c_out = 0; s.c_in = 0; s.c_zdiv = 1;
        s.K = DD; s.N = DFF_; s.alpha = 1.f; s.act = 1; s.qkv = 0;
        tcmm<<<dim3(DFF_ / 128, MTOK / 128, 1), 256, GSMEM>>>(s);
    }

    // out = x2 + ff @ W2 + b2
    {
        TcP s{};
        s.Ah = ffh; s.Al = ffl; s.as_m = DFF_; s.a_out = 0; s.a_in = 0; s.a_zdiv = 1;
        s.Bh = w2h; s.Bl = w2l; s.bs_n = DFF_; s.b_out = 0; s.b_in = 0; s.b_zdiv = 1;
        s.bias = b2; s.R = x2;
        s.Cf = out; s.Ch = nullptr; s.Cl = nullptr;
        s.cs_m = DD; s.c_out = 0; s.c_in = 0; s.c_zdiv = 1;
        s.K = DFF_; s.N = DD; s.alpha = 1.f; s.act = 0; s.qkv = 0;
        tcmm<<<dim3(DD / 128, MTOK / 128, 1), 256, GSMEM>>>(s);
    }
}

// round 7
// speedup vs baseline: 3.8790x; 1.0520x over previous
#include <cuda_runtime.h>
#include <cuda_bf16.h>
#include <cuda_fp16.h>
#include <math.h>
#include <stdint.h>

#define BB   16
#define SSEQ 1024
#define DD   768
#define HH   12
#define DHH  64
#define DFF_ 3072
#define MTOK (BB*SSEQ)
#define QSCL 0.18033688011112042f   /* 0.125 * log2(e) */

// ---------------- scratch ----------------
__device__ float          g_x2 [(size_t)MTOK * DD];
__device__ __nv_bfloat16  g_hh [(size_t)MTOK * DD],  g_hl [(size_t)MTOK * DD];
__device__ __nv_bfloat16  g_qh [(size_t)MTOK * DD],  g_ql [(size_t)MTOK * DD];
__device__ __nv_bfloat16  g_kh [(size_t)MTOK * DD],  g_kl [(size_t)MTOK * DD];
__device__ __half         g_vh [(size_t)MTOK * DD],  g_vl [(size_t)MTOK * DD];
__device__ __nv_bfloat16  g_ch [(size_t)MTOK * DD],  g_cl [(size_t)MTOK * DD];
__device__ __nv_bfloat16  g_ffh[(size_t)MTOK * DFF_], g_ffl[(size_t)MTOK * DFF_];
__device__ __nv_bfloat16  g_wqh[3 * DD * DD], g_wql[3 * DD * DD];
__device__ __nv_bfloat16  g_woh[DD * DD],     g_wol[DD * DD];
__device__ __nv_bfloat16  g_w1h[DD * DFF_],   g_w1l[DD * DFF_];
__device__ __nv_bfloat16  g_w2h[DD * DFF_],   g_w2l[DD * DFF_];

// ---------------- helpers ----------------
__device__ __forceinline__ uint32_t smem_u32(const void* p) {
    uint32_t a;
    asm("{ .reg .u64 t; cvta.to.shared.u64 t, %1; cvt.u32.u64 %0, t; }" : "=r"(a) : "l"(p));
    return a;
}
__device__ __forceinline__ void splitbf(float x, __nv_bfloat16& h, __nv_bfloat16& l) {
    h = __float2bfloat16(x);
    l = __float2bfloat16(x - __bfloat162float(h));
}
__device__ __forceinline__ float gelu_f(float v) {
    return 0.5f * v * (1.f + erff(v * 0.70710678118654752f));
}

#define CP_ASYNC16(dst, src) \
    asm volatile("cp.async.cg.shared.global [%0], [%1], 16;" :: "r"(dst), "l"(src))
#define CP_COMMIT()  asm volatile("cp.async.commit_group;" ::: "memory")
#define CP_WAIT1()   asm volatile("cp.async.wait_group 1;" ::: "memory")
#define CP_WAIT0()   asm volatile("cp.async.wait_group 0;" ::: "memory")

#define LDSM_X4(r0, r1, r2, r3, a) \
    asm volatile("ldmatrix.sync.aligned.m8n8.x4.shared.b16 {%0,%1,%2,%3}, [%4];" \
        : "=r"(r0), "=r"(r1), "=r"(r2), "=r"(r3) : "r"(a))
#define LDSM_X4T(r0, r1, r2, r3, a) \
    asm volatile("ldmatrix.sync.aligned.m8n8.x4.trans.shared.b16 {%0,%1,%2,%3}, [%4];" \
        : "=r"(r0), "=r"(r1), "=r"(r2), "=r"(r3) : "r"(a))

#define MMA16816(c0, c1, c2, c3, a0, a1, a2, a3, b0, b1) \
    asm volatile("mma.sync.aligned.m16n8k16.row.col.f32.bf16.bf16.f32 " \
        "{%0,%1,%2,%3}, {%4,%5,%6,%7}, {%8,%9}, {%0,%1,%2,%3};" \
        : "+f"(c0), "+f"(c1), "+f"(c2), "+f"(c3) \
        : "r"(a0), "r"(a1), "r"(a2), "r"(a3), "r"(b0), "r"(b1))

#define MMAF16(c0, c1, c2, c3, a0, a1, a2, a3, b0, b1) \
    asm volatile("mma.sync.aligned.m16n8k16.row.col.f32.f16.f16.f32 " \
        "{%0,%1,%2,%3}, {%4,%5,%6,%7}, {%8,%9}, {%0,%1,%2,%3};" \
        : "+f"(c0), "+f"(c1), "+f"(c2), "+f"(c3) \
        : "r"(a0), "r"(a1), "r"(a2), "r"(a3), "r"(b0), "r"(b1))

__device__ __forceinline__ void mma_acc(float* c, const uint32_t* a, uint32_t b0, uint32_t b1) {
    MMA16816(c[0], c[1], c[2], c[3], a[0], a[1], a[2], a[3], b0, b1);
}
__device__ __forceinline__ void mma_f16(float* c, const uint32_t* a, uint32_t b0, uint32_t b1) {
    MMAF16(c[0], c[1], c[2], c[3], a[0], a[1], a[2], a[3], b0, b1);
}

// ---------------- HMMA GEMM (4-stage, 1 sync + 1 wait per 2 chunks) ----------------
struct TcP {
    const __nv_bfloat16 *Ah, *Al, *Bh, *Bl;
    const float *bias, *bias1, *bias2, *R;
    float* Cf; __nv_bfloat16 *Ch, *Cl, *Ch1, *Cl1;
    __half *Vh, *Vl;
    long a_out, a_in, b_out, b_in, c_out, c_in;
    int a_zdiv, b_zdiv, c_zdiv;
    int as_m, bs_n, cs_m;
    int K, N; float alpha; int act; int qkv;
};

#define RS   80
#define STGB (128 * RS)
#define STG2 (2 * STGB)          // 20480 per stage
#define GSMEM (4 * STG2)         // 81920

__global__ void __launch_bounds__(256, 2) tcmm(TcP p)
{
    extern __shared__ __align__(128) char gsm[];

    const int tid = threadIdx.x, wid = tid >> 5, lane = tid & 31;
    const int n0 = blockIdx.x * 128, m0 = blockIdx.y * 128, z = blockIdx.z;
    const int wm = (wid >> 2) * 64;
    const int wn = (wid & 3) * 32;

    const __nv_bfloat16* Ah = p.Ah + (long)(z / p.a_zdiv) * p.a_out + (long)(z % p.a_zdiv) * p.a_in;
    const __nv_bfloat16* Al = p.Al + (long)(z / p.a_zdiv) * p.a_out + (long)(z % p.a_zdiv) * p.a_in;
    const __nv_bfloat16* Bh = p.Bh + (long)(z / p.b_zdiv) * p.b_out + (long)(z % p.b_zdiv) * p.b_in;
    const __nv_bfloat16* Bl = p.Bl + (long)(z / p.b_zdiv) * p.b_out + (long)(z % p.b_zdiv) * p.b_in;
    const long coff = (long)(z / p.c_zdiv) * p.c_out + (long)(z % p.c_zdiv) * p.c_in;

    const uint32_t sbase = smem_u32(gsm);
    const int KC = p.K >> 5;
    const int NC = 3 * KC;                 // always even (KC multiple of 8)

    const int rowA0 = tid >> 2,         unitA0 = tid & 3;
    const int rowA1 = (tid + 256) >> 2, unitA1 = tid & 3;
    const bool bok0 = (n0 + rowA0 < p.N);
    const bool bok1 = (n0 + rowA1 < p.N);

    float acc[4][4][4];
    #pragma unroll
    for (int i = 0; i < 4; i++)
        #pragma unroll
        for (int j = 0; j < 4; j++)
            #pragma unroll
            for (int r = 0; r < 4; r++) acc[i][j][r] = 0.f;

    auto load_stage = [&](int s, int c) {
        const int pass = c / KC;
        const int kc   = c - pass * KC;
        const long kof = (long)kc << 5;
        const __nv_bfloat16* A = (pass == 2) ? Al : Ah;
        const __nv_bfloat16* B = (pass == 1) ? Bl : Bh;
        uint32_t dA = sbase + s * STG2;
        uint32_t dB = dA + STGB;
        CP_ASYNC16(dA + rowA0 * RS + unitA0 * 16,
                   A + (long)(m0 + rowA0) * p.as_m + kof + unitA0 * 8);
        CP_ASYNC16(dA + rowA1 * RS + unitA1 * 16,
                   A + (long)(m0 + rowA1) * p.as_m + kof + unitA1 * 8);
        if (bok0)
            CP_ASYNC16(dB + rowA0 * RS + unitA0 * 16,
                       B + (long)(n0 + rowA0) * p.bs_n + kof + unitA0 * 8);
        if (bok1)
            CP_ASYNC16(dB + rowA1 * RS + unitA1 * 16,
                       B + (long)(n0 + rowA1) * p.bs_n + kof + unitA1 * 8);
    };

    // prologue: pair 0 (chunks 0,1 -> stages 0,1)
    load_stage(0, 0);
    load_stage(1, 1);
    CP_COMMIT();

    for (int c = 0; c < NC; c += 2) {
        CP_WAIT0();           // pair c landed (only group in flight)
        __syncthreads();      // publish pair c; all warps done with pair c-2
        if (c + 2 < NC) {     // prefetch pair c+2 into pair c-2's stages (safe)
            load_stage((c + 2) & 3, c + 2);
            load_stage((c + 3) & 3, c + 3);
            CP_COMMIT();
        }

        #pragma unroll
        for (int cc = 0; cc < 2; cc++) {
            const uint32_t sA = sbase + ((c + cc) & 3) * STG2;
            const uint32_t sB = sA + STGB;
            #pragma unroll
            for (int ks = 0; ks < 2; ks++) {
                uint32_t a[4][4], b[4][2];
                #pragma unroll
                for (int i = 0; i < 4; i++) {
                    uint32_t ad = sA + (uint32_t)(wm + i * 16 + (lane & 15)) * RS
                                + ks * 32 + (lane >> 4) * 16;
                    LDSM_X4(a[i][0], a[i][1], a[i][2], a[i][3], ad);
                }
                #pragma unroll
                for (int j = 0; j < 2; j++) {
                    uint32_t bd = sB + (uint32_t)(wn + j * 16 + ((lane >> 4) & 1) * 8 + (lane & 7)) * RS
                                + ks * 32 + ((lane >> 3) & 1) * 16;
                    LDSM_X4(b[2*j][0], b[2*j][1], b[2*j+1][0], b[2*j+1][1], bd);
                }
                #pragma unroll
                for (int i = 0; i < 4; i++)
                    #pragma unroll
                    for (int j = 0; j < 4; j++)
                        MMA16816(acc[i][j][0], acc[i][j][1], acc[i][j][2], acc[i][j][3],
                                 a[i][0], a[i][1], a[i][2], a[i][3], b[j][0], b[j][1]);
            }
        }
    }

    // epilogue (select outputs; for qkv mode z picks the target)
    const float* bias = p.bias;
    float alpha = p.alpha;
    __nv_bfloat16 *Ch = p.Ch, *Cl = p.Cl;
    __half *Vh = nullptr, *Vl = nullptr;
    if (p.qkv) {
        if (z == 0)      { bias = p.bias;  alpha = QSCL; Ch = p.Ch;  Cl = p.Cl; }
        else if (z == 1) { bias = p.bias1; alpha = 1.f;  Ch = p.Ch1; Cl = p.Cl1; }
        else             { bias = p.bias2; alpha = 1.f;  Ch = nullptr; Cl = nullptr;
                           Vh = p.Vh; Vl = p.Vl; }
    }

    #pragma unroll
    for (int i = 0; i < 4; i++) {
        #pragma unroll
        for (int j = 0; j < 4; j++) {
            int n = n0 + wn + j * 8 + (lane & 3) * 2;
            if (n >= p.N) continue;
            #pragma unroll
            for (int half_ = 0; half_ < 2; half_++) {
                int m = m0 + wm + i * 16 + (lane >> 2) + half_ * 8;
                float vx = acc[i][j][half_ * 2 + 0];
                float vy = acc[i][j][half_ * 2 + 1];
                if (bias) { vx += bias[n]; vy += bias[n + 1]; }
                vx *= alpha; vy *= alpha;
                if (p.act)  { vx = gelu_f(vx); vy = gelu_f(vy); }
                const long base = coff + (long)m * p.cs_m + n;
                if (p.R) {
                    float2 rr = *(const float2*)(p.R + base);
                    vx += rr.x; vy += rr.y;
                }
                if (p.Cf) *(float2*)(p.Cf + base) = make_float2(vx, vy);
                if (Ch) {
                    __nv_bfloat16 h0, h1, l0, l1;
                    splitbf(vx, h0, l0); splitbf(vy, h1, l1);
                    *(__nv_bfloat162*)(Ch + base) = __halves2bfloat162(h0, h1);
                    *(__nv_bfloat162*)(Cl + base) = __halves2bfloat162(l0, l1);
                }
                if (Vh) {
                    __half h0 = __float2half_rn(vx), h1 = __float2half_rn(vy);
                    __half l0 = __float2half_rn(vx - __half2float(h0));
                    __half l1 = __float2half_rn(vy - __half2float(h1));
                    *(__half2*)(Vh + base) = __halves2half2(h0, h1);
                    *(__half2*)(Vl + base) = __halves2half2(l0, l1);
                }
            }
        }
    }
}

// ---------------- Flash attention (64-row KV tiles, 2 CTAs/SM) ----------------
#define FRS   144
#define FQPL  (128 * FRS)      // Q plane 18432
#define FKPL  (64 * FRS)       // KV plane 9216
#define FSTG  (4 * FKPL)       // Kh,Kl,Vh,Vl per stage = 36864
#define FSMEM (2 * FQPL + 2 * FSTG)   // 110592
#define NKT   16

__global__ void __launch_bounds__(256, 2) flash_attn(
    const __nv_bfloat16* __restrict__ qh, const __nv_bfloat16* __restrict__ ql,
    const __nv_bfloat16* __restrict__ kh, const __nv_bfloat16* __restrict__ kl,
    const __half* __restrict__ vh, const __half* __restrict__ vl,
    __nv_bfloat16* __restrict__ ch, __nv_bfloat16* __restrict__ cl)
{
    extern __shared__ __align__(128) char fsm[];
    const int tid = threadIdx.x, wid = tid >> 5, lane = tid & 31;
    const int b = blockIdx.z / HH, h = blockIdx.z % HH;
    const size_t qrow0 = (size_t)b * SSEQ + blockIdx.x * 128;
    const size_t krow0 = (size_t)b * SSEQ;
    const int hc = h * DHH;

    const uint32_t sb  = smem_u32(fsm);
    const uint32_t sKV = sb + 2 * FQPL;

    // Q load: 2 planes x 128 rows x 8 chunks = 2048 / 256 threads
    {
        #pragma unroll
        for (int i = 0; i < 8; i++) {
            int id = tid + i * 256;
            int pl = id >> 10, rc = id & 1023;
            int row = rc >> 3, cu = rc & 7;
            const __nv_bfloat16* src = (pl ? ql : qh) + (qrow0 + row) * DD + hc + cu * 8;
            CP_ASYNC16(sb + pl * FQPL + (uint32_t)(row * FRS + cu * 16), src);
        }
    }
    // KV load: 4 planes x 64 rows x 8 chunks = 2048 / 256 threads
    auto loadKV = [&](int kt, int s) {
        uint32_t base = sKV + (uint32_t)s * FSTG;
        size_t r0 = krow0 + (size_t)kt * 64;
        #pragma unroll
        for (int i = 0; i < 8; i++) {
            int id = tid + i * 256;
            int pl = id >> 9, rc = id & 511;
            int row = rc >> 3, cu = rc & 7;
            const char* g = (pl == 0) ? (const char*)kh : (pl == 1) ? (const char*)kl
                          : (pl == 2) ? (const char*)vh : (const char*)vl;
            CP_ASYNC16(base + (uint32_t)(pl * FKPL + row * FRS + cu * 16),
                       g + ((r0 + row) * DD + hc + cu * 8) * 2);
        }
    };
    loadKV(0, 0); CP_COMMIT();
    loadKV(1, 1); CP_COMMIT();
    CP_WAIT1(); __syncthreads();

    // persistent Q-hi fragments only (Q-lo reloaded per kt to fit 128 regs)
    uint32_t qfh[4][4];
    const int mw = wid * 16;
    #pragma unroll
    for (int kf = 0; kf < 4; kf++) {
        uint32_t ad = sb + (uint32_t)((mw + (lane & 15)) * FRS + kf * 32 + (lane >> 4) * 16);
        LDSM_X4(qfh[kf][0], qfh[kf][1], qfh[kf][2], qfh[kf][3], ad);
    }

    float accO[8][4];
    #pragma unroll
    for (int i = 0; i < 8; i++) { accO[i][0] = accO[i][1] = accO[i][2] = accO[i][3] = 0.f; }
    float mrun0 = -1e30f, mrun1 = -1e30f, lrun0 = 0.f, lrun1 = 0.f;

    for (int kt = 0; kt < NKT; kt++) {
        const uint32_t bK = sKV + (uint32_t)(kt & 1) * FSTG;
        const uint32_t bV = bK + 2 * FKPL;

        // ---- S = Q' K^T (log2-domain; 3-pass split) ----
        float S[8][4];
        #pragma unroll
        for (int j = 0; j < 8; j++) { S[j][0] = S[j][1] = S[j][2] = S[j][3] = 0.f; }

        #pragma unroll
        for (int pass = 0; pass < 3; pass++) {
            const uint32_t kb = bK + ((pass == 1) ? FKPL : 0);
            #pragma unroll
            for (int kf = 0; kf < 4; kf++) {
                uint32_t qa[4];
                if (pass == 2) {
                    uint32_t ad = sb + FQPL
                        + (uint32_t)((mw + (lane & 15)) * FRS + kf * 32 + (lane >> 4) * 16);
                    LDSM_X4(qa[0], qa[1], qa[2], qa[3], ad);
                } else {
                    qa[0] = qfh[kf][0]; qa[1] = qfh[kf][1];
                    qa[2] = qfh[kf][2]; qa[3] = qfh[kf][3];
                }
                #pragma unroll
                for (int jp = 0; jp < 4; jp++) {
                    uint32_t b0, b1, b2, b3;
                    uint32_t ad = kb + (uint32_t)((jp * 16 + ((lane >> 4) & 1) * 8 + (lane & 7)) * FRS
                                + kf * 32 + ((lane >> 3) & 1) * 16);
                    LDSM_X4(b0, b1, b2, b3, ad);
                    mma_acc(S[2 * jp],     qa, b0, b1);
                    mma_acc(S[2 * jp + 1], qa, b2, b3);
                }
            }
        }

        // ---- online max (log2 domain) ----
        float rm0 = -1e30f, rm1 = -1e30f;
        #pragma unroll
        for (int j = 0; j < 8; j++) {
            rm0 = fmaxf(rm0, fmaxf(S[j][0], S[j][1]));
            rm1 = fmaxf(rm1, fmaxf(S[j][2], S[j][3]));
        }
        rm0 = fmaxf(rm0, __shfl_xor_sync(0xFFFFFFFFu, rm0, 1));
        rm0 = fmaxf(rm0, __shfl_xor_sync(0xFFFFFFFFu, rm0, 2));
        rm1 = fmaxf(rm1, __shfl_xor_sync(0xFFFFFFFFu, rm1, 1));
        rm1 = fmaxf(rm1, __shfl_xor_sync(0xFFFFFFFFu, rm1, 2));
        float mn0 = fmaxf(mrun0, rm0), mn1 = fmaxf(mrun1, rm1);
        float sc0 = exp2f(mrun0 - mn0), sc1 = exp2f(mrun1 - mn1);
        mrun0 = mn0; mrun1 = mn1;
        #pragma unroll
        for (int i = 0; i < 8; i++) {
            accO[i][0] *= sc0; accO[i][1] *= sc0;
            accO[i][2] *= sc1; accO[i][3] *= sc1;
        }

        // ---- P = exp2(S - m) f16; O += P V (2-pass f16 split V) ----
        float rs0 = 0.f, rs1 = 0.f;
        #pragma unroll
        for (int kf = 0; kf < 4; kf++) {
            __half2 e0 = h2exp2(__floats2half2_rn(S[2*kf][0]   - mn0, S[2*kf][1]   - mn0));
            __half2 e1 = h2exp2(__floats2half2_rn(S[2*kf][2]   - mn1, S[2*kf][3]   - mn1));
            __half2 e2 = h2exp2(__floats2half2_rn(S[2*kf+1][0] - mn0, S[2*kf+1][1] - mn0));
            __half2 e3 = h2exp2(__floats2half2_rn(S[2*kf+1][2] - mn1, S[2*kf+1][3] - mn1));
            uint32_t pa[4];
            pa[0] = *reinterpret_cast<uint32_t*>(&e0);
            pa[1] = *reinterpret_cast<uint32_t*>(&e1);
            pa[2] = *reinterpret_cast<uint32_t*>(&e2);
            pa[3] = *reinterpret_cast<uint32_t*>(&e3);
            float2 f0 = __half22float2(e0), f1 = __half22float2(e1);
            float2 f2 = __half22float2(e2), f3 = __half22float2(e3);
            rs0 += f0.x + f0.y + f2.x + f2.y;
            rs1 += f1.x + f1.y + f3.x + f3.y;

            #pragma unroll
            for (int np = 0; np < 4; np++) {
                uint32_t ad = bV + (uint32_t)((kf * 16 + ((lane >> 3) & 1) * 8 + (lane & 7)) * FRS
                            + np * 32 + (lane >> 4) * 16);
                uint32_t v0, v1, v2, v3;
                LDSM_X4T(v0, v1, v2, v3, ad);
                mma_f16(accO[2 * np],     pa, v0, v1);
                mma_f16(accO[2 * np + 1], pa, v2, v3);
                LDSM_X4T(v0, v1, v2, v3, ad + FKPL);
                mma_f16(accO[2 * np],     pa, v0, v1);
                mma_f16(accO[2 * np + 1], pa, v2, v3);
            }
        }
        rs0 += __shfl_xor_sync(0xFFFFFFFFu, rs0, 1);
        rs0 += __shfl_xor_sync(0xFFFFFFFFu, rs0, 2);
        rs1 += __shfl_xor_sync(0xFFFFFFFFu, rs1, 1);
        rs1 += __shfl_xor_sync(0xFFFFFFFFu, rs1, 2);
        lrun0 = lrun0 * sc0 + rs0;
        lrun1 = lrun1 * sc1 + rs1;

        __syncthreads();
        if (kt + 2 < NKT) { loadKV(kt + 2, kt & 1); CP_COMMIT(); }
        if (kt + 1 < NKT) {
            if (kt + 2 < NKT) { CP_WAIT1(); } else { CP_WAIT0(); }
            __syncthreads();
        }
    }

    float inv0 = 1.f / lrun0, inv1 = 1.f / lrun1;
    size_t r0 = qrow0 + mw + (lane >> 2);
    #pragma unroll
    for (int nt = 0; nt < 8; nt++) {
        int col = hc + nt * 8 + 2 * (lane & 3);
        {
            float vx = accO[nt][0] * inv0, vy = accO[nt][1] * inv0;
            __nv_bfloat16 h0, h1, l0, l1;
            splitbf(vx, h0, l0); splitbf(vy, h1, l1);
            size_t base = r0 * DD + col;
            *(__nv_bfloat162*)(ch + base) = __halves2bfloat162(h0, h1);
            *(__nv_bfloat162*)(cl + base) = __halves2bfloat162(l0, l1);
        }
        {
            float vx = accO[nt][2] * inv1, vy = accO[nt][3] * inv1;
            __nv_bfloat16 h0, h1, l0, l1;
            splitbf(vx, h0, l0); splitbf(vy, h1, l1);
            size_t base = (r0 + 8) * DD + col;
            *(__nv_bfloat162*)(ch + base) = __halves2bfloat162(h0, h1);
            *(__nv_bfloat162*)(cl + base) = __halves2bfloat162(l0, l1);
        }
    }
}

// ---------------- merged weight prep ----------------
#define QKVN (DD * DD)
#define WON  (DD * DD)
#define W12N (DD * DFF_)
__global__ void __launch_bounds__(256) prep_all(
    const float* __restrict__ Wq, const float* __restrict__ Wk, const float* __restrict__ Wv,
    const float* __restrict__ Wo, const float* __restrict__ W1, const float* __restrict__ W2,
    __nv_bfloat16* __restrict__ wqh, __nv_bfloat16* __restrict__ wql,
    __nv_bfloat16* __restrict__ woh, __nv_bfloat16* __restrict__ wol,
    __nv_bfloat16* __restrict__ w1h, __nv_bfloat16* __restrict__ w1l,
    __nv_bfloat16* __restrict__ w2h, __nv_bfloat16* __restrict__ w2l)
{
    long idx = (long)blockIdx.x * 256 + threadIdx.x;
    __nv_bfloat16 hh, ll;
    if (idx < QKVN) {
        int n = (int)(idx / DD), d = (int)(idx % DD);
        int h = n >> 6, c = n & 63;
        size_t src = (size_t)h * DD * DHH + (size_t)d * DHH + c;
        splitbf(Wq[src], hh, ll); wqh[idx] = hh;              wql[idx] = ll;
        splitbf(Wk[src], hh, ll); wqh[idx + QKVN] = hh;       wql[idx + QKVN] = ll;
        splitbf(Wv[src], hh, ll); wqh[idx + 2*QKVN] = hh;     wql[idx + 2*QKVN] = ll;
        return;
    }
    idx -= QKVN;
    if (idx < WON) {
        int n = (int)(idx / DD), k = (int)(idx % DD);
        splitbf(Wo[(long)k * DD + n], hh, ll);
        woh[idx] = hh; wol[idx] = ll;
        return;
    }
    idx -= WON;
    if (idx < W12N) {
        int n = (int)(idx / DD), k = (int)(idx % DD);
        splitbf(W1[(long)k * DFF_ + n], hh, ll);
        w1h[idx] = hh; w1l[idx] = ll;
        return;
    }
    idx -= W12N;
    if (idx < W12N) {
        int n = (int)(idx / DFF_), k = (int)(idx % DFF_);
        splitbf(W2[(long)k * DD + n], hh, ll);
        w2h[idx] = hh; w2l[idx] = ll;
    }
}

// ---------------- LayerNorm -> split bf16 ----------------
__global__ void __launch_bounds__(256) lnorm_kernel(
    const float* __restrict__ x, const float* __restrict__ g, const float* __restrict__ b,
    __nv_bfloat16* __restrict__ oh, __nv_bfloat16* __restrict__ ol)
{
    size_t row = blockIdx.x;
    const float* xr = x + row * DD;
    int t = threadIdx.x;
    float v0 = xr[t], v1 = xr[t + 256], v2 = xr[t + 512];
    float s  = v0 + v1 + v2;
    float s2 = v0*v0 + v1*v1 + v2*v2;
    #pragma unroll
    for (int o = 16; o; o >>= 1) {
        s  += __shfl_xor_sync(0xFFFFFFFFu, s,  o);
        s2 += __shfl_xor_sync(0xFFFFFFFFu, s2, o);
    }
    __shared__ float sh[2][8];
    int w = t >> 5, l = t & 31;
    if (l == 0) { sh[0][w] = s; sh[1][w] = s2; }
    __syncthreads();
    s = 0.f; s2 = 0.f;
    #pragma unroll
    for (int i = 0; i < 8; i++) { s += sh[0][i]; s2 += sh[1][i]; }
    float mean = s * (1.f / 768.f);
    float var  = s2 * (1.f / 768.f) - mean * mean;
    float inv  = rsqrtf(var + 1e-5f);
    __nv_bfloat16 hh, ll;
    float y0 = (v0 - mean) * inv * g[t]       + b[t];
    float y1 = (v1 - mean) * inv * g[t + 256] + b[t + 256];
    float y2 = (v2 - mean) * inv * g[t + 512] + b[t + 512];
    splitbf(y0, hh, ll); oh[row*DD + t]       = hh; ol[row*DD + t]       = ll;
    splitbf(y1, hh, ll); oh[row*DD + t + 256] = hh; ol[row*DD + t + 256] = ll;
    splitbf(y2, hh, ll); oh[row*DD + t + 512] = hh; ol[row*DD + t + 512] = ll;
}

// ---------------- host ----------------
extern "C" void kernel_launch(void* const* d_in, const int* in_sizes, int n_in,
                              void* d_out, int out_size)
{
    (void)in_sizes; (void)n_in; (void)out_size;
    const float* x    = (const float*)d_in[0];
    const float* ln1g = (const float*)d_in[1];
    const float* ln1b = (const float*)d_in[2];
    const float* Wq   = (const float*)d_in[3];
    const float* bq   = (const float*)d_in[4];
    const float* Wk   = (const float*)d_in[5];
    const float* bk   = (const float*)d_in[6];
    const float* Wv   = (const float*)d_in[7];
    const float* bv   = (const float*)d_in[8];
    const float* Wo   = (const float*)d_in[9];
    const float* bo   = (const float*)d_in[10];
    const float* ln2g = (const float*)d_in[11];
    const float* ln2b = (const float*)d_in[12];
    const float* W1   = (const float*)d_in[13];
    const float* b1   = (const float*)d_in[14];
    const float* W2   = (const float*)d_in[15];
    const float* b2   = (const float*)d_in[16];
    float* out = (float*)d_out;

    float *x2;
    __nv_bfloat16 *hh, *hl, *qh, *ql, *kh, *kl, *ch, *cl,
                  *ffh, *ffl, *wqh, *wql, *woh, *wol, *w1h, *w1l, *w2h, *w2l;
    __half *vh, *vl;
    cudaGetSymbolAddress((void**)&x2,  g_x2);
    cudaGetSymbolAddress((void**)&hh,  g_hh);  cudaGetSymbolAddress((void**)&hl,  g_hl);
    cudaGetSymbolAddress((void**)&qh,  g_qh);  cudaGetSymbolAddress((void**)&ql,  g_ql);
    cudaGetSymbolAddress((void**)&kh,  g_kh);  cudaGetSymbolAddress((void**)&kl,  g_kl);
    cudaGetSymbolAddress((void**)&vh,  g_vh);  cudaGetSymbolAddress((void**)&vl,  g_vl);
    cudaGetSymbolAddress((void**)&ch,  g_ch);  cudaGetSymbolAddress((void**)&cl,  g_cl);
    cudaGetSymbolAddress((void**)&ffh, g_ffh); cudaGetSymbolAddress((void**)&ffl, g_ffl);
    cudaGetSymbolAddress((void**)&wqh, g_wqh); cudaGetSymbolAddress((void**)&wql, g_wql);
    cudaGetSymbolAddress((void**)&woh, g_woh); cudaGetSymbolAddress((void**)&wol, g_wol);
    cudaGetSymbolAddress((void**)&w1h, g_w1h); cudaGetSymbolAddress((void**)&w1l, g_w1l);
    cudaGetSymbolAddress((void**)&w2h, g_w2h); cudaGetSymbolAddress((void**)&w2l, g_w2l);

    cudaFuncSetAttribute(tcmm, cudaFuncAttributeMaxDynamicSharedMemorySize, GSMEM);
    cudaFuncSetAttribute(flash_attn, cudaFuncAttributeMaxDynamicSharedMemorySize, FSMEM);

    // merged weight prep
    {
        long total = (long)QKVN + WON + 2L * W12N;
        prep_all<<<(unsigned)((total + 255) / 256), 256>>>(
            Wq, Wk, Wv, Wo, W1, W2, wqh, wql, woh, wol, w1h, w1l, w2h, w2l);
    }

    // ln1
    lnorm_kernel<<<MTOK, 256>>>(x, ln1g, ln1b, hh, hl);

    // fused QKV projection (z = 0:q, 1:k, 2:v)
    {
        TcP p{};
        p.Ah = hh; p.Al = hl; p.as_m = DD; p.a_out = 0; p.a_in = 0; p.a_zdiv = 1;
        p.Bh = wqh; p.Bl = wql; p.bs_n = DD;
        p.b_out = (long)DD * DD; p.b_in = 0; p.b_zdiv = 1;
        p.cs_m = DD; p.c_out = 0; p.c_in = 0; p.c_zdiv = 1;
        p.K = DD; p.N = DD; p.alpha = 1.f; p.act = 0; p.R = nullptr; p.Cf = nullptr;
        p.qkv = 1;
        p.bias = bq; p.bias1 = bk; p.bias2 = bv;
        p.Ch = qh; p.Cl = ql; p.Ch1 = kh; p.Cl1 = kl; p.Vh = vh; p.Vl = vl;
        tcmm<<<dim3(DD / 128, MTOK / 128, 3), 256, GSMEM>>>(p);
    }

    // fused attention
    flash_attn<<<dim3(SSEQ / 128, 1, BB * HH), 256, FSMEM>>>(
        qh, ql, kh, kl, vh, vl, ch, cl);

    // x2 = x + ctx @ Wo + bo
    {
        TcP s{};
        s.Ah = ch; s.Al = cl; s.as_m = DD; s.a_out = 0; s.a_in = 0; s.a_zdiv = 1;
        s.Bh = woh; s.Bl = wol; s.bs_n = DD; s.b_out = 0; s.b_in = 0; s.b_zdiv = 1;
        s.bias = bo; s.R = x;
        s.Cf = x2; s.Ch = nullptr; s.Cl = nullptr;
        s.cs_m = DD; s.c_out = 0; s.c_in = 0; s.c_zdiv = 1;
        s.K = DD; s.N = DD; s.alpha = 1.f; s.act = 0; s.qkv = 0;
        tcmm<<<dim3(DD / 128, MTOK / 128, 1), 256, GSMEM>>>(s);
    }

    // ln2
    lnorm_kernel<<<MTOK, 256>>>(x2, ln2g, ln2b, hh, hl);

    // ff = gelu(h @ W1 + b1)
    {
        TcP s{};
        s.Ah = hh; s.Al = hl; s.as_m = DD; s.a_out = 0; s.a_in = 0; s.a_zdiv = 1;
        s.Bh = w1h; s.Bl = w1l; s.bs_n = DD; s.b_out = 0; s.b_in = 0; s.b_zdiv = 1;
        s.bias = b1; s.R = nullptr;
        s.Cf = nullptr; s.Ch = ffh; s.Cl = ffl;
        s.cs_m = DFF_; s.c_out = 0; s.c_in = 0; s.c_zdiv = 1;
        s.K = DD; s.N = DFF_; s.alpha = 1.f; s.act = 1; s.qkv = 0;
        tcmm<<<dim3(DFF_ / 128, MTOK / 128, 1), 256, GSMEM>>>(s);
    }

    // out = x2 + ff @ W2 + b2
    {
        TcP s{};
        s.Ah = ffh; s.Al = ffl; s.as_m = DFF_; s.a_out = 0; s.a_in = 0; s.a_zdiv = 1;
        s.Bh = w2h; s.Bl = w2l; s.bs_n = DFF_; s.b_out = 0; s.b_in = 0; s.b_zdiv = 1;
        s.bias = b2; s.R = x2;
        s.Cf = out; s.Ch = nullptr; s.Cl = nullptr;
        s.cs_m = DD; s.c_out = 0; s.c_in = 0; s.c_zdiv = 1;
        s.K = DFF_; s.N = DD; s.alpha = 1.f; s.act = 0; s.qkv = 0;
        tcmm<<<dim3(DD / 128, MTOK / 128, 1), 256, GSMEM>>>(s);
    }
}

// round 8
// speedup vs baseline: 5.7719x; 1.4880x over previous
#include <cuda_runtime.h>
#include <cuda_bf16.h>
#include <cuda_fp16.h>
#include <math.h>
#include <stdint.h>

#define BB   16
#define SSEQ 1024
#define DD   768
#define HH   12
#define DHH  64
#define DFF_ 3072
#define MTOK (BB*SSEQ)
#define QSCL 0.18033688011112042f   /* 0.125 * log2(e) */

// ---------------- scratch ----------------
__device__ float          g_x2 [(size_t)MTOK * DD];
__device__ __half         g_h  [(size_t)MTOK * DD];
__device__ __nv_bfloat16  g_qh [(size_t)MTOK * DD],  g_ql [(size_t)MTOK * DD];
__device__ __nv_bfloat16  g_kh [(size_t)MTOK * DD],  g_kl [(size_t)MTOK * DD];
__device__ __half         g_vh [(size_t)MTOK * DD],  g_vl [(size_t)MTOK * DD];
__device__ __half         g_c  [(size_t)MTOK * DD];
__device__ __half         g_ff [(size_t)MTOK * DFF_];
__device__ __half         g_wqh[3 * DD * DD], g_wql[3 * DD * DD];
__device__ __half         g_woh[DD * DD],     g_wol[DD * DD];
__device__ __half         g_w1h[DD * DFF_],   g_w1l[DD * DFF_];
__device__ __half         g_w2h[DD * DFF_],   g_w2l[DD * DFF_];

// ---------------- helpers ----------------
__device__ __forceinline__ uint32_t smem_u32(const void* p) {
    uint32_t a;
    asm("{ .reg .u64 t; cvta.to.shared.u64 t, %1; cvt.u32.u64 %0, t; }" : "=r"(a) : "l"(p));
    return a;
}
__device__ __forceinline__ void splitbf(float x, __nv_bfloat16& h, __nv_bfloat16& l) {
    h = __float2bfloat16(x);
    l = __float2bfloat16(x - __bfloat162float(h));
}
__device__ __forceinline__ void splith(float x, __half& h, __half& l) {
    h = __float2half_rn(x);
    l = __float2half_rn(x - __half2float(h));
}
__device__ __forceinline__ float gelu_f(float v) {
    return 0.5f * v * (1.f + erff(v * 0.70710678118654752f));
}

#define CP_ASYNC16(dst, src) \
    asm volatile("cp.async.cg.shared.global [%0], [%1], 16;" :: "r"(dst), "l"(src))
#define CP_COMMIT()  asm volatile("cp.async.commit_group;" ::: "memory")
#define CP_WAIT1()   asm volatile("cp.async.wait_group 1;" ::: "memory")
#define CP_WAIT0()   asm volatile("cp.async.wait_group 0;" ::: "memory")

#define LDSM_X4(r0, r1, r2, r3, a) \
    asm volatile("ldmatrix.sync.aligned.m8n8.x4.shared.b16 {%0,%1,%2,%3}, [%4];" \
        : "=r"(r0), "=r"(r1), "=r"(r2), "=r"(r3) : "r"(a))
#define LDSM_X4T(r0, r1, r2, r3, a) \
    asm volatile("ldmatrix.sync.aligned.m8n8.x4.trans.shared.b16 {%0,%1,%2,%3}, [%4];" \
        : "=r"(r0), "=r"(r1), "=r"(r2), "=r"(r3) : "r"(a))

#define MMA16816(c0, c1, c2, c3, a0, a1, a2, a3, b0, b1) \
    asm volatile("mma.sync.aligned.m16n8k16.row.col.f32.bf16.bf16.f32 " \
        "{%0,%1,%2,%3}, {%4,%5,%6,%7}, {%8,%9}, {%0,%1,%2,%3};" \
        : "+f"(c0), "+f"(c1), "+f"(c2), "+f"(c3) \
        : "r"(a0), "r"(a1), "r"(a2), "r"(a3), "r"(b0), "r"(b1))

#define MMAF16(c0, c1, c2, c3, a0, a1, a2, a3, b0, b1) \
    asm volatile("mma.sync.aligned.m16n8k16.row.col.f32.f16.f16.f32 " \
        "{%0,%1,%2,%3}, {%4,%5,%6,%7}, {%8,%9}, {%0,%1,%2,%3};" \
        : "+f"(c0), "+f"(c1), "+f"(c2), "+f"(c3) \
        : "r"(a0), "r"(a1), "r"(a2), "r"(a3), "r"(b0), "r"(b1))

__device__ __forceinline__ void mma_acc(float* c, const uint32_t* a, uint32_t b0, uint32_t b1) {
    MMA16816(c[0], c[1], c[2], c[3], a[0], a[1], a[2], a[3], b0, b1);
}
__device__ __forceinline__ void mma_f16(float* c, const uint32_t* a, uint32_t b0, uint32_t b1) {
    MMAF16(c[0], c[1], c[2], c[3], a[0], a[1], a[2], a[3], b0, b1);
}

// ---------------- HMMA GEMM: A fp16 single, B fp16 hi/lo, 2 MMA passes per chunk ----------------
struct TcP {
    const __half *A, *Bh, *Bl;
    const float *bias, *bias1, *bias2, *R;
    float* Cf; __half* Cs;
    __nv_bfloat16 *Qh, *Ql, *Kh, *Kl;
    __half *Vh, *Vl;
    long a_out, a_in, b_out, b_in, c_out, c_in;
    int a_zdiv, b_zdiv, c_zdiv;
    int as_m, bs_n, cs_m;
    int K, N; float alpha; int act; int qkv;
};

#define RS   80
#define STGB (128 * RS)          // 10240 per plane
#define STG3 (3 * STGB)          // 30720 per stage (A, Bh, Bl)
#define GSMEM (3 * STG3)         // 92160

__global__ void __launch_bounds__(256, 2) tcmm(TcP p)
{
    extern __shared__ __align__(128) char gsm[];

    const int tid = threadIdx.x, wid = tid >> 5, lane = tid & 31;
    const int n0 = blockIdx.x * 128, m0 = blockIdx.y * 128, z = blockIdx.z;
    const int wm = (wid >> 2) * 64;
    const int wn = (wid & 3) * 32;

    const __half* A  = p.A  + (long)(z / p.a_zdiv) * p.a_out + (long)(z % p.a_zdiv) * p.a_in;
    const __half* Bh = p.Bh + (long)(z / p.b_zdiv) * p.b_out + (long)(z % p.b_zdiv) * p.b_in;
    const __half* Bl = p.Bl + (long)(z / p.b_zdiv) * p.b_out + (long)(z % p.b_zdiv) * p.b_in;
    const long coff = (long)(z / p.c_zdiv) * p.c_out + (long)(z % p.c_zdiv) * p.c_in;

    const uint32_t sbase = smem_u32(gsm);
    const int KC = p.K >> 5;

    const int rowA0 = tid >> 2,         unitA0 = tid & 3;
    const int rowA1 = (tid + 256) >> 2, unitA1 = tid & 3;
    const bool bok0 = (n0 + rowA0 < p.N);
    const bool bok1 = (n0 + rowA1 < p.N);

    float acc[4][4][4];
    #pragma unroll
    for (int i = 0; i < 4; i++)
        #pragma unroll
        for (int j = 0; j < 4; j++)
            #pragma unroll
            for (int r = 0; r < 4; r++) acc[i][j][r] = 0.f;

    auto load_stage = [&](int s, int c) {
        const long kof = (long)c << 5;
        uint32_t dA  = sbase + s * STG3;
        uint32_t dBh = dA + STGB;
        uint32_t dBl = dA + 2 * STGB;
        CP_ASYNC16(dA + rowA0 * RS + unitA0 * 16,
                   A + (long)(m0 + rowA0) * p.as_m + kof + unitA0 * 8);
        CP_ASYNC16(dA + rowA1 * RS + unitA1 * 16,
                   A + (long)(m0 + rowA1) * p.as_m + kof + unitA1 * 8);
        if (bok0) {
            long bo = (long)(n0 + rowA0) * p.bs_n + kof + unitA0 * 8;
            CP_ASYNC16(dBh + rowA0 * RS + unitA0 * 16, Bh + bo);
            CP_ASYNC16(dBl + rowA0 * RS + unitA0 * 16, Bl + bo);
        }
        if (bok1) {
            long bo = (long)(n0 + rowA1) * p.bs_n + kof + unitA1 * 8;
            CP_ASYNC16(dBh + rowA1 * RS + unitA1 * 16, Bh + bo);
            CP_ASYNC16(dBl + rowA1 * RS + unitA1 * 16, Bl + bo);
        }
    };

    load_stage(0, 0); CP_COMMIT();
    load_stage(1, 1); CP_COMMIT();

    for (int c = 0; c < KC; c++) {
        if (c + 1 < KC) { CP_WAIT1(); } else { CP_WAIT0(); }
        __syncthreads();
        if (c + 2 < KC) { load_stage((c + 2) % 3, c + 2); CP_COMMIT(); }

        const uint32_t sA  = sbase + (c % 3) * STG3;
        const uint32_t sBh = sA + STGB;

        #pragma unroll
        for (int ks = 0; ks < 2; ks++) {
            uint32_t a[4][4];
            #pragma unroll
            for (int i = 0; i < 4; i++) {
                uint32_t ad = sA + (uint32_t)(wm + i * 16 + (lane & 15)) * RS
                            + ks * 32 + (lane >> 4) * 16;
                LDSM_X4(a[i][0], a[i][1], a[i][2], a[i][3], ad);
            }
            #pragma unroll
            for (int j = 0; j < 2; j++) {
                uint32_t boff = (uint32_t)(wn + j * 16 + ((lane >> 4) & 1) * 8 + (lane & 7)) * RS
                              + ks * 32 + ((lane >> 3) & 1) * 16;
                uint32_t b0, b1, b2, b3;
                LDSM_X4(b0, b1, b2, b3, sBh + boff);
                #pragma unroll
                for (int i = 0; i < 4; i++) {
                    MMAF16(acc[i][2*j][0],   acc[i][2*j][1],   acc[i][2*j][2],   acc[i][2*j][3],
                           a[i][0], a[i][1], a[i][2], a[i][3], b0, b1);
                    MMAF16(acc[i][2*j+1][0], acc[i][2*j+1][1], acc[i][2*j+1][2], acc[i][2*j+1][3],
                           a[i][0], a[i][1], a[i][2], a[i][3], b2, b3);
                }
                LDSM_X4(b0, b1, b2, b3, sBh + STGB + boff);
                #pragma unroll
                for (int i = 0; i < 4; i++) {
                    MMAF16(acc[i][2*j][0],   acc[i][2*j][1],   acc[i][2*j][2],   acc[i][2*j][3],
                           a[i][0], a[i][1], a[i][2], a[i][3], b0, b1);
                    MMAF16(acc[i][2*j+1][0], acc[i][2*j+1][1], acc[i][2*j+1][2], acc[i][2*j+1][3],
                           a[i][0], a[i][1], a[i][2], a[i][3], b2, b3);
                }
            }
        }
    }

    // epilogue
    #pragma unroll
    for (int i = 0; i < 4; i++) {
        #pragma unroll
        for (int j = 0; j < 4; j++) {
            int n = n0 + wn + j * 8 + (lane & 3) * 2;
            if (n >= p.N) continue;
            #pragma unroll
            for (int half_ = 0; half_ < 2; half_++) {
                int m = m0 + wm + i * 16 + (lane >> 2) + half_ * 8;
                float vx = acc[i][j][half_ * 2 + 0];
                float vy = acc[i][j][half_ * 2 + 1];
                const long base = coff + (long)m * p.cs_m + n;
                if (p.qkv) {
                    const float* bias = (z == 0) ? p.bias : (z == 1) ? p.bias1 : p.bias2;
                    vx += bias[n]; vy += bias[n + 1];
                    if (z == 0) { vx *= QSCL; vy *= QSCL; }
                    if (z == 2) {
                        __half h0, h1, l0, l1;
                        splith(vx, h0, l0); splith(vy, h1, l1);
                        *(__half2*)(p.Vh + base) = __halves2half2(h0, h1);
                        *(__half2*)(p.Vl + base) = __halves2half2(l0, l1);
                    } else {
                        __nv_bfloat16 h0, h1, l0, l1;
                        splitbf(vx, h0, l0); splitbf(vy, h1, l1);
                        __nv_bfloat16* oh = (z == 0) ? p.Qh : p.Kh;
                        __nv_bfloat16* ol = (z == 0) ? p.Ql : p.Kl;
                        *(__nv_bfloat162*)(oh + base) = __halves2bfloat162(h0, h1);
                        *(__nv_bfloat162*)(ol + base) = __halves2bfloat162(l0, l1);
                    }
                } else {
                    if (p.bias) { vx += p.bias[n]; vy += p.bias[n + 1]; }
                    if (p.act)  { vx = gelu_f(vx); vy = gelu_f(vy); }
                    if (p.R) {
                        float2 rr = *(const float2*)(p.R + base);
                        vx += rr.x; vy += rr.y;
                    }
                    if (p.Cf) *(float2*)(p.Cf + base) = make_float2(vx, vy);
                    if (p.Cs) *(__half2*)(p.Cs + base) = __floats2half2_rn(vx, vy);
                }
            }
        }
    }
}

// ---------------- Flash attention (unchanged core; ctx out single fp16) ----------------
#define FRS   144
#define FQPL  (128 * FRS)
#define FKPL  (64 * FRS)
#define FSTG  (4 * FKPL)
#define FSMEM (2 * FQPL + 2 * FSTG)   // 110592
#define NKT   16

__global__ void __launch_bounds__(256, 2) flash_attn(
    const __nv_bfloat16* __restrict__ qh, const __nv_bfloat16* __restrict__ ql,
    const __nv_bfloat16* __restrict__ kh, const __nv_bfloat16* __restrict__ kl,
    const __half* __restrict__ vh, const __half* __restrict__ vl,
    __half* __restrict__ ch)
{
    extern __shared__ __align__(128) char fsm[];
    const int tid = threadIdx.x, wid = tid >> 5, lane = tid & 31;
    const int b = blockIdx.z / HH, h = blockIdx.z % HH;
    const size_t qrow0 = (size_t)b * SSEQ + blockIdx.x * 128;
    const size_t krow0 = (size_t)b * SSEQ;
    const int hc = h * DHH;

    const uint32_t sb  = smem_u32(fsm);
    const uint32_t sKV = sb + 2 * FQPL;

    {
        #pragma unroll
        for (int i = 0; i < 8; i++) {
            int id = tid + i * 256;
            int pl = id >> 10, rc = id & 1023;
            int row = rc >> 3, cu = rc & 7;
            const __nv_bfloat16* src = (pl ? ql : qh) + (qrow0 + row) * DD + hc + cu * 8;
            CP_ASYNC16(sb + pl * FQPL + (uint32_t)(row * FRS + cu * 16), src);
        }
    }
    auto loadKV = [&](int kt, int s) {
        uint32_t base = sKV + (uint32_t)s * FSTG;
        size_t r0 = krow0 + (size_t)kt * 64;
        #pragma unroll
        for (int i = 0; i < 8; i++) {
            int id = tid + i * 256;
            int pl = id >> 9, rc = id & 511;
            int row = rc >> 3, cu = rc & 7;
            const char* g = (pl == 0) ? (const char*)kh : (pl == 1) ? (const char*)kl
                          : (pl == 2) ? (const char*)vh : (const char*)vl;
            CP_ASYNC16(base + (uint32_t)(pl * FKPL + row * FRS + cu * 16),
                       g + ((r0 + row) * DD + hc + cu * 8) * 2);
        }
    };
    loadKV(0, 0); CP_COMMIT();
    loadKV(1, 1); CP_COMMIT();
    CP_WAIT1(); __syncthreads();

    uint32_t qfh[4][4];
    const int mw = wid * 16;
    #pragma unroll
    for (int kf = 0; kf < 4; kf++) {
        uint32_t ad = sb + (uint32_t)((mw + (lane & 15)) * FRS + kf * 32 + (lane >> 4) * 16);
        LDSM_X4(qfh[kf][0], qfh[kf][1], qfh[kf][2], qfh[kf][3], ad);
    }

    float accO[8][4];
    #pragma unroll
    for (int i = 0; i < 8; i++) { accO[i][0] = accO[i][1] = accO[i][2] = accO[i][3] = 0.f; }
    float mrun0 = -1e30f, mrun1 = -1e30f, lrun0 = 0.f, lrun1 = 0.f;

    for (int kt = 0; kt < NKT; kt++) {
        const uint32_t bK = sKV + (uint32_t)(kt & 1) * FSTG;
        const uint32_t bV = bK + 2 * FKPL;

        float S[8][4];
        #pragma unroll
        for (int j = 0; j < 8; j++) { S[j][0] = S[j][1] = S[j][2] = S[j][3] = 0.f; }

        #pragma unroll
        for (int pass = 0; pass < 3; pass++) {
            const uint32_t kb = bK + ((pass == 1) ? FKPL : 0);
            #pragma unroll
            for (int kf = 0; kf < 4; kf++) {
                uint32_t qa[4];
                if (pass == 2) {
                    uint32_t ad = sb + FQPL
                        + (uint32_t)((mw + (lane & 15)) * FRS + kf * 32 + (lane >> 4) * 16);
                    LDSM_X4(qa[0], qa[1], qa[2], qa[3], ad);
                } else {
                    qa[0] = qfh[kf][0]; qa[1] = qfh[kf][1];
                    qa[2] = qfh[kf][2]; qa[3] = qfh[kf][3];
                }
                #pragma unroll
                for (int jp = 0; jp < 4; jp++) {
                    uint32_t b0, b1, b2, b3;
                    uint32_t ad = kb + (uint32_t)((jp * 16 + ((lane >> 4) & 1) * 8 + (lane & 7)) * FRS
                                + kf * 32 + ((lane >> 3) & 1) * 16);
                    LDSM_X4(b0, b1, b2, b3, ad);
                    mma_acc(S[2 * jp],     qa, b0, b1);
                    mma_acc(S[2 * jp + 1], qa, b2, b3);
                }
            }
        }

        float rm0 = -1e30f, rm1 = -1e30f;
        #pragma unroll
        for (int j = 0; j < 8; j++) {
            rm0 = fmaxf(rm0, fmaxf(S[j][0], S[j][1]));
            rm1 = fmaxf(rm1, fmaxf(S[j][2], S[j][3]));
        }
        rm0 = fmaxf(rm0, __shfl_xor_sync(0xFFFFFFFFu, rm0, 1));
        rm0 = fmaxf(rm0, __shfl_xor_sync(0xFFFFFFFFu, rm0, 2));
        rm1 = fmaxf(rm1, __shfl_xor_sync(0xFFFFFFFFu, rm1, 1));
        rm1 = fmaxf(rm1, __shfl_xor_sync(0xFFFFFFFFu, rm1, 2));
        float mn0 = fmaxf(mrun0, rm0), mn1 = fmaxf(mrun1, rm1);
        float sc0 = exp2f(mrun0 - mn0), sc1 = exp2f(mrun1 - mn1);
        mrun0 = mn0; mrun1 = mn1;
        #pragma unroll
        for (int i = 0; i < 8; i++) {
            accO[i][0] *= sc0; accO[i][1] *= sc0;
            accO[i][2] *= sc1; accO[i][3] *= sc1;
        }

        float rs0 = 0.f, rs1 = 0.f;
        #pragma unroll
        for (int kf = 0; kf < 4; kf++) {
            __half2 e0 = h2exp2(__floats2half2_rn(S[2*kf][0]   - mn0, S[2*kf][1]   - mn0));
            __half2 e1 = h2exp2(__floats2half2_rn(S[2*kf][2]   - mn1, S[2*kf][3]   - mn1));
            __half2 e2 = h2exp2(__floats2half2_rn(S[2*kf+1][0] - mn0, S[2*kf+1][1] - mn0));
            __half2 e3 = h2exp2(__floats2half2_rn(S[2*kf+1][2] - mn1, S[2*kf+1][3] - mn1));
            uint32_t pa[4];
            pa[0] = *reinterpret_cast<uint32_t*>(&e0);
            pa[1] = *reinterpret_cast<uint32_t*>(&e1);
            pa[2] = *reinterpret_cast<uint32_t*>(&e2);
            pa[3] = *reinterpret_cast<uint32_t*>(&e3);
            float2 f0 = __half22float2(e0), f1 = __half22float2(e1);
            float2 f2 = __half22float2(e2), f3 = __half22float2(e3);
            rs0 += f0.x + f0.y + f2.x + f2.y;
            rs1 += f1.x + f1.y + f3.x + f3.y;

            #pragma unroll
            for (int np = 0; np < 4; np++) {
                uint32_t ad = bV + (uint32_t)((kf * 16 + ((lane >> 3) & 1) * 8 + (lane & 7)) * FRS
                            + np * 32 + (lane >> 4) * 16);
                uint32_t v0, v1, v2, v3;
                LDSM_X4T(v0, v1, v2, v3, ad);
                mma_f16(accO[2 * np],     pa, v0, v1);
                mma_f16(accO[2 * np + 1], pa, v2, v3);
                LDSM_X4T(v0, v1, v2, v3, ad + FKPL);
                mma_f16(accO[2 * np],     pa, v0, v1);
                mma_f16(accO[2 * np + 1], pa, v2, v3);
            }
        }
        rs0 += __shfl_xor_sync(0xFFFFFFFFu, rs0, 1);
        rs0 += __shfl_xor_sync(0xFFFFFFFFu, rs0, 2);
        rs1 += __shfl_xor_sync(0xFFFFFFFFu, rs1, 1);
        rs1 += __shfl_xor_sync(0xFFFFFFFFu, rs1, 2);
        lrun0 = lrun0 * sc0 + rs0;
        lrun1 = lrun1 * sc1 + rs1;

        __syncthreads();
        if (kt + 2 < NKT) { loadKV(kt + 2, kt & 1); CP_COMMIT(); }
        if (kt + 1 < NKT) {
            if (kt + 2 < NKT) { CP_WAIT1(); } else { CP_WAIT0(); }
            __syncthreads();
        }
    }

    float inv0 = 1.f / lrun0, inv1 = 1.f / lrun1;
    size_t r0 = qrow0 + mw + (lane >> 2);
    #pragma unroll
    for (int nt = 0; nt < 8; nt++) {
        int col = hc + nt * 8 + 2 * (lane & 3);
        *(__half2*)(ch + r0 * DD + col) =
            __floats2half2_rn(accO[nt][0] * inv0, accO[nt][1] * inv0);
        *(__half2*)(ch + (r0 + 8) * DD + col) =
            __floats2half2_rn(accO[nt][2] * inv1, accO[nt][3] * inv1);
    }
}

// ---------------- merged weight prep (fp16 hi/lo) ----------------
#define QKVN (DD * DD)
#define WON  (DD * DD)
#define W12N (DD * DFF_)
__global__ void __launch_bounds__(256) prep_all(
    const float* __restrict__ Wq, const float* __restrict__ Wk, const float* __restrict__ Wv,
    const float* __restrict__ Wo, const float* __restrict__ W1, const float* __restrict__ W2,
    __half* __restrict__ wqh, __half* __restrict__ wql,
    __half* __restrict__ woh, __half* __restrict__ wol,
    __half* __restrict__ w1h, __half* __restrict__ w1l,
    __half* __restrict__ w2h, __half* __restrict__ w2l)
{
    long idx = (long)blockIdx.x * 256 + threadIdx.x;
    __half hh, ll;
    if (idx < QKVN) {
        int n = (int)(idx / DD), d = (int)(idx % DD);
        int h = n >> 6, c = n & 63;
        size_t src = (size_t)h * DD * DHH + (size_t)d * DHH + c;
        splith(Wq[src], hh, ll); wqh[idx] = hh;              wql[idx] = ll;
        splith(Wk[src], hh, ll); wqh[idx + QKVN] = hh;       wql[idx + QKVN] = ll;
        splith(Wv[src], hh, ll); wqh[idx + 2*QKVN] = hh;     wql[idx + 2*QKVN] = ll;
        return;
    }
    idx -= QKVN;
    if (idx < WON) {
        int n = (int)(idx / DD), k = (int)(idx % DD);
        splith(Wo[(long)k * DD + n], hh, ll);
        woh[idx] = hh; wol[idx] = ll;
        return;
    }
    idx -= WON;
    if (idx < W12N) {
        int n = (int)(idx / DD), k = (int)(idx % DD);
        splith(W1[(long)k * DFF_ + n], hh, ll);
        w1h[idx] = hh; w1l[idx] = ll;
        return;
    }
    idx -= W12N;
    if (idx < W12N) {
        int n = (int)(idx / DFF_), k = (int)(idx % DFF_);
        splith(W2[(long)k * DD + n], hh, ll);
        w2h[idx] = hh; w2l[idx] = ll;
    }
}

// ---------------- LayerNorm -> single fp16 ----------------
__global__ void __launch_bounds__(256) lnorm_kernel(
    const float* __restrict__ x, const float* __restrict__ g, const float* __restrict__ b,
    __half* __restrict__ oh)
{
    size_t row = blockIdx.x;
    const float* xr = x + row * DD;
    int t = threadIdx.x;
    float v0 = xr[t], v1 = xr[t + 256], v2 = xr[t + 512];
    float s  = v0 + v1 + v2;
    float s2 = v0*v0 + v1*v1 + v2*v2;
    #pragma unroll
    for (int o = 16; o; o >>= 1) {
        s  += __shfl_xor_sync(0xFFFFFFFFu, s,  o);
        s2 += __shfl_xor_sync(0xFFFFFFFFu, s2, o);
    }
    __shared__ float sh[2][8];
    int w = t >> 5, l = t & 31;
    if (l == 0) { sh[0][w] = s; sh[1][w] = s2; }
    __syncthreads();
    s = 0.f; s2 = 0.f;
    #pragma unroll
    for (int i = 0; i < 8; i++) { s += sh[0][i]; s2 += sh[1][i]; }
    float mean = s * (1.f / 768.f);
    float var  = s2 * (1.f / 768.f) - mean * mean;
    float inv  = rsqrtf(var + 1e-5f);
    oh[row*DD + t]       = __float2half_rn((v0 - mean) * inv * g[t]       + b[t]);
    oh[row*DD + t + 256] = __float2half_rn((v1 - mean) * inv * g[t + 256] + b[t + 256]);
    oh[row*DD + t + 512] = __float2half_rn((v2 - mean) * inv * g[t + 512] + b[t + 512]);
}

// ---------------- host ----------------
extern "C" void kernel_launch(void* const* d_in, const int* in_sizes, int n_in,
                              void* d_out, int out_size)
{
    (void)in_sizes; (void)n_in; (void)out_size;
    const float* x    = (const float*)d_in[0];
    const float* ln1g = (const float*)d_in[1];
    const float* ln1b = (const float*)d_in[2];
    const float* Wq   = (const float*)d_in[3];
    const float* bq   = (const float*)d_in[4];
    const float* Wk   = (const float*)d_in[5];
    const float* bk   = (const float*)d_in[6];
    const float* Wv   = (const float*)d_in[7];
    const float* bv   = (const float*)d_in[8];
    const float* Wo   = (const float*)d_in[9];
    const float* bo   = (const float*)d_in[10];
    const float* ln2g = (const float*)d_in[11];
    const float* ln2b = (const float*)d_in[12];
    const float* W1   = (const float*)d_in[13];
    const float* b1   = (const float*)d_in[14];
    const float* W2   = (const float*)d_in[15];
    const float* b2   = (const float*)d_in[16];
    float* out = (float*)d_out;

    float *x2;
    __nv_bfloat16 *qh, *ql, *kh, *kl;
    __half *h, *vh, *vl, *c, *ff, *wqh, *wql, *woh, *wol, *w1h, *w1l, *w2h, *w2l;
    cudaGetSymbolAddress((void**)&x2,  g_x2);
    cudaGetSymbolAddress((void**)&h,   g_h);
    cudaGetSymbolAddress((void**)&qh,  g_qh);  cudaGetSymbolAddress((void**)&ql,  g_ql);
    cudaGetSymbolAddress((void**)&kh,  g_kh);  cudaGetSymbolAddress((void**)&kl,  g_kl);
    cudaGetSymbolAddress((void**)&vh,  g_vh);  cudaGetSymbolAddress((void**)&vl,  g_vl);
    cudaGetSymbolAddress((void**)&c,   g_c);
    cudaGetSymbolAddress((void**)&ff,  g_ff);
    cudaGetSymbolAddress((void**)&wqh, g_wqh); cudaGetSymbolAddress((void**)&wql, g_wql);
    cudaGetSymbolAddress((void**)&woh, g_woh); cudaGetSymbolAddress((void**)&wol, g_wol);
    cudaGetSymbolAddress((void**)&w1h, g_w1h); cudaGetSymbolAddress((void**)&w1l, g_w1l);
    cudaGetSymbolAddress((void**)&w2h, g_w2h); cudaGetSymbolAddress((void**)&w2l, g_w2l);

    cudaFuncSetAttribute(tcmm, cudaFuncAttributeMaxDynamicSharedMemorySize, GSMEM);
    cudaFuncSetAttribute(flash_attn, cudaFuncAttributeMaxDynamicSharedMemorySize, FSMEM);

    {
        long total = (long)QKVN + WON + 2L * W12N;
        prep_all<<<(unsigned)((total + 255) / 256), 256>>>(
            Wq, Wk, Wv, Wo, W1, W2, wqh, wql, woh, wol, w1h, w1l, w2h, w2l);
    }

    lnorm_kernel<<<MTOK, 256>>>(x, ln1g, ln1b, h);

    // fused QKV projection (z = 0:q, 1:k, 2:v)
    {
        TcP p{};
        p.A = h; p.as_m = DD; p.a_out = 0; p.a_in = 0; p.a_zdiv = 1;
        p.Bh = wqh; p.Bl = wql; p.bs_n = DD;
        p.b_out = (long)DD * DD; p.b_in = 0; p.b_zdiv = 1;
        p.cs_m = DD; p.c_out = 0; p.c_in = 0; p.c_zdiv = 1;
        p.K = DD; p.N = DD; p.alpha = 1.f; p.act = 0; p.qkv = 1;
        p.bias = bq; p.bias1 = bk; p.bias2 = bv;
        p.Qh = qh; p.Ql = ql; p.Kh = kh; p.Kl = kl; p.Vh = vh; p.Vl = vl;
        tcmm<<<dim3(DD / 128, MTOK / 128, 3), 256, GSMEM>>>(p);
    }

    flash_attn<<<dim3(SSEQ / 128, 1, BB * HH), 256, FSMEM>>>(
        qh, ql, kh, kl, vh, vl, c);

    // x2 = x + ctx @ Wo + bo
    {
        TcP s{};
        s.A = c; s.as_m = DD; s.a_out = 0; s.a_in = 0; s.a_zdiv = 1;
        s.Bh = woh; s.Bl = wol; s.bs_n = DD; s.b_out = 0; s.b_in = 0; s.b_zdiv = 1;
        s.bias = bo; s.R = x;
        s.Cf = x2;
        s.cs_m = DD; s.c_out = 0; s.c_in = 0; s.c_zdiv = 1;
        s.K = DD; s.N = DD; s.alpha = 1.f; s.act = 0; s.qkv = 0;
        tcmm<<<dim3(DD / 128, MTOK / 128, 1), 256, GSMEM>>>(s);
    }

    lnorm_kernel<<<MTOK, 256>>>(x2, ln2g, ln2b, h);

    // ff = gelu(h @ W1 + b1)
    {
        TcP s{};
        s.A = h; s.as_m = DD; s.a_out = 0; s.a_in = 0; s.a_zdiv = 1;
        s.Bh = w1h; s.Bl = w1l; s.bs_n = DD; s.b_out = 0; s.b_in = 0; s.b_zdiv = 1;
        s.bias = b1;
        s.Cs = ff;
        s.cs_m = DFF_; s.c_out = 0; s.c_in = 0; s.c_zdiv = 1;
        s.K = DD; s.N = DFF_; s.alpha = 1.f; s.act = 1; s.qkv = 0;
        tcmm<<<dim3(DFF_ / 128, MTOK / 128, 1), 256, GSMEM>>>(s);
    }

    // out = x2 + ff @ W2 + b2
    {
        TcP s{};
        s.A = ff; s.as_m = DFF_; s.a_out = 0; s.a_in = 0; s.a_zdiv = 1;
        s.Bh = w2h; s.Bl = w2l; s.bs_n = DFF_; s.b_out = 0; s.b_in = 0; s.b_zdiv = 1;
        s.bias = b2; s.R = x2;
        s.Cf = out;
        s.cs_m = DD; s.c_out = 0; s.c_in = 0; s.c_zdiv = 1;
        s.K = DFF_; s.N = DD; s.alpha = 1.f; s.act = 0; s.qkv = 0;
        tcmm<<<dim3(DD / 128, MTOK / 128, 1), 256, GSMEM>>>(s);
    }
}

// round 9
// speedup vs baseline: 7.9911x; 1.3845x over previous
#include <cuda_runtime.h>
#include <cuda_bf16.h>
#include <cuda_fp16.h>
#include <math.h>
#include <stdint.h>

#define BB   16
#define SSEQ 1024
#define DD   768
#define HH   12
#define DHH  64
#define DFF_ 3072
#define MTOK (BB*SSEQ)
#define QSCL 0.18033688011112042f   /* 0.125 * log2(e) */

// ---------------- scratch ----------------
__device__ float          g_x2 [(size_t)MTOK * DD];
__device__ __half         g_h  [(size_t)MTOK * DD];
__device__ __nv_bfloat16  g_qh [(size_t)MTOK * DD],  g_ql [(size_t)MTOK * DD];
__device__ __nv_bfloat16  g_kh [(size_t)MTOK * DD],  g_kl [(size_t)MTOK * DD];
__device__ __half         g_vh [(size_t)MTOK * DD],  g_vl [(size_t)MTOK * DD];
__device__ __half         g_c  [(size_t)MTOK * DD];
__device__ __half         g_ff [(size_t)MTOK * DFF_];
__device__ __half         g_wq [3 * DD * DD];
__device__ __half         g_wo [DD * DD];
__device__ __half         g_w1 [DD * DFF_];
__device__ __half         g_w2 [DD * DFF_];

// ---------------- helpers ----------------
__device__ __forceinline__ uint32_t smem_u32(const void* p) {
    uint32_t a;
    asm("{ .reg .u64 t; cvta.to.shared.u64 t, %1; cvt.u32.u64 %0, t; }" : "=r"(a) : "l"(p));
    return a;
}
__device__ __forceinline__ void splitbf(float x, __nv_bfloat16& h, __nv_bfloat16& l) {
    h = __float2bfloat16(x);
    l = __float2bfloat16(x - __bfloat162float(h));
}
__device__ __forceinline__ void splith(float x, __half& h, __half& l) {
    h = __float2half_rn(x);
    l = __float2half_rn(x - __half2float(h));
}
__device__ __forceinline__ float gelu_f(float v) {
    return 0.5f * v * (1.f + erff(v * 0.70710678118654752f));
}

#define CP_ASYNC16(dst, src) \
    asm volatile("cp.async.cg.shared.global [%0], [%1], 16;" :: "r"(dst), "l"(src))
#define CP_COMMIT()  asm volatile("cp.async.commit_group;" ::: "memory")
#define CP_WAIT1()   asm volatile("cp.async.wait_group 1;" ::: "memory")
#define CP_WAIT0()   asm volatile("cp.async.wait_group 0;" ::: "memory")

#define LDSM_X4(r0, r1, r2, r3, a) \
    asm volatile("ldmatrix.sync.aligned.m8n8.x4.shared.b16 {%0,%1,%2,%3}, [%4];" \
        : "=r"(r0), "=r"(r1), "=r"(r2), "=r"(r3) : "r"(a))
#define LDSM_X4T(r0, r1, r2, r3, a) \
    asm volatile("ldmatrix.sync.aligned.m8n8.x4.trans.shared.b16 {%0,%1,%2,%3}, [%4];" \
        : "=r"(r0), "=r"(r1), "=r"(r2), "=r"(r3) : "r"(a))

#define MMA16816(c0, c1, c2, c3, a0, a1, a2, a3, b0, b1) \
    asm volatile("mma.sync.aligned.m16n8k16.row.col.f32.bf16.bf16.f32 " \
        "{%0,%1,%2,%3}, {%4,%5,%6,%7}, {%8,%9}, {%0,%1,%2,%3};" \
        : "+f"(c0), "+f"(c1), "+f"(c2), "+f"(c3) \
        : "r"(a0), "r"(a1), "r"(a2), "r"(a3), "r"(b0), "r"(b1))

#define MMAF16(c0, c1, c2, c3, a0, a1, a2, a3, b0, b1) \
    asm volatile("mma.sync.aligned.m16n8k16.row.col.f32.f16.f16.f32 " \
        "{%0,%1,%2,%3}, {%4,%5,%6,%7}, {%8,%9}, {%0,%1,%2,%3};" \
        : "+f"(c0), "+f"(c1), "+f"(c2), "+f"(c3) \
        : "r"(a0), "r"(a1), "r"(a2), "r"(a3), "r"(b0), "r"(b1))

__device__ __forceinline__ void mma_acc(float* c, const uint32_t* a, uint32_t b0, uint32_t b1) {
    MMA16816(c[0], c[1], c[2], c[3], a[0], a[1], a[2], a[3], b0, b1);
}
__device__ __forceinline__ void mma_f16(float* c, const uint32_t* a, uint32_t b0, uint32_t b1) {
    MMAF16(c[0], c[1], c[2], c[3], a[0], a[1], a[2], a[3], b0, b1);
}

// ---------------- HMMA GEMM: pure fp16 single-pass, 4-stage paired pipeline ----------------
struct TcP {
    const __half *A, *B;
    const float *bias, *bias1, *bias2, *R;
    float* Cf; __half* Cs;
    __nv_bfloat16 *Qh, *Ql, *Kh, *Kl;
    __half *Vh, *Vl;
    long a_out, a_in, b_out, b_in, c_out, c_in;
    int a_zdiv, b_zdiv, c_zdiv;
    int as_m, bs_n, cs_m;
    int K, N; int act; int qkv;
};

#define RS   80
#define STGB (128 * RS)          // 10240 per plane
#define STG2 (2 * STGB)          // 20480 per stage (A, B)
#define GSMEM (4 * STG2)         // 81920

__global__ void __launch_bounds__(256, 2) tcmm(TcP p)
{
    extern __shared__ __align__(128) char gsm[];

    const int tid = threadIdx.x, wid = tid >> 5, lane = tid & 31;
    const int n0 = blockIdx.x * 128, m0 = blockIdx.y * 128, z = blockIdx.z;
    const int wm = (wid >> 2) * 64;
    const int wn = (wid & 3) * 32;

    const __half* A = p.A + (long)(z / p.a_zdiv) * p.a_out + (long)(z % p.a_zdiv) * p.a_in;
    const __half* B = p.B + (long)(z / p.b_zdiv) * p.b_out + (long)(z % p.b_zdiv) * p.b_in;
    const long coff = (long)(z / p.c_zdiv) * p.c_out + (long)(z % p.c_zdiv) * p.c_in;

    const uint32_t sbase = smem_u32(gsm);
    const int KC = p.K >> 5;             // even for all our shapes

    const int rowA0 = tid >> 2,         unitA0 = tid & 3;
    const int rowA1 = (tid + 256) >> 2, unitA1 = tid & 3;
    const bool bok0 = (n0 + rowA0 < p.N);
    const bool bok1 = (n0 + rowA1 < p.N);

    float acc[4][4][4];
    #pragma unroll
    for (int i = 0; i < 4; i++)
        #pragma unroll
        for (int j = 0; j < 4; j++)
            #pragma unroll
            for (int r = 0; r < 4; r++) acc[i][j][r] = 0.f;

    auto load_stage = [&](int s, int c) {
        const long kof = (long)c << 5;
        uint32_t dA = sbase + s * STG2;
        uint32_t dB = dA + STGB;
        CP_ASYNC16(dA + rowA0 * RS + unitA0 * 16,
                   A + (long)(m0 + rowA0) * p.as_m + kof + unitA0 * 8);
        CP_ASYNC16(dA + rowA1 * RS + unitA1 * 16,
                   A + (long)(m0 + rowA1) * p.as_m + kof + unitA1 * 8);
        if (bok0)
            CP_ASYNC16(dB + rowA0 * RS + unitA0 * 16,
                       B + (long)(n0 + rowA0) * p.bs_n + kof + unitA0 * 8);
        if (bok1)
            CP_ASYNC16(dB + rowA1 * RS + unitA1 * 16,
                       B + (long)(n0 + rowA1) * p.bs_n + kof + unitA1 * 8);
    };

    load_stage(0, 0);
    load_stage(1, 1);
    CP_COMMIT();

    for (int c = 0; c < KC; c += 2) {
        CP_WAIT0();
        __syncthreads();
        if (c + 2 < KC) {
            load_stage((c + 2) & 3, c + 2);
            load_stage((c + 3) & 3, c + 3);
            CP_COMMIT();
        }

        #pragma unroll
        for (int cc = 0; cc < 2; cc++) {
            const uint32_t sA = sbase + ((c + cc) & 3) * STG2;
            const uint32_t sB = sA + STGB;
            #pragma unroll
            for (int ks = 0; ks < 2; ks++) {
                uint32_t a[4][4], b[4][2];
                #pragma unroll
                for (int i = 0; i < 4; i++) {
                    uint32_t ad = sA + (uint32_t)(wm + i * 16 + (lane & 15)) * RS
                                + ks * 32 + (lane >> 4) * 16;
                    LDSM_X4(a[i][0], a[i][1], a[i][2], a[i][3], ad);
                }
                #pragma unroll
                for (int j = 0; j < 2; j++) {
                    uint32_t bd = sB + (uint32_t)(wn + j * 16 + ((lane >> 4) & 1) * 8 + (lane & 7)) * RS
                                + ks * 32 + ((lane >> 3) & 1) * 16;
                    LDSM_X4(b[2*j][0], b[2*j][1], b[2*j+1][0], b[2*j+1][1], bd);
                }
                #pragma unroll
                for (int i = 0; i < 4; i++)
                    #pragma unroll
                    for (int j = 0; j < 4; j++)
                        MMAF16(acc[i][j][0], acc[i][j][1], acc[i][j][2], acc[i][j][3],
                               a[i][0], a[i][1], a[i][2], a[i][3], b[j][0], b[j][1]);
            }
        }
    }

    // epilogue
    #pragma unroll
    for (int i = 0; i < 4; i++) {
        #pragma unroll
        for (int j = 0; j < 4; j++) {
            int n = n0 + wn + j * 8 + (lane & 3) * 2;
            if (n >= p.N) continue;
            #pragma unroll
            for (int half_ = 0; half_ < 2; half_++) {
                int m = m0 + wm + i * 16 + (lane >> 2) + half_ * 8;
                float vx = acc[i][j][half_ * 2 + 0];
                float vy = acc[i][j][half_ * 2 + 1];
                const long base = coff + (long)m * p.cs_m + n;
                if (p.qkv) {
                    const float* bias = (z == 0) ? p.bias : (z == 1) ? p.bias1 : p.bias2;
                    vx += bias[n]; vy += bias[n + 1];
                    if (z == 0) { vx *= QSCL; vy *= QSCL; }
                    if (z == 2) {
                        __half h0, h1, l0, l1;
                        splith(vx, h0, l0); splith(vy, h1, l1);
                        *(__half2*)(p.Vh + base) = __halves2half2(h0, h1);
                        *(__half2*)(p.Vl + base) = __halves2half2(l0, l1);
                    } else {
                        __nv_bfloat16 h0, h1, l0, l1;
                        splitbf(vx, h0, l0); splitbf(vy, h1, l1);
                        __nv_bfloat16* oh = (z == 0) ? p.Qh : p.Kh;
                        __nv_bfloat16* ol = (z == 0) ? p.Ql : p.Kl;
                        *(__nv_bfloat162*)(oh + base) = __halves2bfloat162(h0, h1);
                        *(__nv_bfloat162*)(ol + base) = __halves2bfloat162(l0, l1);
                    }
                } else {
                    if (p.bias) { vx += p.bias[n]; vy += p.bias[n + 1]; }
                    if (p.act)  { vx = gelu_f(vx); vy = gelu_f(vy); }
                    if (p.R) {
                        float2 rr = *(const float2*)(p.R + base);
                        vx += rr.x; vy += rr.y;
                    }
                    if (p.Cf) *(float2*)(p.Cf + base) = make_float2(vx, vy);
                    if (p.Cs) *(__half2*)(p.Cs + base) = __floats2half2_rn(vx, vy);
                }
            }
        }
    }
}

// ---------------- Flash attention (unchanged from R8) ----------------
#define FRS   144
#define FQPL  (128 * FRS)
#define FKPL  (64 * FRS)
#define FSTG  (4 * FKPL)
#define FSMEM (2 * FQPL + 2 * FSTG)   // 110592
#define NKT   16

__global__ void __launch_bounds__(256, 2) flash_attn(
    const __nv_bfloat16* __restrict__ qh, const __nv_bfloat16* __restrict__ ql,
    const __nv_bfloat16* __restrict__ kh, const __nv_bfloat16* __restrict__ kl,
    const __half* __restrict__ vh, const __half* __restrict__ vl,
    __half* __restrict__ ch)
{
    extern __shared__ __align__(128) char fsm[];
    const int tid = threadIdx.x, wid = tid >> 5, lane = tid & 31;
    const int b = blockIdx.z / HH, h = blockIdx.z % HH;
    const size_t qrow0 = (size_t)b * SSEQ + blockIdx.x * 128;
    const size_t krow0 = (size_t)b * SSEQ;
    const int hc = h * DHH;

    const uint32_t sb  = smem_u32(fsm);
    const uint32_t sKV = sb + 2 * FQPL;

    {
        #pragma unroll
        for (int i = 0; i < 8; i++) {
            int id = tid + i * 256;
            int pl = id >> 10, rc = id & 1023;
            int row = rc >> 3, cu = rc & 7;
            const __nv_bfloat16* src = (pl ? ql : qh) + (qrow0 + row) * DD + hc + cu * 8;
            CP_ASYNC16(sb + pl * FQPL + (uint32_t)(row * FRS + cu * 16), src);
        }
    }
    auto loadKV = [&](int kt, int s) {
        uint32_t base = sKV + (uint32_t)s * FSTG;
        size_t r0 = krow0 + (size_t)kt * 64;
        #pragma unroll
        for (int i = 0; i < 8; i++) {
            int id = tid + i * 256;
            int pl = id >> 9, rc = id & 511;
            int row = rc >> 3, cu = rc & 7;
            const char* g = (pl == 0) ? (const char*)kh : (pl == 1) ? (const char*)kl
                          : (pl == 2) ? (const char*)vh : (const char*)vl;
            CP_ASYNC16(base + (uint32_t)(pl * FKPL + row * FRS + cu * 16),
                       g + ((r0 + row) * DD + hc + cu * 8) * 2);
        }
    };
    loadKV(0, 0); CP_COMMIT();
    loadKV(1, 1); CP_COMMIT();
    CP_WAIT1(); __syncthreads();

    uint32_t qfh[4][4];
    const int mw = wid * 16;
    #pragma unroll
    for (int kf = 0; kf < 4; kf++) {
        uint32_t ad = sb + (uint32_t)((mw + (lane & 15)) * FRS + kf * 32 + (lane >> 4) * 16);
        LDSM_X4(qfh[kf][0], qfh[kf][1], qfh[kf][2], qfh[kf][3], ad);
    }

    float accO[8][4];
    #pragma unroll
    for (int i = 0; i < 8; i++) { accO[i][0] = accO[i][1] = accO[i][2] = accO[i][3] = 0.f; }
    float mrun0 = -1e30f, mrun1 = -1e30f, lrun0 = 0.f, lrun1 = 0.f;

    for (int kt = 0; kt < NKT; kt++) {
        const uint32_t bK = sKV + (uint32_t)(kt & 1) * FSTG;
        const uint32_t bV = bK + 2 * FKPL;

        float S[8][4];
        #pragma unroll
        for (int j = 0; j < 8; j++) { S[j][0] = S[j][1] = S[j][2] = S[j][3] = 0.f; }

        #pragma unroll
        for (int pass = 0; pass < 3; pass++) {
            const uint32_t kb = bK + ((pass == 1) ? FKPL : 0);
            #pragma unroll
            for (int kf = 0; kf < 4; kf++) {
                uint32_t qa[4];
                if (pass == 2) {
                    uint32_t ad = sb + FQPL
                        + (uint32_t)((mw + (lane & 15)) * FRS + kf * 32 + (lane >> 4) * 16);
                    LDSM_X4(qa[0], qa[1], qa[2], qa[3], ad);
                } else {
                    qa[0] = qfh[kf][0]; qa[1] = qfh[kf][1];
                    qa[2] = qfh[kf][2]; qa[3] = qfh[kf][3];
                }
                #pragma unroll
                for (int jp = 0; jp < 4; jp++) {
                    uint32_t b0, b1, b2, b3;
                    uint32_t ad = kb + (uint32_t)((jp * 16 + ((lane >> 4) & 1) * 8 + (lane & 7)) * FRS
                                + kf * 32 + ((lane >> 3) & 1) * 16);
                    LDSM_X4(b0, b1, b2, b3, ad);
                    mma_acc(S[2 * jp],     qa, b0, b1);
                    mma_acc(S[2 * jp + 1], qa, b2, b3);
                }
            }
        }

        float rm0 = -1e30f, rm1 = -1e30f;
        #pragma unroll
        for (int j = 0; j < 8; j++) {
            rm0 = fmaxf(rm0, fmaxf(S[j][0], S[j][1]));
            rm1 = fmaxf(rm1, fmaxf(S[j][2], S[j][3]));
        }
        rm0 = fmaxf(rm0, __shfl_xor_sync(0xFFFFFFFFu, rm0, 1));
        rm0 = fmaxf(rm0, __shfl_xor_sync(0xFFFFFFFFu, rm0, 2));
        rm1 = fmaxf(rm1, __shfl_xor_sync(0xFFFFFFFFu, rm1, 1));
        rm1 = fmaxf(rm1, __shfl_xor_sync(0xFFFFFFFFu, rm1, 2));
        float mn0 = fmaxf(mrun0, rm0), mn1 = fmaxf(mrun1, rm1);
        float sc0 = exp2f(mrun0 - mn0), sc1 = exp2f(mrun1 - mn1);
        mrun0 = mn0; mrun1 = mn1;
        #pragma unroll
        for (int i = 0; i < 8; i++) {
            accO[i][0] *= sc0; accO[i][1] *= sc0;
            accO[i][2] *= sc1; accO[i][3] *= sc1;
        }

        float rs0 = 0.f, rs1 = 0.f;
        #pragma unroll
        for (int kf = 0; kf < 4; kf++) {
            __half2 e0 = h2exp2(__floats2half2_rn(S[2*kf][0]   - mn0, S[2*kf][1]   - mn0));
            __half2 e1 = h2exp2(__floats2half2_rn(S[2*kf][2]   - mn1, S[2*kf][3]   - mn1));
            __half2 e2 = h2exp2(__floats2half2_rn(S[2*kf+1][0] - mn0, S[2*kf+1][1] - mn0));
            __half2 e3 = h2exp2(__floats2half2_rn(S[2*kf+1][2] - mn1, S[2*kf+1][3] - mn1));
            uint32_t pa[4];
            pa[0] = *reinterpret_cast<uint32_t*>(&e0);
            pa[1] = *reinterpret_cast<uint32_t*>(&e1);
            pa[2] = *reinterpret_cast<uint32_t*>(&e2);
            pa[3] = *reinterpret_cast<uint32_t*>(&e3);
            float2 f0 = __half22float2(e0), f1 = __half22float2(e1);
            float2 f2 = __half22float2(e2), f3 = __half22float2(e3);
            rs0 += f0.x + f0.y + f2.x + f2.y;
            rs1 += f1.x + f1.y + f3.x + f3.y;

            #pragma unroll
            for (int np = 0; np < 4; np++) {
                uint32_t ad = bV + (uint32_t)((kf * 16 + ((lane >> 3) & 1) * 8 + (lane & 7)) * FRS
                            + np * 32 + (lane >> 4) * 16);
                uint32_t v0, v1, v2, v3;
                LDSM_X4T(v0, v1, v2, v3, ad);
                mma_f16(accO[2 * np],     pa, v0, v1);
                mma_f16(accO[2 * np + 1], pa, v2, v3);
                LDSM_X4T(v0, v1, v2, v3, ad + FKPL);
                mma_f16(accO[2 * np],     pa, v0, v1);
                mma_f16(accO[2 * np + 1], pa, v2, v3);
            }
        }
        rs0 += __shfl_xor_sync(0xFFFFFFFFu, rs0, 1);
        rs0 += __shfl_xor_sync(0xFFFFFFFFu, rs0, 2);
        rs1 += __shfl_xor_sync(0xFFFFFFFFu, rs1, 1);
        rs1 += __shfl_xor_sync(0xFFFFFFFFu, rs1, 2);
        lrun0 = lrun0 * sc0 + rs0;
        lrun1 = lrun1 * sc1 + rs1;

        __syncthreads();
        if (kt + 2 < NKT) { loadKV(kt + 2, kt & 1); CP_COMMIT(); }
        if (kt + 1 < NKT) {
            if (kt + 2 < NKT) { CP_WAIT1(); } else { CP_WAIT0(); }
            __syncthreads();
        }
    }

    float inv0 = 1.f / lrun0, inv1 = 1.f / lrun1;
    size_t r0 = qrow0 + mw + (lane >> 2);
    #pragma unroll
    for (int nt = 0; nt < 8; nt++) {
        int col = hc + nt * 8 + 2 * (lane & 3);
        *(__half2*)(ch + r0 * DD + col) =
            __floats2half2_rn(accO[nt][0] * inv0, accO[nt][1] * inv0);
        *(__half2*)(ch + (r0 + 8) * DD + col) =
            __floats2half2_rn(accO[nt][2] * inv1, accO[nt][3] * inv1);
    }
}

// ---------------- merged weight prep (single fp16) ----------------
#define QKVN (DD * DD)
#define WON  (DD * DD)
#define W12N (DD * DFF_)
__global__ void __launch_bounds__(256) prep_all(
    const float* __restrict__ Wq, const float* __restrict__ Wk, const float* __restrict__ Wv,
    const float* __restrict__ Wo, const float* __restrict__ W1, const float* __restrict__ W2,
    __half* __restrict__ wq, __half* __restrict__ wo,
    __half* __restrict__ w1, __half* __restrict__ w2)
{
    long idx = (long)blockIdx.x * 256 + threadIdx.x;
    if (idx < QKVN) {
        int n = (int)(idx / DD), d = (int)(idx % DD);
        int h = n >> 6, c = n & 63;
        size_t src = (size_t)h * DD * DHH + (size_t)d * DHH + c;
        wq[idx]            = __float2half_rn(Wq[src]);
        wq[idx + QKVN]     = __float2half_rn(Wk[src]);
        wq[idx + 2 * QKVN] = __float2half_rn(Wv[src]);
        return;
    }
    idx -= QKVN;
    if (idx < WON) {
        int n = (int)(idx / DD), k = (int)(idx % DD);
        wo[idx] = __float2half_rn(Wo[(long)k * DD + n]);
        return;
    }
    idx -= WON;
    if (idx < W12N) {
        int n = (int)(idx / DD), k = (int)(idx % DD);
        w1[idx] = __float2half_rn(W1[(long)k * DFF_ + n]);
        return;
    }
    idx -= W12N;
    if (idx < W12N) {
        int n = (int)(idx / DFF_), k = (int)(idx % DFF_);
        w2[idx] = __float2half_rn(W2[(long)k * DD + n]);
    }
}

// ---------------- LayerNorm -> single fp16 ----------------
__global__ void __launch_bounds__(256) lnorm_kernel(
    const float* __restrict__ x, const float* __restrict__ g, const float* __restrict__ b,
    __half* __restrict__ oh)
{
    size_t row = blockIdx.x;
    const float* xr = x + row * DD;
    int t = threadIdx.x;
    float v0 = xr[t], v1 = xr[t + 256], v2 = xr[t + 512];
    float s  = v0 + v1 + v2;
    float s2 = v0*v0 + v1*v1 + v2*v2;
    #pragma unroll
    for (int o = 16; o; o >>= 1) {
        s  += __shfl_xor_sync(0xFFFFFFFFu, s,  o);
        s2 += __shfl_xor_sync(0xFFFFFFFFu, s2, o);
    }
    __shared__ float sh[2][8];
    int w = t >> 5, l = t & 31;
    if (l == 0) { sh[0][w] = s; sh[1][w] = s2; }
    __syncthreads();
    s = 0.f; s2 = 0.f;
    #pragma unroll
    for (int i = 0; i < 8; i++) { s += sh[0][i]; s2 += sh[1][i]; }
    float mean = s * (1.f / 768.f);
    float var  = s2 * (1.f / 768.f) - mean * mean;
    float inv  = rsqrtf(var + 1e-5f);
    oh[row*DD + t]       = __float2half_rn((v0 - mean) * inv * g[t]       + b[t]);
    oh[row*DD + t + 256] = __float2half_rn((v1 - mean) * inv * g[t + 256] + b[t + 256]);
    oh[row*DD + t + 512] = __float2half_rn((v2 - mean) * inv * g[t + 512] + b[t + 512]);
}

// ---------------- host ----------------
extern "C" void kernel_launch(void* const* d_in, const int* in_sizes, int n_in,
                              void* d_out, int out_size)
{
    (void)in_sizes; (void)n_in; (void)out_size;
    const float* x    = (const float*)d_in[0];
    const float* ln1g = (const float*)d_in[1];
    const float* ln1b = (const float*)d_in[2];
    const float* Wq   = (const float*)d_in[3];
    const float* bq   = (const float*)d_in[4];
    const float* Wk   = (const float*)d_in[5];
    const float* bk   = (const float*)d_in[6];
    const float* Wv   = (const float*)d_in[7];
    const float* bv   = (const float*)d_in[8];
    const float* Wo   = (const float*)d_in[9];
    const float* bo   = (const float*)d_in[10];
    const float* ln2g = (const float*)d_in[11];
    const float* ln2b = (const float*)d_in[12];
    const float* W1   = (const float*)d_in[13];
    const float* b1   = (const float*)d_in[14];
    const float* W2   = (const float*)d_in[15];
    const float* b2   = (const float*)d_in[16];
    float* out = (float*)d_out;

    float *x2;
    __nv_bfloat16 *qh, *ql, *kh, *kl;
    __half *h, *vh, *vl, *c, *ff, *wq, *wo, *w1, *w2;
    cudaGetSymbolAddress((void**)&x2,  g_x2);
    cudaGetSymbolAddress((void**)&h,   g_h);
    cudaGetSymbolAddress((void**)&qh,  g_qh);  cudaGetSymbolAddress((void**)&ql,  g_ql);
    cudaGetSymbolAddress((void**)&kh,  g_kh);  cudaGetSymbolAddress((void**)&kl,  g_kl);
    cudaGetSymbolAddress((void**)&vh,  g_vh);  cudaGetSymbolAddress((void**)&vl,  g_vl);
    cudaGetSymbolAddress((void**)&c,   g_c);
    cudaGetSymbolAddress((void**)&ff,  g_ff);
    cudaGetSymbolAddress((void**)&wq,  g_wq);
    cudaGetSymbolAddress((void**)&wo,  g_wo);
    cudaGetSymbolAddress((void**)&w1,  g_w1);
    cudaGetSymbolAddress((void**)&w2,  g_w2);

    cudaFuncSetAttribute(tcmm, cudaFuncAttributeMaxDynamicSharedMemorySize, GSMEM);
    cudaFuncSetAttribute(flash_attn, cudaFuncAttributeMaxDynamicSharedMemorySize, FSMEM);

    {
        long total = (long)QKVN + WON + 2L * W12N;
        prep_all<<<(unsigned)((total + 255) / 256), 256>>>(
            Wq, Wk, Wv, Wo, W1, W2, wq, wo, w1, w2);
    }

    lnorm_kernel<<<MTOK, 256>>>(x, ln1g, ln1b, h);

    // fused QKV projection (z = 0:q, 1:k, 2:v)
    {
        TcP p{};
        p.A = h; p.as_m = DD; p.a_out = 0; p.a_in = 0; p.a_zdiv = 1;
        p.B = wq; p.bs_n = DD;
        p.b_out = (long)DD * DD; p.b_in = 0; p.b_zdiv = 1;
        p.cs_m = DD; p.c_out = 0; p.c_in = 0; p.c_zdiv = 1;
        p.K = DD; p.N = DD; p.act = 0; p.qkv = 1;
        p.bias = bq; p.bias1 = bk; p.bias2 = bv;
        p.Qh = qh; p.Ql = ql; p.Kh = kh; p.Kl = kl; p.Vh = vh; p.Vl = vl;
        tcmm<<<dim3(DD / 128, MTOK / 128, 3), 256, GSMEM>>>(p);
    }

    flash_attn<<<dim3(SSEQ / 128, 1, BB * HH), 256, FSMEM>>>(
        qh, ql, kh, kl, vh, vl, c);

    // x2 = x + ctx @ Wo + bo
    {
        TcP s{};
        s.A = c; s.as_m = DD; s.a_out = 0; s.a_in = 0; s.a_zdiv = 1;
        s.B = wo; s.bs_n = DD; s.b_out = 0; s.b_in = 0; s.b_zdiv = 1;
        s.bias = bo; s.R = x;
        s.Cf = x2;
        s.cs_m = DD; s.c_out = 0; s.c_in = 0; s.c_zdiv = 1;
        s.K = DD; s.N = DD; s.act = 0; s.qkv = 0;
        tcmm<<<dim3(DD / 128, MTOK / 128, 1), 256, GSMEM>>>(s);
    }

    lnorm_kernel<<<MTOK, 256>>>(x2, ln2g, ln2b, h);

    // ff = gelu(h @ W1 + b1)
    {
        TcP s{};
        s.A = h; s.as_m = DD; s.a_out = 0; s.a_in = 0; s.a_zdiv = 1;
        s.B = w1; s.bs_n = DD; s.b_out = 0; s.b_in = 0; s.b_zdiv = 1;
        s.bias = b1;
        s.Cs = ff;
        s.cs_m = DFF_; s.c_out = 0; s.c_in = 0; s.c_zdiv = 1;
        s.K = DD; s.N = DFF_; s.act = 1; s.qkv = 0;
        tcmm<<<dim3(DFF_ / 128, MTOK / 128, 1), 256, GSMEM>>>(s);
    }

    // out = x2 + ff @ W2 + b2
    {
        TcP s{};
        s.A = ff; s.as_m = DFF_; s.a_out = 0; s.a_in = 0; s.a_zdiv = 1;
        s.B = w2; s.bs_n = DFF_; s.b_out = 0; s.b_in = 0; s.b_zdiv = 1;
        s.bias = b2; s.R = x2;
        s.Cf = out;
        s.cs_m = DD; s.c_out = 0; s.c_in = 0; s.c_zdiv = 1;
        s.K = DFF_; s.N = DD; s.act = 0; s.qkv = 0;
        tcmm<<<dim3(DD / 128, MTOK / 128, 1), 256, GSMEM>>>(s);
    }
}

// round 10
// speedup vs baseline: 8.8150x; 1.1031x over previous
#include <cuda_runtime.h>
#include <cuda_bf16.h>
#include <cuda_fp16.h>
#include <math.h>
#include <stdint.h>

#define BB   16
#define SSEQ 1024
#define DD   768
#define HH   12
#define DHH  64
#define DFF_ 3072
#define MTOK (BB*SSEQ)
#define QSCL 0.18033688011112042f   /* 0.125 * log2(e) */

// ---------------- scratch ----------------
__device__ float   g_x2 [(size_t)MTOK * DD];
__device__ __half  g_h  [(size_t)MTOK * DD];
__device__ __half  g_q  [(size_t)MTOK * DD];
__device__ __half  g_kh [(size_t)MTOK * DD],  g_kl [(size_t)MTOK * DD];
__device__ __half  g_v  [(size_t)MTOK * DD];
__device__ __half  g_c  [(size_t)MTOK * DD];
__device__ __half  g_ff [(size_t)MTOK * DFF_];
__device__ __half  g_wq [3 * DD * DD];
__device__ __half  g_wo [DD * DD];
__device__ __half  g_w1 [DD * DFF_];
__device__ __half  g_w2 [DD * DFF_];

// ---------------- helpers ----------------
__device__ __forceinline__ uint32_t smem_u32(const void* p) {
    uint32_t a;
    asm("{ .reg .u64 t; cvta.to.shared.u64 t, %1; cvt.u32.u64 %0, t; }" : "=r"(a) : "l"(p));
    return a;
}
__device__ __forceinline__ void splith(float x, __half& h, __half& l) {
    h = __float2half_rn(x);
    l = __float2half_rn(x - __half2float(h));
}
__device__ __forceinline__ float gelu_f(float v) {
    return 0.5f * v * (1.f + erff(v * 0.70710678118654752f));
}

#define CP_ASYNC16(dst, src) \
    asm volatile("cp.async.cg.shared.global [%0], [%1], 16;" :: "r"(dst), "l"(src))
#define CP_COMMIT()  asm volatile("cp.async.commit_group;" ::: "memory")
#define CP_WAIT1()   asm volatile("cp.async.wait_group 1;" ::: "memory")
#define CP_WAIT0()   asm volatile("cp.async.wait_group 0;" ::: "memory")

#define LDSM_X4(r0, r1, r2, r3, a) \
    asm volatile("ldmatrix.sync.aligned.m8n8.x4.shared.b16 {%0,%1,%2,%3}, [%4];" \
        : "=r"(r0), "=r"(r1), "=r"(r2), "=r"(r3) : "r"(a))
#define LDSM_X4T(r0, r1, r2, r3, a) \
    asm volatile("ldmatrix.sync.aligned.m8n8.x4.trans.shared.b16 {%0,%1,%2,%3}, [%4];" \
        : "=r"(r0), "=r"(r1), "=r"(r2), "=r"(r3) : "r"(a))

#define MMAF16(c0, c1, c2, c3, a0, a1, a2, a3, b0, b1) \
    asm volatile("mma.sync.aligned.m16n8k16.row.col.f32.f16.f16.f32 " \
        "{%0,%1,%2,%3}, {%4,%5,%6,%7}, {%8,%9}, {%0,%1,%2,%3};" \
        : "+f"(c0), "+f"(c1), "+f"(c2), "+f"(c3) \
        : "r"(a0), "r"(a1), "r"(a2), "r"(a3), "r"(b0), "r"(b1))

__device__ __forceinline__ void mma_f16(float* c, const uint32_t* a, uint32_t b0, uint32_t b1) {
    MMAF16(c[0], c[1], c[2], c[3], a[0], a[1], a[2], a[3], b0, b1);
}

// ---------------- HMMA GEMM: pure fp16, 4-stage paired pipeline ----------------
struct TcP {
    const __half *A, *B;
    const float *bias, *bias1, *bias2, *R;
    float* Cf; __half* Cs;
    __half *Q, *Kh, *Kl, *V;
    long a_out, a_in, b_out, b_in, c_out, c_in;
    int a_zdiv, b_zdiv, c_zdiv;
    int as_m, bs_n, cs_m;
    int K, N; int act; int qkv;
};

#define RS   80
#define STGB (128 * RS)
#define STG2 (2 * STGB)          // 20480 per stage
#define GSMEM (4 * STG2)         // 81920

__global__ void __launch_bounds__(256, 2) tcmm(TcP p)
{
    extern __shared__ __align__(128) char gsm[];

    const int tid = threadIdx.x, wid = tid >> 5, lane = tid & 31;
    const int n0 = blockIdx.x * 128, m0 = blockIdx.y * 128, z = blockIdx.z;
    const int wm = (wid >> 2) * 64;
    const int wn = (wid & 3) * 32;

    const __half* A = p.A + (long)(z / p.a_zdiv) * p.a_out + (long)(z % p.a_zdiv) * p.a_in;
    const __half* B = p.B + (long)(z / p.b_zdiv) * p.b_out + (long)(z % p.b_zdiv) * p.b_in;
    const long coff = (long)(z / p.c_zdiv) * p.c_out + (long)(z % p.c_zdiv) * p.c_in;

    const uint32_t sbase = smem_u32(gsm);
    const int KC = p.K >> 5;

    const int rowA0 = tid >> 2,         unitA0 = tid & 3;
    const int rowA1 = (tid + 256) >> 2, unitA1 = tid & 3;
    const bool bok0 = (n0 + rowA0 < p.N);
    const bool bok1 = (n0 + rowA1 < p.N);

    float acc[4][4][4];
    #pragma unroll
    for (int i = 0; i < 4; i++)
        #pragma unroll
        for (int j = 0; j < 4; j++)
            #pragma unroll
            for (int r = 0; r < 4; r++) acc[i][j][r] = 0.f;

    auto load_stage = [&](int s, int c) {
        const long kof = (long)c << 5;
        uint32_t dA = sbase + s * STG2;
        uint32_t dB = dA + STGB;
        CP_ASYNC16(dA + rowA0 * RS + unitA0 * 16,
                   A + (long)(m0 + rowA0) * p.as_m + kof + unitA0 * 8);
        CP_ASYNC16(dA + rowA1 * RS + unitA1 * 16,
                   A + (long)(m0 + rowA1) * p.as_m + kof + unitA1 * 8);
        if (bok0)
            CP_ASYNC16(dB + rowA0 * RS + unitA0 * 16,
                       B + (long)(n0 + rowA0) * p.bs_n + kof + unitA0 * 8);
        if (bok1)
            CP_ASYNC16(dB + rowA1 * RS + unitA1 * 16,
                       B + (long)(n0 + rowA1) * p.bs_n + kof + unitA1 * 8);
    };

    load_stage(0, 0);
    load_stage(1, 1);
    CP_COMMIT();

    for (int c = 0; c < KC; c += 2) {
        CP_WAIT0();
        __syncthreads();
        if (c + 2 < KC) {
            load_stage((c + 2) & 3, c + 2);
            load_stage((c + 3) & 3, c + 3);
            CP_COMMIT();
        }

        #pragma unroll
        for (int cc = 0; cc < 2; cc++) {
            const uint32_t sA = sbase + ((c + cc) & 3) * STG2;
            const uint32_t sB = sA + STGB;
            #pragma unroll
            for (int ks = 0; ks < 2; ks++) {
                uint32_t a[4][4], b[4][2];
                #pragma unroll
                for (int i = 0; i < 4; i++) {
                    uint32_t ad = sA + (uint32_t)(wm + i * 16 + (lane & 15)) * RS
                                + ks * 32 + (lane >> 4) * 16;
                    LDSM_X4(a[i][0], a[i][1], a[i][2], a[i][3], ad);
                }
                #pragma unroll
                for (int j = 0; j < 2; j++) {
                    uint32_t bd = sB + (uint32_t)(wn + j * 16 + ((lane >> 4) & 1) * 8 + (lane & 7)) * RS
                                + ks * 32 + ((lane >> 3) & 1) * 16;
                    LDSM_X4(b[2*j][0], b[2*j][1], b[2*j+1][0], b[2*j+1][1], bd);
                }
                #pragma unroll
                for (int i = 0; i < 4; i++)
                    #pragma unroll
                    for (int j = 0; j < 4; j++)
                        MMAF16(acc[i][j][0], acc[i][j][1], acc[i][j][2], acc[i][j][3],
                               a[i][0], a[i][1], a[i][2], a[i][3], b[j][0], b[j][1]);
            }
        }
    }

    // epilogue
    #pragma unroll
    for (int i = 0; i < 4; i++) {
        #pragma unroll
        for (int j = 0; j < 4; j++) {
            int n = n0 + wn + j * 8 + (lane & 3) * 2;
            if (n >= p.N) continue;
            #pragma unroll
            for (int half_ = 0; half_ < 2; half_++) {
                int m = m0 + wm + i * 16 + (lane >> 2) + half_ * 8;
                float vx = acc[i][j][half_ * 2 + 0];
                float vy = acc[i][j][half_ * 2 + 1];
                const long base = coff + (long)m * p.cs_m + n;
                if (p.qkv) {
                    const float* bias = (z == 0) ? p.bias : (z == 1) ? p.bias1 : p.bias2;
                    vx += bias[n]; vy += bias[n + 1];
                    if (z == 0) {
                        *(__half2*)(p.Q + base) = __floats2half2_rn(vx * QSCL, vy * QSCL);
                    } else if (z == 1) {
                        __half h0, h1, l0, l1;
                        splith(vx, h0, l0); splith(vy, h1, l1);
                        *(__half2*)(p.Kh + base) = __halves2half2(h0, h1);
                        *(__half2*)(p.Kl + base) = __halves2half2(l0, l1);
                    } else {
                        *(__half2*)(p.V + base) = __floats2half2_rn(vx, vy);
                    }
                } else {
                    if (p.bias) { vx += p.bias[n]; vy += p.bias[n + 1]; }
                    if (p.act)  { vx = gelu_f(vx); vy = gelu_f(vy); }
                    if (p.R) {
                        float2 rr = *(const float2*)(p.R + base);
                        vx += rr.x; vy += rr.y;
                    }
                    if (p.Cf) *(float2*)(p.Cf + base) = make_float2(vx, vy);
                    if (p.Cs) *(__half2*)(p.Cs + base) = __floats2half2_rn(vx, vy);
                }
            }
        }
    }
}

// ---------------- Flash attention: Q fp16, K hi/lo (2-pass), V single (1-pass) ----------------
#define FRS   144
#define FQPL  (128 * FRS)      // 18432
#define FKPL  (64 * FRS)       // 9216
#define FSTG  (3 * FKPL)       // Kh, Kl, V per stage = 27648
#define FSMEM (FQPL + 2 * FSTG)   // 73728
#define NKT   16

__global__ void __launch_bounds__(256, 2) flash_attn(
    const __half* __restrict__ q,
    const __half* __restrict__ kh, const __half* __restrict__ kl,
    const __half* __restrict__ v,
    __half* __restrict__ ch)
{
    extern __shared__ __align__(128) char fsm[];
    const int tid = threadIdx.x, wid = tid >> 5, lane = tid & 31;
    const int b = blockIdx.z / HH, h = blockIdx.z % HH;
    const size_t qrow0 = (size_t)b * SSEQ + blockIdx.x * 128;
    const size_t krow0 = (size_t)b * SSEQ;
    const int hc = h * DHH;

    const uint32_t sb  = smem_u32(fsm);
    const uint32_t sKV = sb + FQPL;

    // Q load: 128 rows x 8 chunks = 1024 / 256 threads
    {
        #pragma unroll
        for (int i = 0; i < 4; i++) {
            int id = tid + i * 256;
            int row = id >> 3, cu = id & 7;
            CP_ASYNC16(sb + (uint32_t)(row * FRS + cu * 16),
                       q + (qrow0 + row) * DD + hc + cu * 8);
        }
    }
    // KV load: 3 planes (Kh,Kl,V) x 64 rows x 8 chunks = 1536 / 256 threads
    auto loadKV = [&](int kt, int s) {
        uint32_t base = sKV + (uint32_t)s * FSTG;
        size_t r0 = krow0 + (size_t)kt * 64;
        #pragma unroll
        for (int i = 0; i < 6; i++) {
            int id = tid + i * 256;
            int pl = id >> 9, rc = id & 511;
            int row = rc >> 3, cu = rc & 7;
            const __half* g = (pl == 0) ? kh : (pl == 1) ? kl : v;
            CP_ASYNC16(base + (uint32_t)(pl * FKPL + row * FRS + cu * 16),
                       g + (r0 + row) * DD + hc + cu * 8);
        }
    };
    loadKV(0, 0); CP_COMMIT();
    loadKV(1, 1); CP_COMMIT();
    CP_WAIT1(); __syncthreads();

    // persistent Q fragments (single plane)
    uint32_t qf[4][4];
    const int mw = wid * 16;
    #pragma unroll
    for (int kf = 0; kf < 4; kf++) {
        uint32_t ad = sb + (uint32_t)((mw + (lane & 15)) * FRS + kf * 32 + (lane >> 4) * 16);
        LDSM_X4(qf[kf][0], qf[kf][1], qf[kf][2], qf[kf][3], ad);
    }

    float accO[8][4];
    #pragma unroll
    for (int i = 0; i < 8; i++) { accO[i][0] = accO[i][1] = accO[i][2] = accO[i][3] = 0.f; }
    float mrun0 = -1e30f, mrun1 = -1e30f, lrun0 = 0.f, lrun1 = 0.f;

    for (int kt = 0; kt < NKT; kt++) {
        const uint32_t bK = sKV + (uint32_t)(kt & 1) * FSTG;
        const uint32_t bV = bK + 2 * FKPL;

        // ---- S = Q K^T, 2 passes (Kh then Kl), log2 domain ----
        float S[8][4];
        #pragma unroll
        for (int j = 0; j < 8; j++) { S[j][0] = S[j][1] = S[j][2] = S[j][3] = 0.f; }

        #pragma unroll
        for (int pass = 0; pass < 2; pass++) {
            const uint32_t kb = bK + pass * FKPL;
            #pragma unroll
            for (int kf = 0; kf < 4; kf++) {
                #pragma unroll
                for (int jp = 0; jp < 4; jp++) {
                    uint32_t b0, b1, b2, b3;
                    uint32_t ad = kb + (uint32_t)((jp * 16 + ((lane >> 4) & 1) * 8 + (lane & 7)) * FRS
                                + kf * 32 + ((lane >> 3) & 1) * 16);
                    LDSM_X4(b0, b1, b2, b3, ad);
                    mma_f16(S[2 * jp],     qf[kf], b0, b1);
                    mma_f16(S[2 * jp + 1], qf[kf], b2, b3);
                }
            }
        }

        // ---- online max ----
        float rm0 = -1e30f, rm1 = -1e30f;
        #pragma unroll
        for (int j = 0; j < 8; j++) {
            rm0 = fmaxf(rm0, fmaxf(S[j][0], S[j][1]));
            rm1 = fmaxf(rm1, fmaxf(S[j][2], S[j][3]));
        }
        rm0 = fmaxf(rm0, __shfl_xor_sync(0xFFFFFFFFu, rm0, 1));
        rm0 = fmaxf(rm0, __shfl_xor_sync(0xFFFFFFFFu, rm0, 2));
        rm1 = fmaxf(rm1, __shfl_xor_sync(0xFFFFFFFFu, rm1, 1));
        rm1 = fmaxf(rm1, __shfl_xor_sync(0xFFFFFFFFu, rm1, 2));
        float mn0 = fmaxf(mrun0, rm0), mn1 = fmaxf(mrun1, rm1);
        float sc0 = exp2f(mrun0 - mn0), sc1 = exp2f(mrun1 - mn1);
        mrun0 = mn0; mrun1 = mn1;
        #pragma unroll
        for (int i = 0; i < 8; i++) {
            accO[i][0] *= sc0; accO[i][1] *= sc0;
            accO[i][2] *= sc1; accO[i][3] *= sc1;
        }

        // ---- P = exp2(S - m) f16; O += P V (single V pass) ----
        float rs0 = 0.f, rs1 = 0.f;
        #pragma unroll
        for (int kf = 0; kf < 4; kf++) {
            __half2 e0 = h2exp2(__floats2half2_rn(S[2*kf][0]   - mn0, S[2*kf][1]   - mn0));
            __half2 e1 = h2exp2(__floats2half2_rn(S[2*kf][2]   - mn1, S[2*kf][3]   - mn1));
            __half2 e2 = h2exp2(__floats2half2_rn(S[2*kf+1][0] - mn0, S[2*kf+1][1] - mn0));
            __half2 e3 = h2exp2(__floats2half2_rn(S[2*kf+1][2] - mn1, S[2*kf+1][3] - mn1));
            uint32_t pa[4];
            pa[0] = *reinterpret_cast<uint32_t*>(&e0);
            pa[1] = *reinterpret_cast<uint32_t*>(&e1);
            pa[2] = *reinterpret_cast<uint32_t*>(&e2);
            pa[3] = *reinterpret_cast<uint32_t*>(&e3);
            float2 f0 = __half22float2(e0), f1 = __half22float2(e1);
            float2 f2 = __half22float2(e2), f3 = __half22float2(e3);
            rs0 += f0.x + f0.y + f2.x + f2.y;
            rs1 += f1.x + f1.y + f3.x + f3.y;

            #pragma unroll
            for (int np = 0; np < 4; np++) {
                uint32_t ad = bV + (uint32_t)((kf * 16 + ((lane >> 3) & 1) * 8 + (lane & 7)) * FRS
                            + np * 32 + (lane >> 4) * 16);
                uint32_t v0, v1, v2, v3;
                LDSM_X4T(v0, v1, v2, v3, ad);
                mma_f16(accO[2 * np],     pa, v0, v1);
                mma_f16(accO[2 * np + 1], pa, v2, v3);
            }
        }
        rs0 += __shfl_xor_sync(0xFFFFFFFFu, rs0, 1);
        rs0 += __shfl_xor_sync(0xFFFFFFFFu, rs0, 2);
        rs1 += __shfl_xor_sync(0xFFFFFFFFu, rs1, 1);
        rs1 += __shfl_xor_sync(0xFFFFFFFFu, rs1, 2);
        lrun0 = lrun0 * sc0 + rs0;
        lrun1 = lrun1 * sc1 + rs1;

        __syncthreads();
        if (kt + 2 < NKT) { loadKV(kt + 2, kt & 1); CP_COMMIT(); }
        if (kt + 1 < NKT) {
            if (kt + 2 < NKT) { CP_WAIT1(); } else { CP_WAIT0(); }
            __syncthreads();
        }
    }

    float inv0 = 1.f / lrun0, inv1 = 1.f / lrun1;
    size_t r0 = qrow0 + mw + (lane >> 2);
    #pragma unroll
    for (int nt = 0; nt < 8; nt++) {
        int col = hc + nt * 8 + 2 * (lane & 3);
        *(__half2*)(ch + r0 * DD + col) =
            __floats2half2_rn(accO[nt][0] * inv0, accO[nt][1] * inv0);
        *(__half2*)(ch + (r0 + 8) * DD + col) =
            __floats2half2_rn(accO[nt][2] * inv1, accO[nt][3] * inv1);
    }
}

// ---------------- merged weight prep ----------------
#define QKVN (DD * DD)
#define WON  (DD * DD)
#define W12N (DD * DFF_)
__global__ void __launch_bounds__(256) prep_all(
    const float* __restrict__ Wq, const float* __restrict__ Wk, const float* __restrict__ Wv,
    const float* __restrict__ Wo, const float* __restrict__ W1, const float* __restrict__ W2,
    __half* __restrict__ wq, __half* __restrict__ wo,
    __half* __restrict__ w1, __half* __restrict__ w2)
{
    long idx = (long)blockIdx.x * 256 + threadIdx.x;
    if (idx < QKVN) {
        int n = (int)(idx / DD), d = (int)(idx % DD);
        int h = n >> 6, c = n & 63;
        size_t src = (size_t)h * DD * DHH + (size_t)d * DHH + c;
        wq[idx]            = __float2half_rn(Wq[src]);
        wq[idx + QKVN]     = __float2half_rn(Wk[src]);
        wq[idx + 2 * QKVN] = __float2half_rn(Wv[src]);
        return;
    }
    idx -= QKVN;
    if (idx < WON) {
        int n = (int)(idx / DD), k = (int)(idx % DD);
        wo[idx] = __float2half_rn(Wo[(long)k * DD + n]);
        return;
    }
    idx -= WON;
    if (idx < W12N) {
        int n = (int)(idx / DD), k = (int)(idx % DD);
        w1[idx] = __float2half_rn(W1[(long)k * DFF_ + n]);
        return;
    }
    idx -= W12N;
    if (idx < W12N) {
        int n = (int)(idx / DFF_), k = (int)(idx % DFF_);
        w2[idx] = __float2half_rn(W2[(long)k * DD + n]);
    }
}

// ---------------- LayerNorm -> single fp16 ----------------
__global__ void __launch_bounds__(256) lnorm_kernel(
    const float* __restrict__ x, const float* __restrict__ g, const float* __restrict__ b,
    __half* __restrict__ oh)
{
    size_t row = blockIdx.x;
    const float* xr = x + row * DD;
    int t = threadIdx.x;
    float v0 = xr[t], v1 = xr[t + 256], v2 = xr[t + 512];
    float s  = v0 + v1 + v2;
    float s2 = v0*v0 + v1*v1 + v2*v2;
    #pragma unroll
    for (int o = 16; o; o >>= 1) {
        s  += __shfl_xor_sync(0xFFFFFFFFu, s,  o);
        s2 += __shfl_xor_sync(0xFFFFFFFFu, s2, o);
    }
    __shared__ float sh[2][8];
    int w = t >> 5, l = t & 31;
    if (l == 0) { sh[0][w] = s; sh[1][w] = s2; }
    __syncthreads();
    s = 0.f; s2 = 0.f;
    #pragma unroll
    for (int i = 0; i < 8; i++) { s += sh[0][i]; s2 += sh[1][i]; }
    float mean = s * (1.f / 768.f);
    float var  = s2 * (1.f / 768.f) - mean * mean;
    float inv  = rsqrtf(var + 1e-5f);
    oh[row*DD + t]       = __float2half_rn((v0 - mean) * inv * g[t]       + b[t]);
    oh[row*DD + t + 256] = __float2half_rn((v1 - mean) * inv * g[t + 256] + b[t + 256]);
    oh[row*DD + t + 512] = __float2half_rn((v2 - mean) * inv * g[t + 512] + b[t + 512]);
}

// ---------------- host ----------------
extern "C" void kernel_launch(void* const* d_in, const int* in_sizes, int n_in,
                              void* d_out, int out_size)
{
    (void)in_sizes; (void)n_in; (void)out_size;
    const float* x    = (const float*)d_in[0];
    const float* ln1g = (const float*)d_in[1];
    const float* ln1b = (const float*)d_in[2];
    const float* Wq   = (const float*)d_in[3];
    const float* bq   = (const float*)d_in[4];
    const float* Wk   = (const float*)d_in[5];
    const float* bk   = (const float*)d_in[6];
    const float* Wv   = (const float*)d_in[7];
    const float* bv   = (const float*)d_in[8];
    const float* Wo   = (const float*)d_in[9];
    const float* bo   = (const float*)d_in[10];
    const float* ln2g = (const float*)d_in[11];
    const float* ln2b = (const float*)d_in[12];
    const float* W1   = (const float*)d_in[13];
    const float* b1   = (const float*)d_in[14];
    const float* W2   = (const float*)d_in[15];
    const float* b2   = (const float*)d_in[16];
    float* out = (float*)d_out;

    float *x2;
    __half *h, *q, *kh, *kl, *v, *c, *ff, *wq, *wo, *w1, *w2;
    cudaGetSymbolAddress((void**)&x2,  g_x2);
    cudaGetSymbolAddress((void**)&h,   g_h);
    cudaGetSymbolAddress((void**)&q,   g_q);
    cudaGetSymbolAddress((void**)&kh,  g_kh);  cudaGetSymbolAddress((void**)&kl,  g_kl);
    cudaGetSymbolAddress((void**)&v,   g_v);
    cudaGetSymbolAddress((void**)&c,   g_c);
    cudaGetSymbolAddress((void**)&ff,  g_ff);
    cudaGetSymbolAddress((void**)&wq,  g_wq);
    cudaGetSymbolAddress((void**)&wo,  g_wo);
    cudaGetSymbolAddress((void**)&w1,  g_w1);
    cudaGetSymbolAddress((void**)&w2,  g_w2);

    cudaFuncSetAttribute(tcmm, cudaFuncAttributeMaxDynamicSharedMemorySize, GSMEM);
    cudaFuncSetAttribute(flash_attn, cudaFuncAttributeMaxDynamicSharedMemorySize, FSMEM);

    {
        long total = (long)QKVN + WON + 2L * W12N;
        prep_all<<<(unsigned)((total + 255) / 256), 256>>>(
            Wq, Wk, Wv, Wo, W1, W2, wq, wo, w1, w2);
    }

    lnorm_kernel<<<MTOK, 256>>>(x, ln1g, ln1b, h);

    // fused QKV projection (z = 0:q, 1:k, 2:v)
    {
        TcP p{};
        p.A = h; p.as_m = DD; p.a_out = 0; p.a_in = 0; p.a_zdiv = 1;
        p.B = wq; p.bs_n = DD;
        p.b_out = (long)DD * DD; p.b_in = 0; p.b_zdiv = 1;
        p.cs_m = DD; p.c_out = 0; p.c_in = 0; p.c_zdiv = 1;
        p.K = DD; p.N = DD; p.act = 0; p.qkv = 1;
        p.bias = bq; p.bias1 = bk; p.bias2 = bv;
        p.Q = q; p.Kh = kh; p.Kl = kl; p.V = v;
        tcmm<<<dim3(DD / 128, MTOK / 128, 3), 256, GSMEM>>>(p);
    }

    flash_attn<<<dim3(SSEQ / 128, 1, BB * HH), 256, FSMEM>>>(q, kh, kl, v, c);

    // x2 = x + ctx @ Wo + bo
    {
        TcP s{};
        s.A = c; s.as_m = DD; s.a_out = 0; s.a_in = 0; s.a_zdiv = 1;
        s.B = wo; s.bs_n = DD; s.b_out = 0; s.b_in = 0; s.b_zdiv = 1;
        s.bias = bo; s.R = x;
        s.Cf = x2;
        s.cs_m = DD; s.c_out = 0; s.c_in = 0; s.c_zdiv = 1;
        s.K = DD; s.N = DD; s.act = 0; s.qkv = 0;
        tcmm<<<dim3(DD / 128, MTOK / 128, 1), 256, GSMEM>>>(s);
    }

    lnorm_kernel<<<MTOK, 256>>>(x2, ln2g, ln2b, h);

    // ff = gelu(h @ W1 + b1)
    {
        TcP s{};
        s.A = h; s.as_m = DD; s.a_out = 0; s.a_in = 0; s.a_zdiv = 1;
        s.B = w1; s.bs_n = DD; s.b_out = 0; s.b_in = 0; s.b_zdiv = 1;
        s.bias = b1;
        s.Cs = ff;
        s.cs_m = DFF_; s.c_out = 0; s.c_in = 0; s.c_zdiv = 1;
        s.K = DD; s.N = DFF_; s.act = 1; s.qkv = 0;
        tcmm<<<dim3(DFF_ / 128, MTOK / 128, 1), 256, GSMEM>>>(s);
    }

    // out = x2 + ff @ W2 + b2
    {
        TcP s{};
        s.A = ff; s.as_m = DFF_; s.a_out = 0; s.a_in = 0; s.a_zdiv = 1;
        s.B = w2; s.bs_n = DFF_; s.b_out = 0; s.b_in = 0; s.b_zdiv = 1;
        s.bias = b2; s.R = x2;
        s.Cf = out;
        s.cs_m = DD; s.c_out = 0; s.c_in = 0; s.c_zdiv = 1;
        s.K = DFF_; s.N = DD; s.act = 0; s.qkv = 0;
        tcmm<<<dim3(DD / 128, MTOK / 128, 1), 256, GSMEM>>>(s);
    }
}

// round 11
// speedup vs baseline: 10.2578x; 1.1637x over previous
#include <cuda_runtime.h>
#include <cuda_bf16.h>
#include <cuda_fp16.h>
#include <math.h>
#include <stdint.h>

#define BB   16
#define SSEQ 1024
#define DD   768
#define HH   12
#define DHH  64
#define DFF_ 3072
#define MTOK (BB*SSEQ)
#define QSCL 0.18033688011112042f   /* 0.125 * log2(e) */

// ---------------- scratch ----------------
__device__ float   g_x2 [(size_t)MTOK * DD];
__device__ __half  g_h  [(size_t)MTOK * DD];
__device__ __half  g_q  [(size_t)MTOK * DD];
__device__ __half  g_k  [(size_t)MTOK * DD];
__device__ __half  g_v  [(size_t)MTOK * DD];
__device__ __half  g_c  [(size_t)MTOK * DD];
__device__ __half  g_ff [(size_t)MTOK * DFF_];
__device__ __half  g_wq [3 * DD * DD];
__device__ __half  g_wo [DD * DD];
__device__ __half  g_w1 [DD * DFF_];
__device__ __half  g_w2 [DD * DFF_];

// ---------------- helpers ----------------
__device__ __forceinline__ uint32_t smem_u32(const void* p) {
    uint32_t a;
    asm("{ .reg .u64 t; cvta.to.shared.u64 t, %1; cvt.u32.u64 %0, t; }" : "=r"(a) : "l"(p));
    return a;
}
__device__ __forceinline__ float gelu_f(float v) {
    return 0.5f * v * (1.f + erff(v * 0.70710678118654752f));
}

#define CP_ASYNC16(dst, src) \
    asm volatile("cp.async.cg.shared.global [%0], [%1], 16;" :: "r"(dst), "l"(src))
#define CP_COMMIT()  asm volatile("cp.async.commit_group;" ::: "memory")
#define CP_WAIT1()   asm volatile("cp.async.wait_group 1;" ::: "memory")
#define CP_WAIT0()   asm volatile("cp.async.wait_group 0;" ::: "memory")

#define LDSM_X4(r0, r1, r2, r3, a) \
    asm volatile("ldmatrix.sync.aligned.m8n8.x4.shared.b16 {%0,%1,%2,%3}, [%4];" \
        : "=r"(r0), "=r"(r1), "=r"(r2), "=r"(r3) : "r"(a))
#define LDSM_X4T(r0, r1, r2, r3, a) \
    asm volatile("ldmatrix.sync.aligned.m8n8.x4.trans.shared.b16 {%0,%1,%2,%3}, [%4];" \
        : "=r"(r0), "=r"(r1), "=r"(r2), "=r"(r3) : "r"(a))

#define MMAF16(c0, c1, c2, c3, a0, a1, a2, a3, b0, b1) \
    asm volatile("mma.sync.aligned.m16n8k16.row.col.f32.f16.f16.f32 " \
        "{%0,%1,%2,%3}, {%4,%5,%6,%7}, {%8,%9}, {%0,%1,%2,%3};" \
        : "+f"(c0), "+f"(c1), "+f"(c2), "+f"(c3) \
        : "r"(a0), "r"(a1), "r"(a2), "r"(a3), "r"(b0), "r"(b1))

__device__ __forceinline__ void mma_f16(float* c, const uint32_t* a, uint32_t b0, uint32_t b1) {
    MMAF16(c[0], c[1], c[2], c[3], a[0], a[1], a[2], a[3], b0, b1);
}

// ---------------- HMMA GEMM: pure fp16, 64-wide k-chunks, 3-stage ring ----------------
struct TcP {
    const __half *A, *B;
    const float *bias, *bias1, *bias2, *R;
    float* Cf; __half* Cs;
    __half *Q, *K_, *V;
    long a_out, a_in, b_out, b_in, c_out, c_in;
    int a_zdiv, b_zdiv, c_zdiv;
    int as_m, bs_n, cs_m;
    int K, N; int act; int qkv;
};

#define RS64  144
#define PL64  (128 * RS64)        // 18432 per plane
#define STG64 (2 * PL64)          // 36864 per stage (A, B)
#define GSMEM (3 * STG64)         // 110592

__global__ void __launch_bounds__(256, 2) tcmm(TcP p)
{
    extern __shared__ __align__(128) char gsm[];

    const int tid = threadIdx.x, wid = tid >> 5, lane = tid & 31;
    const int n0 = blockIdx.x * 128, m0 = blockIdx.y * 128, z = blockIdx.z;
    const int wm = (wid >> 2) * 64;
    const int wn = (wid & 3) * 32;

    const __half* A = p.A + (long)(z / p.a_zdiv) * p.a_out + (long)(z % p.a_zdiv) * p.a_in;
    const __half* B = p.B + (long)(z / p.b_zdiv) * p.b_out + (long)(z % p.b_zdiv) * p.b_in;
    const long coff = (long)(z / p.c_zdiv) * p.c_out + (long)(z % p.c_zdiv) * p.c_in;

    const uint32_t sbase = smem_u32(gsm);
    const int KC = p.K >> 6;          // 64-wide chunks

    float acc[4][4][4];
    #pragma unroll
    for (int i = 0; i < 4; i++)
        #pragma unroll
        for (int j = 0; j < 4; j++)
            #pragma unroll
            for (int r = 0; r < 4; r++) acc[i][j][r] = 0.f;

    auto load_stage = [&](int s, int c) {
        const long kof = (long)c << 6;
        uint32_t dA = sbase + s * STG64;
        uint32_t dB = dA + PL64;
        #pragma unroll
        for (int i = 0; i < 4; i++) {
            int id = tid + i * 256;
            int row = id >> 3, u = id & 7;
            CP_ASYNC16(dA + (uint32_t)(row * RS64 + u * 16),
                       A + (long)(m0 + row) * p.as_m + kof + u * 8);
            if (n0 + row < p.N)
                CP_ASYNC16(dB + (uint32_t)(row * RS64 + u * 16),
                           B + (long)(n0 + row) * p.bs_n + kof + u * 8);
        }
    };

    load_stage(0, 0); CP_COMMIT();
    load_stage(1, 1); CP_COMMIT();

    for (int c = 0; c < KC; c++) {
        if (c + 1 < KC) { CP_WAIT1(); } else { CP_WAIT0(); }
        __syncthreads();
        if (c + 2 < KC) { load_stage((c + 2) % 3, c + 2); CP_COMMIT(); }

        const uint32_t sA = sbase + (c % 3) * STG64;
        const uint32_t sB = sA + PL64;

        #pragma unroll
        for (int ks = 0; ks < 4; ks++) {
            uint32_t a[4][4], b[4][2];
            #pragma unroll
            for (int i = 0; i < 4; i++) {
                uint32_t ad = sA + (uint32_t)(wm + i * 16 + (lane & 15)) * RS64
                            + ks * 32 + (lane >> 4) * 16;
                LDSM_X4(a[i][0], a[i][1], a[i][2], a[i][3], ad);
            }
            #pragma unroll
            for (int j = 0; j < 2; j++) {
                uint32_t bd = sB + (uint32_t)(wn + j * 16 + ((lane >> 4) & 1) * 8 + (lane & 7)) * RS64
                            + ks * 32 + ((lane >> 3) & 1) * 16;
                LDSM_X4(b[2*j][0], b[2*j][1], b[2*j+1][0], b[2*j+1][1], bd);
            }
            #pragma unroll
            for (int i = 0; i < 4; i++)
                #pragma unroll
                for (int j = 0; j < 4; j++)
                    MMAF16(acc[i][j][0], acc[i][j][1], acc[i][j][2], acc[i][j][3],
                           a[i][0], a[i][1], a[i][2], a[i][3], b[j][0], b[j][1]);
        }
    }

    // epilogue
    #pragma unroll
    for (int i = 0; i < 4; i++) {
        #pragma unroll
        for (int j = 0; j < 4; j++) {
            int n = n0 + wn + j * 8 + (lane & 3) * 2;
            if (n >= p.N) continue;
            #pragma unroll
            for (int half_ = 0; half_ < 2; half_++) {
                int m = m0 + wm + i * 16 + (lane >> 2) + half_ * 8;
                float vx = acc[i][j][half_ * 2 + 0];
                float vy = acc[i][j][half_ * 2 + 1];
                const long base = coff + (long)m * p.cs_m + n;
                if (p.qkv) {
                    const float* bias = (z == 0) ? p.bias : (z == 1) ? p.bias1 : p.bias2;
                    vx += bias[n]; vy += bias[n + 1];
                    float sc = (z == 0) ? QSCL : 1.f;
                    __half* o = (z == 0) ? p.Q : (z == 1) ? p.K_ : p.V;
                    *(__half2*)(o + base) = __floats2half2_rn(vx * sc, vy * sc);
                } else {
                    if (p.bias) { vx += p.bias[n]; vy += p.bias[n + 1]; }
                    if (p.act)  { vx = gelu_f(vx); vy = gelu_f(vy); }
                    if (p.R) {
                        float2 rr = *(const float2*)(p.R + base);
                        vx += rr.x; vy += rr.y;
                    }
                    if (p.Cf) *(float2*)(p.Cf + base) = make_float2(vx, vy);
                    if (p.Cs) *(__half2*)(p.Cs + base) = __floats2half2_rn(vx, vy);
                }
            }
        }
    }
}

// ---------------- Flash attention: all fp16 single-plane, 1-pass QK + 1-pass PV ----------------
#define FRS   144
#define FQPL  (128 * FRS)      // 18432
#define FKPL  (64 * FRS)       // 9216
#define FSTG  (2 * FKPL)       // K, V per stage = 18432
#define FSMEM (FQPL + 2 * FSTG)   // 55296
#define NKT   16

__global__ void __launch_bounds__(256, 2) flash_attn(
    const __half* __restrict__ q,
    const __half* __restrict__ k,
    const __half* __restrict__ v,
    __half* __restrict__ ch)
{
    extern __shared__ __align__(128) char fsm[];
    const int tid = threadIdx.x, wid = tid >> 5, lane = tid & 31;
    const int b = blockIdx.z / HH, h = blockIdx.z % HH;
    const size_t qrow0 = (size_t)b * SSEQ + blockIdx.x * 128;
    const size_t krow0 = (size_t)b * SSEQ;
    const int hc = h * DHH;

    const uint32_t sb  = smem_u32(fsm);
    const uint32_t sKV = sb + FQPL;

    // Q load
    {
        #pragma unroll
        for (int i = 0; i < 4; i++) {
            int id = tid + i * 256;
            int row = id >> 3, cu = id & 7;
            CP_ASYNC16(sb + (uint32_t)(row * FRS + cu * 16),
                       q + (qrow0 + row) * DD + hc + cu * 8);
        }
    }
    // KV load: 2 planes (K, V) x 64 rows x 8 chunks = 1024 / 256 threads
    auto loadKV = [&](int kt, int s) {
        uint32_t base = sKV + (uint32_t)s * FSTG;
        size_t r0 = krow0 + (size_t)kt * 64;
        #pragma unroll
        for (int i = 0; i < 4; i++) {
            int id = tid + i * 256;
            int pl = id >> 9, rc = id & 511;
            int row = rc >> 3, cu = rc & 7;
            const __half* g = pl ? v : k;
            CP_ASYNC16(base + (uint32_t)(pl * FKPL + row * FRS + cu * 16),
                       g + (r0 + row) * DD + hc + cu * 8);
        }
    };
    loadKV(0, 0); CP_COMMIT();
    loadKV(1, 1); CP_COMMIT();
    CP_WAIT1(); __syncthreads();

    // persistent Q fragments
    uint32_t qf[4][4];
    const int mw = wid * 16;
    #pragma unroll
    for (int kf = 0; kf < 4; kf++) {
        uint32_t ad = sb + (uint32_t)((mw + (lane & 15)) * FRS + kf * 32 + (lane >> 4) * 16);
        LDSM_X4(qf[kf][0], qf[kf][1], qf[kf][2], qf[kf][3], ad);
    }

    float accO[8][4];
    #pragma unroll
    for (int i = 0; i < 8; i++) { accO[i][0] = accO[i][1] = accO[i][2] = accO[i][3] = 0.f; }
    float mrun0 = -1e30f, mrun1 = -1e30f, lrun0 = 0.f, lrun1 = 0.f;

    for (int kt = 0; kt < NKT; kt++) {
        const uint32_t bK = sKV + (uint32_t)(kt & 1) * FSTG;
        const uint32_t bV = bK + FKPL;

        // ---- S = Q K^T (single pass, log2 domain) ----
        float S[8][4];
        #pragma unroll
        for (int j = 0; j < 8; j++) { S[j][0] = S[j][1] = S[j][2] = S[j][3] = 0.f; }

        #pragma unroll
        for (int kf = 0; kf < 4; kf++) {
            #pragma unroll
            for (int jp = 0; jp < 4; jp++) {
                uint32_t b0, b1, b2, b3;
                uint32_t ad = bK + (uint32_t)((jp * 16 + ((lane >> 4) & 1) * 8 + (lane & 7)) * FRS
                            + kf * 32 + ((lane >> 3) & 1) * 16);
                LDSM_X4(b0, b1, b2, b3, ad);
                mma_f16(S[2 * jp],     qf[kf], b0, b1);
                mma_f16(S[2 * jp + 1], qf[kf], b2, b3);
            }
        }

        // ---- online max ----
        float rm0 = -1e30f, rm1 = -1e30f;
        #pragma unroll
        for (int j = 0; j < 8; j++) {
            rm0 = fmaxf(rm0, fmaxf(S[j][0], S[j][1]));
            rm1 = fmaxf(rm1, fmaxf(S[j][2], S[j][3]));
        }
        rm0 = fmaxf(rm0, __shfl_xor_sync(0xFFFFFFFFu, rm0, 1));
        rm0 = fmaxf(rm0, __shfl_xor_sync(0xFFFFFFFFu, rm0, 2));
        rm1 = fmaxf(rm1, __shfl_xor_sync(0xFFFFFFFFu, rm1, 1));
        rm1 = fmaxf(rm1, __shfl_xor_sync(0xFFFFFFFFu, rm1, 2));
        float mn0 = fmaxf(mrun0, rm0), mn1 = fmaxf(mrun1, rm1);
        float sc0 = exp2f(mrun0 - mn0), sc1 = exp2f(mrun1 - mn1);
        mrun0 = mn0; mrun1 = mn1;
        #pragma unroll
        for (int i = 0; i < 8; i++) {
            accO[i][0] *= sc0; accO[i][1] *= sc0;
            accO[i][2] *= sc1; accO[i][3] *= sc1;
        }

        // ---- P = exp2(S - m) f16; O += P V ----
        float rs0 = 0.f, rs1 = 0.f;
        #pragma unroll
        for (int kf = 0; kf < 4; kf++) {
            __half2 e0 = h2exp2(__floats2half2_rn(S[2*kf][0]   - mn0, S[2*kf][1]   - mn0));
            __half2 e1 = h2exp2(__floats2half2_rn(S[2*kf][2]   - mn1, S[2*kf][3]   - mn1));
            __half2 e2 = h2exp2(__floats2half2_rn(S[2*kf+1][0] - mn0, S[2*kf+1][1] - mn0));
            __half2 e3 = h2exp2(__floats2half2_rn(S[2*kf+1][2] - mn1, S[2*kf+1][3] - mn1));
            uint32_t pa[4];
            pa[0] = *reinterpret_cast<uint32_t*>(&e0);
            pa[1] = *reinterpret_cast<uint32_t*>(&e1);
            pa[2] = *reinterpret_cast<uint32_t*>(&e2);
            pa[3] = *reinterpret_cast<uint32_t*>(&e3);
            float2 f0 = __half22float2(e0), f1 = __half22float2(e1);
            float2 f2 = __half22float2(e2), f3 = __half22float2(e3);
            rs0 += f0.x + f0.y + f2.x + f2.y;
            rs1 += f1.x + f1.y + f3.x + f3.y;

            #pragma unroll
            for (int np = 0; np < 4; np++) {
                uint32_t ad = bV + (uint32_t)((kf * 16 + ((lane >> 3) & 1) * 8 + (lane & 7)) * FRS
                            + np * 32 + (lane >> 4) * 16);
                uint32_t v0, v1, v2, v3;
                LDSM_X4T(v0, v1, v2, v3, ad);
                mma_f16(accO[2 * np],     pa, v0, v1);
                mma_f16(accO[2 * np + 1], pa, v2, v3);
            }
        }
        rs0 += __shfl_xor_sync(0xFFFFFFFFu, rs0, 1);
        rs0 += __shfl_xor_sync(0xFFFFFFFFu, rs0, 2);
        rs1 += __shfl_xor_sync(0xFFFFFFFFu, rs1, 1);
        rs1 += __shfl_xor_sync(0xFFFFFFFFu, rs1, 2);
        lrun0 = lrun0 * sc0 + rs0;
        lrun1 = lrun1 * sc1 + rs1;

        __syncthreads();
        if (kt + 2 < NKT) { loadKV(kt + 2, kt & 1); CP_COMMIT(); }
        if (kt + 1 < NKT) {
            if (kt + 2 < NKT) { CP_WAIT1(); } else { CP_WAIT0(); }
            __syncthreads();
        }
    }

    float inv0 = 1.f / lrun0, inv1 = 1.f / lrun1;
    size_t r0 = qrow0 + mw + (lane >> 2);
    #pragma unroll
    for (int nt = 0; nt < 8; nt++) {
        int col = hc + nt * 8 + 2 * (lane & 3);
        *(__half2*)(ch + r0 * DD + col) =
            __floats2half2_rn(accO[nt][0] * inv0, accO[nt][1] * inv0);
        *(__half2*)(ch + (r0 + 8) * DD + col) =
            __floats2half2_rn(accO[nt][2] * inv1, accO[nt][3] * inv1);
    }
}

// ---------------- merged weight prep ----------------
#define QKVN (DD * DD)
#define WON  (DD * DD)
#define W12N (DD * DFF_)
__global__ void __launch_bounds__(256) prep_all(
    const float* __restrict__ Wq, const float* __restrict__ Wk, const float* __restrict__ Wv,
    const float* __restrict__ Wo, const float* __restrict__ W1, const float* __restrict__ W2,
    __half* __restrict__ wq, __half* __restrict__ wo,
    __half* __restrict__ w1, __half* __restrict__ w2)
{
    long idx = (long)blockIdx.x * 256 + threadIdx.x;
    if (idx < QKVN) {
        int n = (int)(idx / DD), d = (int)(idx % DD);
        int h = n >> 6, c = n & 63;
        size_t src = (size_t)h * DD * DHH + (size_t)d * DHH + c;
        wq[idx]            = __float2half_rn(Wq[src]);
        wq[idx + QKVN]     = __float2half_rn(Wk[src]);
        wq[idx + 2 * QKVN] = __float2half_rn(Wv[src]);
        return;
    }
    idx -= QKVN;
    if (idx < WON) {
        int n = (int)(idx / DD), k = (int)(idx % DD);
        wo[idx] = __float2half_rn(Wo[(long)k * DD + n]);
        return;
    }
    idx -= WON;
    if (idx < W12N) {
        int n = (int)(idx / DD), k = (int)(idx % DD);
        w1[idx] = __float2half_rn(W1[(long)k * DFF_ + n]);
        return;
    }
    idx -= W12N;
    if (idx < W12N) {
        int n = (int)(idx / DFF_), k = (int)(idx % DFF_);
        w2[idx] = __float2half_rn(W2[(long)k * DD + n]);
    }
}

// ---------------- LayerNorm -> single fp16 ----------------
__global__ void __launch_bounds__(256) lnorm_kernel(
    const float* __restrict__ x, const float* __restrict__ g, const float* __restrict__ b,
    __half* __restrict__ oh)
{
    size_t row = blockIdx.x;
    const float* xr = x + row * DD;
    int t = threadIdx.x;
    float v0 = xr[t], v1 = xr[t + 256], v2 = xr[t + 512];
    float s  = v0 + v1 + v2;
    float s2 = v0*v0 + v1*v1 + v2*v2;
    #pragma unroll
    for (int o = 16; o; o >>= 1) {
        s  += __shfl_xor_sync(0xFFFFFFFFu, s,  o);
        s2 += __shfl_xor_sync(0xFFFFFFFFu, s2, o);
    }
    __shared__ float sh[2][8];
    int w = t >> 5, l = t & 31;
    if (l == 0) { sh[0][w] = s; sh[1][w] = s2; }
    __syncthreads();
    s = 0.f; s2 = 0.f;
    #pragma unroll
    for (int i = 0; i < 8; i++) { s += sh[0][i]; s2 += sh[1][i]; }
    float mean = s * (1.f / 768.f);
    float var  = s2 * (1.f / 768.f) - mean * mean;
    float inv  = rsqrtf(var + 1e-5f);
    oh[row*DD + t]       = __float2half_rn((v0 - mean) * inv * g[t]       + b[t]);
    oh[row*DD + t + 256] = __float2half_rn((v1 - mean) * inv * g[t + 256] + b[t + 256]);
    oh[row*DD + t + 512] = __float2half_rn((v2 - mean) * inv * g[t + 512] + b[t + 512]);
}

// ---------------- host ----------------
extern "C" void kernel_launch(void* const* d_in, const int* in_sizes, int n_in,
                              void* d_out, int out_size)
{
    (void)in_sizes; (void)n_in; (void)out_size;
    const float* x    = (const float*)d_in[0];
    const float* ln1g = (const float*)d_in[1];
    const float* ln1b = (const float*)d_in[2];
    const float* Wq   = (const float*)d_in[3];
    const float* bq   = (const float*)d_in[4];
    const float* Wk   = (const float*)d_in[5];
    const float* bk   = (const float*)d_in[6];
    const float* Wv   = (const float*)d_in[7];
    const float* bv   = (const float*)d_in[8];
    const float* Wo   = (const float*)d_in[9];
    const float* bo   = (const float*)d_in[10];
    const float* ln2g = (const float*)d_in[11];
    const float* ln2b = (const float*)d_in[12];
    const float* W1   = (const float*)d_in[13];
    const float* b1   = (const float*)d_in[14];
    const float* W2   = (const float*)d_in[15];
    const float* b2   = (const float*)d_in[16];
    float* out = (float*)d_out;

    float *x2;
    __half *h, *q, *k, *v, *c, *ff, *wq, *wo, *w1, *w2;
    cudaGetSymbolAddress((void**)&x2,  g_x2);
    cudaGetSymbolAddress((void**)&h,   g_h);
    cudaGetSymbolAddress((void**)&q,   g_q);
    cudaGetSymbolAddress((void**)&k,   g_k);
    cudaGetSymbolAddress((void**)&v,   g_v);
    cudaGetSymbolAddress((void**)&c,   g_c);
    cudaGetSymbolAddress((void**)&ff,  g_ff);
    cudaGetSymbolAddress((void**)&wq,  g_wq);
    cudaGetSymbolAddress((void**)&wo,  g_wo);
    cudaGetSymbolAddress((void**)&w1,  g_w1);
    cudaGetSymbolAddress((void**)&w2,  g_w2);

    cudaFuncSetAttribute(tcmm, cudaFuncAttributeMaxDynamicSharedMemorySize, GSMEM);
    cudaFuncSetAttribute(flash_attn, cudaFuncAttributeMaxDynamicSharedMemorySize, FSMEM);

    {
        long total = (long)QKVN + WON + 2L * W12N;
        prep_all<<<(unsigned)((total + 255) / 256), 256>>>(
            Wq, Wk, Wv, Wo, W1, W2, wq, wo, w1, w2);
    }

    lnorm_kernel<<<MTOK, 256>>>(x, ln1g, ln1b, h);

    // fused QKV projection (z = 0:q, 1:k, 2:v)
    {
        TcP p{};
        p.A = h; p.as_m = DD; p.a_out = 0; p.a_in = 0; p.a_zdiv = 1;
        p.B = wq; p.bs_n = DD;
        p.b_out = (long)DD * DD; p.b_in = 0; p.b_zdiv = 1;
        p.cs_m = DD; p.c_out = 0; p.c_in = 0; p.c_zdiv = 1;
        p.K = DD; p.N = DD; p.act = 0; p.qkv = 1;
        p.bias = bq; p.bias1 = bk; p.bias2 = bv;
        p.Q = q; p.K_ = k; p.V = v;
        tcmm<<<dim3(DD / 128, MTOK / 128, 3), 256, GSMEM>>>(p);
    }

    flash_attn<<<dim3(SSEQ / 128, 1, BB * HH), 256, FSMEM>>>(q, k, v, c);

    // x2 = x + ctx @ Wo + bo
    {
        TcP s{};
        s.A = c; s.as_m = DD; s.a_out = 0; s.a_in = 0; s.a_zdiv = 1;
        s.B = wo; s.bs_n = DD; s.b_out = 0; s.b_in = 0; s.b_zdiv = 1;
        s.bias = bo; s.R = x;
        s.Cf = x2;
        s.cs_m = DD; s.c_out = 0; s.c_in = 0; s.c_zdiv = 1;
        s.K = DD; s.N = DD; s.act = 0; s.qkv = 0;
        tcmm<<<dim3(DD / 128, MTOK / 128, 1), 256, GSMEM>>>(s);
    }

    lnorm_kernel<<<MTOK, 256>>>(x2, ln2g, ln2b, h);

    // ff = gelu(h @ W1 + b1)
    {
        TcP s{};
        s.A = h; s.as_m = DD; s.a_out = 0; s.a_in = 0; s.a_zdiv = 1;
        s.B = w1; s.bs_n = DD; s.b_out = 0; s.b_in = 0; s.b_zdiv = 1;
        s.bias = b1;
        s.Cs = ff;
        s.cs_m = DFF_; s.c_out = 0; s.c_in = 0; s.c_zdiv = 1;
        s.K = DD; s.N = DFF_; s.act = 1; s.qkv = 0;
        tcmm<<<dim3(DFF_ / 128, MTOK / 128, 1), 256, GSMEM>>>(s);
    }

    // out = x2 + ff @ W2 + b2
    {
        TcP s{};
        s.A = ff; s.as_m = DFF_; s.a_out = 0; s.a_in = 0; s.a_zdiv = 1;
        s.B = w2; s.bs_n = DFF_; s.b_out = 0; s.b_in = 0; s.b_zdiv = 1;
        s.bias = b2; s.R = x2;
        s.Cf = out;
        s.cs_m = DD; s.c_out = 0; s.c_in = 0; s.c_zdiv = 1;
        s.K = DFF_; s.N = DD; s.act = 0; s.qkv = 0;
        tcmm<<<dim3(DD / 128, MTOK / 128, 1), 256, GSMEM>>>(s);
    }
}